// round 5
// baseline (speedup 1.0000x reference)
#include <cuda_runtime.h>
#include <math.h>

#define BB 8
#define NN 2048
#define CC 32
#define DD 64
#define QQ 256
#define KK 205
#define JP 36           // padded j dimension (33 -> 36 for float4)
#define RANK (KK-1)
#define NT 288

// ---------------- scratch ----------------
__device__ float d_xl[BB*NN*CC];        // 2 MB
__device__ float d_W2t[33*64*32];       // W2ext transposed: [j][d][c]
__device__ float d_Wm1t[256*64];        // Wm1 transposed:  [i][d2]
__device__ float d_Wm2t[64*256];        // Wm2 transposed:  [d][i]

__device__ __forceinline__ float gelu_f(float x){
    return 0.5f*x*(1.0f+erff(x*0.70710678118654752440f));
}

__device__ __forceinline__ void cp_async16(float* smem_dst, const float4* gsrc){
    unsigned sm = (unsigned)__cvta_generic_to_shared(smem_dst);
    asm volatile("cp.async.cg.shared.global [%0], [%1], 16;\n" :: "r"(sm), "l"(gsrc));
}
#define CP_COMMIT() asm volatile("cp.async.commit_group;\n")
#define CP_WAIT(n)  asm volatile("cp.async.wait_group %0;\n" :: "n"(n))

// ---------------- kernel A: xl = x@W_lin+b, qp copy, weight transposes ----
__global__ __launch_bounds__(256) void k_xl(const float* __restrict__ x,
                                            const float* __restrict__ W,
                                            const float* __restrict__ bl,
                                            const float* __restrict__ qp,
                                            float* __restrict__ out,
                                            const float* __restrict__ W2,
                                            const float* __restrict__ filt,
                                            const float* __restrict__ Wm1,
                                            const float* __restrict__ Wm2){
    const int bid = blockIdx.x, tid = threadIdx.x;
    if(bid >= 2048){
        int tb = bid - 2048;
        if(tb < 8){
            // W2t[(j*64+d)*32+c] = (j<32) ? W2[j*2048 + c*64 + d] : filt[c*64+d]
            for(int i = tb*256 + tid; i < 33*64*32; i += 2048){
                int j = i>>11, d = (i>>5)&63, c = i&31;
                d_W2t[i] = (j<32) ? W2[(j<<11)+(c<<6)+d] : filt[(c<<6)+d];
            }
        } else if(tb == 8){
            for(int i=tid;i<16384;i+=256){ int ii=i>>6, d2=i&63; d_Wm1t[i]=Wm1[d2*256+ii]; }
        } else {
            for(int i=tid;i<16384;i+=256){ int d=i>>8, ii=i&255; d_Wm2t[i]=Wm2[ii*64+d]; }
        }
        return;
    }
    __shared__ float sW[CC*CC];
    for(int i=tid;i<CC*CC;i+=256) sW[i]=W[i];
    __syncthreads();
    int row  = bid*8 + (tid>>5);
    int lane = tid&31;
    float xv  = x[row*CC + lane];
    float acc = bl[lane];
    #pragma unroll
    for(int ci=0;ci<CC;ci++)
        acc = fmaf(__shfl_sync(0xffffffffu, xv, ci), sW[ci*CC+lane], acc);
    d_xl[row*CC+lane] = acc;
    if(bid < 2){
        int i = bid*256 + tid;
        out[BB*QQ*DD + i] = qp[i];
    }
}

// ---------------- fused kernel ---------------------------------------------
// smem layout (floats). Total 24484 floats = 97,936 B -> 2 blocks/SM.
#define OFF_G   0                 // g 205*36=7380 (later reused as sh1 2048)
#define OFF_X   7380              // 16384: select scratch | gather bufs | sM
#define OFF_IND 23764             // 208 ints
#define OFF_Y   23972             // 512
#define SMEM_FLOATS 24484
#define SMEM_BYTES (SMEM_FLOATS*4)

// select-scratch offsets inside X region:
#define XS_ED    0                // 2048
#define XS_FEAT  2048             // 205*32 = 6560
#define XS_D0    8608
#define XS_D1    8813
#define XS_EDK   9018
#define XS_KD    9223
#define XS_W1    9428             // 1024
#define XS_B1    10452
#define XS_HIST  10484            // 256 (uint)
#define XS_RA    10740
#define XS_RB    10749
#define XS_SC    10758

__global__ __launch_bounds__(NT,2) void k_fused(
        const float* __restrict__ pos, const float* __restrict__ qpos,
        const float* __restrict__ rffB,
        const float* __restrict__ W1,  const float* __restrict__ b1,
        const float* __restrict__ qmw, const float* __restrict__ qmo,
        const float* __restrict__ bias,
        const float* __restrict__ bm1, const float* __restrict__ bm2,
        float* __restrict__ out)
{
    extern __shared__ float smem[];
    float* sg  = smem + OFF_G;
    float* px  = smem + OFF_X;
    int*   sind= (int*)(smem + OFF_IND);
    float* sy  = smem + OFF_Y;

    const int q = blockIdx.x, tid = threadIdx.x;
    const int warp = tid>>5, lane = tid&31;
    const float qx = qpos[q*2], qy = qpos[q*2+1];

    // ======================= SELECT PHASE =======================
    {
        float* sed  = px + XS_ED;
        float* sfeat= px + XS_FEAT;
        float* sd0  = px + XS_D0;
        float* sd1  = px + XS_D1;
        float* sedk = px + XS_EDK;
        float* skd  = px + XS_KD;
        float* sW1  = px + XS_W1;
        float* sb1  = px + XS_B1;
        unsigned int* hist = (unsigned int*)(px + XS_HIST);
        float* rbufA= px + XS_RA;
        float* rbufB= px + XS_RB;
        unsigned int* s_prefix = (unsigned int*)(px + XS_SC);
        unsigned int* s_r      = (unsigned int*)(px + XS_SC + 1);
        unsigned int* s_cnt    = (unsigned int*)(px + XS_SC + 2);
        float* s_min = px + XS_SC + 3;
        float* s_max = px + XS_SC + 4;
        float* s_sum = px + XS_SC + 5;

        for(int i=tid;i<CC*CC;i+=NT) sW1[i]=W1[i];
        if(tid<CC) sb1[tid]=b1[tid];

        for(int n=tid;n<NN;n+=NT){
            float2 p = ((const float2*)pos)[n];
            float d0 = qx - p.x; d0 += 0.5f; d0 -= floorf(d0); d0 -= 0.5f;
            float d1 = qy - p.y; d1 += 0.5f; d1 -= floorf(d1); d1 -= 0.5f;
            sed[n] = d0*d0 + d1*d1;
        }
        if(tid==0){ *s_prefix=0u; *s_r=RANK; *s_cnt=0u; }
        __syncthreads();

        // 4-pass MSD radix select on float bits (all >= 0)
        for(int pass=0; pass<4; ++pass){
            const int shift = 24 - 8*pass;
            for(int i=tid;i<256;i+=NT) hist[i]=0u;
            __syncthreads();
            const unsigned int prefix = *s_prefix;
            const unsigned int hm = (pass==0) ? 0u : (0xFFFFFFFFu << (shift+8));
            for(int n=tid;n<NN;n+=NT){
                unsigned int k = __float_as_uint(sed[n]);
                if((k & hm) == prefix) atomicAdd(&hist[(k>>shift)&255u], 1u);
            }
            __syncthreads();
            if(tid==0){
                unsigned int cum=0, rr=*s_r; int bsel=255;
                for(int bkt=0;bkt<256;bkt++){
                    unsigned int c=hist[bkt];
                    if(cum + c > rr){ bsel=bkt; break; }
                    cum += c;
                }
                *s_prefix = prefix | ((unsigned int)bsel << shift);
                *s_r = rr - cum;
            }
            __syncthreads();
        }
        const unsigned int T = *s_prefix;

        for(int n=tid;n<NN;n+=NT){
            unsigned int k = __float_as_uint(sed[n]);
            if(k < T){ unsigned int p = atomicAdd(s_cnt,1u); sind[p]=n; }
        }
        __syncthreads();
        for(int n=tid;n<NN;n+=NT){
            unsigned int k = __float_as_uint(sed[n]);
            if(k == T){ unsigned int p = atomicAdd(s_cnt,1u); if(p<KK) sind[p]=n; }
        }
        __syncthreads();

        for(int k2=tid;k2<KK;k2+=NT){
            int n = sind[k2];
            float2 p = ((const float2*)pos)[n];
            float d0 = qx - p.x; d0 += 0.5f; d0 -= floorf(d0); d0 -= 0.5f;
            float d1 = qy - p.y; d1 += 0.5f; d1 -= floorf(d1); d1 -= 0.5f;
            sd0[k2]=d0; sd1[k2]=d1; sedk[k2]=sed[n];
        }
        __syncthreads();

        float mn = 1e30f, mx = -1e30f;
        for(int k2=tid;k2<KK;k2+=NT){ mn=fminf(mn,sedk[k2]); mx=fmaxf(mx,sedk[k2]); }
        #pragma unroll
        for(int o=16;o>0;o>>=1){
            mn = fminf(mn, __shfl_down_sync(0xffffffffu,mn,o));
            mx = fmaxf(mx, __shfl_down_sync(0xffffffffu,mx,o));
        }
        if(lane==0){ rbufA[warp]=mn; rbufB[warp]=mx; }
        __syncthreads();
        if(tid==0){
            float a=rbufA[0], b=rbufB[0];
            for(int w=1;w<9;w++){ a=fminf(a,rbufA[w]); b=fmaxf(b,rbufB[w]); }
            *s_min=a; *s_max=b;
        }
        __syncthreads();

        const float inv = 1.0f/(*s_max - *s_min + 1e-8f);
        const float smin = *s_min;
        float lsum = 0.0f;
        for(int k2=tid;k2<KK;k2+=NT){
            float w = expf(-(sedk[k2]-smin)*inv);
            skd[k2]=w; lsum+=w;
        }
        #pragma unroll
        for(int o=16;o>0;o>>=1) lsum += __shfl_down_sync(0xffffffffu,lsum,o);
        if(lane==0) rbufA[warp]=lsum;
        __syncthreads();
        if(tid==0){
            float s=0.f; for(int w=0;w<9;w++) s+=rbufA[w];
            *s_sum=s;
        }
        __syncthreads();
        const float invsum = 1.0f/(*s_sum);

        for(int i=tid;i<KK*16;i+=NT){
            int k2=i>>4, j=i&15;
            float pr = 6.28318530717958647692f*(sd0[k2]*rffB[j] + sd1[k2]*rffB[16+j]);
            float s,c; sincosf(pr,&s,&c);
            sfeat[k2*32+j]=s; sfeat[k2*32+16+j]=c;
        }
        __syncthreads();

        // g = gelu((feat@W1+b1)*qmw+qmo)*kd ; ch 32 = kd; pad 33..35
        for(int i=tid;i<KK*CC;i+=NT){
            int k2=i>>5, ii=i&31;
            float acc = sb1[ii];
            const float* fr = &sfeat[k2*32];
            #pragma unroll
            for(int f=0;f<CC;f++) acc = fmaf(fr[f], sW1[f*CC+ii], acc);
            float h = acc*qmw[q*CC+ii] + qmo[q*CC+ii];
            sg[k2*JP + ii] = gelu_f(h) * (skd[k2]*invsum);
        }
        for(int k2=tid;k2<KK;k2+=NT){
            sg[k2*JP+32] = skd[k2]*invsum;
            sg[k2*JP+33] = 0.f; sg[k2*JP+34] = 0.f; sg[k2*JP+35] = 0.f;
        }
        __syncthreads();
    }
    // ======================= M-GEMM PHASE =======================
    const int jg = tid>>5;     // 0..8
    const int cg = tid&31;     // 0..31

    float acc[4][8];
    #pragma unroll
    for(int jj=0;jj<4;jj++)
        #pragma unroll
        for(int cc=0;cc<8;cc++) acc[jj][cc]=0.f;

    const float4* sg4 = (const float4*)sg;
    float* xb0 = px;
    float* xb1 = px + 8192;

    {
        for(int i=tid;i<32*64;i+=NT){
            int kk=i>>6, ch=i&63, b=ch>>3, c4=ch&7;
            int n = sind[kk];
            cp_async16(&xb0[kk*256 + ch*4], (const float4*)&d_xl[((b<<11)+n)*CC] + c4);
        }
        CP_COMMIT();
    }

    const int NCH = (KK + 31)/32;  // 7
    for(int ci=0; ci<NCH; ++ci){
        const int k0 = ci*32;
        const int nk = (KK-k0 < 32) ? (KK-k0) : 32;
        if(ci+1 < NCH){
            const int k0n = k0+32;
            const int nkn = (KK-k0n < 32) ? (KK-k0n) : 32;
            float* dst = (ci&1) ? xb0 : xb1;
            for(int i=tid;i<nkn*64;i+=NT){
                int kk=i>>6, ch=i&63, b=ch>>3, c4=ch&7;
                int n = sind[k0n+kk];
                cp_async16(&dst[kk*256 + ch*4], (const float4*)&d_xl[((b<<11)+n)*CC] + c4);
            }
            CP_COMMIT();
            CP_WAIT(1);
        } else {
            CP_WAIT(0);
        }
        __syncthreads();
        const float4* sx4 = (const float4*)((ci&1) ? xb1 : xb0);
        #pragma unroll 2
        for(int kk=0; kk<nk; ++kk){
            float4 g4v = sg4[(k0+kk)*(JP/4) + jg];
            float4 xa = sx4[kk*64 + cg];
            float4 xc = sx4[kk*64 + 32 + cg];
            float gs[4] = {g4v.x,g4v.y,g4v.z,g4v.w};
            #pragma unroll
            for(int jj=0;jj<4;jj++){
                acc[jj][0] = fmaf(gs[jj], xa.x, acc[jj][0]);
                acc[jj][1] = fmaf(gs[jj], xa.y, acc[jj][1]);
                acc[jj][2] = fmaf(gs[jj], xa.z, acc[jj][2]);
                acc[jj][3] = fmaf(gs[jj], xa.w, acc[jj][3]);
                acc[jj][4] = fmaf(gs[jj], xc.x, acc[jj][4]);
                acc[jj][5] = fmaf(gs[jj], xc.y, acc[jj][5]);
                acc[jj][6] = fmaf(gs[jj], xc.z, acc[jj][6]);
                acc[jj][7] = fmaf(gs[jj], xc.w, acc[jj][7]);
            }
        }
        __syncthreads();
    }

    // stage M (33 x 256) into smem (aliases gather buffers; all reads done)
    float* sM = px;
    #pragma unroll
    for(int jj=0;jj<4;jj++){
        int j = jg*4 + jj;
        if(j < 33){
            *(float4*)&sM[j*256 + 4*cg]       = make_float4(acc[jj][0],acc[jj][1],acc[jj][2],acc[jj][3]);
            *(float4*)&sM[j*256 + 128 + 4*cg] = make_float4(acc[jj][4],acc[jj][5],acc[jj][6],acc[jj][7]);
        }
    }
    __syncthreads();

    // ======================= W2 EPILOGUE (transposed weights) ==============
    // y[b,d] = sum_{j,c} M[j,b*32+c] * W2t[j,d,c]; 2 batches/thread, 8 chains
    if(tid < 256){
        const int b_ = tid>>6, d_ = tid&63;
        float a00=0.f,a01=0.f,a02=0.f,a03=0.f;
        float a10=0.f,a11=0.f,a12=0.f,a13=0.f;
        for(int j=0;j<33;j++){
            const float4* w4 = (const float4*)&d_W2t[(j*64+d_)*32];
            const float4* m0 = (const float4*)&sM[j*256 + b_*32];
            const float4* m1 = (const float4*)&sM[j*256 + 128 + b_*32];
            #pragma unroll
            for(int c4=0;c4<8;c4++){
                float4 wv  = w4[c4];
                float4 mv0 = m0[c4];
                float4 mv1 = m1[c4];
                a00 = fmaf(mv0.x, wv.x, a00);
                a01 = fmaf(mv0.y, wv.y, a01);
                a02 = fmaf(mv0.z, wv.z, a02);
                a03 = fmaf(mv0.w, wv.w, a03);
                a10 = fmaf(mv1.x, wv.x, a10);
                a11 = fmaf(mv1.y, wv.y, a11);
                a12 = fmaf(mv1.z, wv.z, a12);
                a13 = fmaf(mv1.w, wv.w, a13);
            }
        }
        float a0 = (a00+a01)+(a02+a03);
        float a1 = (a10+a11)+(a12+a13);
        sy[b_*64+d_]     = gelu_f(a0 + bias[d_]);
        sy[(b_+4)*64+d_] = gelu_f(a1 + bias[d_]);
    }
    __syncthreads();

    // ======================= MLP (transposed weights) ======================
    // h1 = gelu(y @ Wm1 + bm1)   (sh1 aliases sg)
    float* sh1 = sg;
    for(int o=tid; o<BB*256; o+=NT){
        int b = o>>8, i = o&255;
        float a0=0.f,a1=0.f,a2=0.f,a3=0.f;
        const float4* w4 = (const float4*)&d_Wm1t[i*64];
        const float4* y4 = (const float4*)&sy[b*64];
        #pragma unroll
        for(int d4=0; d4<16; ++d4){
            float4 yv = y4[d4];
            float4 wv = w4[d4];
            a0 = fmaf(yv.x, wv.x, a0);
            a1 = fmaf(yv.y, wv.y, a1);
            a2 = fmaf(yv.z, wv.z, a2);
            a3 = fmaf(yv.w, wv.w, a3);
        }
        sh1[o] = gelu_f(((a0+a1)+(a2+a3)) + bm1[i]);
    }
    __syncthreads();

    // out = h1 @ Wm2 + bm2 + y
    for(int o=tid; o<BB*DD; o+=NT){
        int b = o>>6, d = o&63;
        float a0=0.f,a1=0.f,a2=0.f,a3=0.f;
        const float4* w4 = (const float4*)&d_Wm2t[d*256];
        const float4* h4 = (const float4*)&sh1[b*256];
        #pragma unroll
        for(int i4=0;i4<64;i4++){
            float4 hv = h4[i4];
            float4 wv = w4[i4];
            a0 = fmaf(hv.x, wv.x, a0);
            a1 = fmaf(hv.y, wv.y, a1);
            a2 = fmaf(hv.z, wv.z, a2);
            a3 = fmaf(hv.w, wv.w, a3);
        }
        out[(b*QQ + q)*DD + d] = (a0+a1)+(a2+a3) + bm2[d] + sy[o];
    }
}

// ---------------- launch --------------------------------------------------
extern "C" void kernel_launch(void* const* d_in, const int* in_sizes, int n_in,
                              void* d_out, int out_size){
    (void)in_sizes; (void)n_in; (void)out_size;
    const float* x     = (const float*)d_in[0];
    const float* pos   = (const float*)d_in[1];
    const float* qpos  = (const float*)d_in[2];
    const float* qmw   = (const float*)d_in[3];
    const float* qmo   = (const float*)d_in[4];
    const float* W_lin = (const float*)d_in[5];
    const float* b_lin = (const float*)d_in[6];
    const float* rffB  = (const float*)d_in[7];
    const float* W1    = (const float*)d_in[8];
    const float* b1    = (const float*)d_in[9];
    const float* W2    = (const float*)d_in[10];
    const float* filt  = (const float*)d_in[11];
    const float* bias  = (const float*)d_in[12];
    const float* Wm1   = (const float*)d_in[13];
    const float* bm1   = (const float*)d_in[14];
    const float* Wm2   = (const float*)d_in[15];
    const float* bm2   = (const float*)d_in[16];
    float* out = (float*)d_out;

    cudaFuncSetAttribute(k_fused, cudaFuncAttributeMaxDynamicSharedMemorySize, SMEM_BYTES);

    k_xl   <<<2048+10, 256>>>(x, W_lin, b_lin, qpos, out, W2, filt, Wm1, Wm2);
    k_fused<<<QQ, NT, SMEM_BYTES>>>(pos, qpos, rffB, W1, b1, qmw, qmo,
                                    bias, bm1, bm2, out);
}

// round 6
// speedup vs baseline: 1.8159x; 1.8159x over previous
#include <cuda_runtime.h>
#include <math.h>

#define BB 8
#define NN 2048
#define CC 32
#define DD 64
#define QQ 256
#define KK 205
#define JP 36           // padded j dimension (33 -> 36 for float4)
#define RANK (KK-1)
#define NT 384
#define NWARP 12

// ---------------- scratch ----------------
__device__ float d_xl[BB*NN*CC];        // 2 MB

__device__ __forceinline__ float gelu_f(float x){
    return 0.5f*x*(1.0f+erff(x*0.70710678118654752440f));
}

__device__ __forceinline__ void cp_async16(float* smem_dst, const float4* gsrc){
    unsigned sm = (unsigned)__cvta_generic_to_shared(smem_dst);
    asm volatile("cp.async.cg.shared.global [%0], [%1], 16;\n" :: "r"(sm), "l"(gsrc));
}
#define CP_COMMIT() asm volatile("cp.async.commit_group;\n")
#define CP_WAIT(n)  asm volatile("cp.async.wait_group %0;\n" :: "n"(n))

// ---------------- kernel A: xl = x @ W_lin + b_lin (+ query_pos copy) -----
__global__ __launch_bounds__(256) void k_xl(const float* __restrict__ x,
                                            const float* __restrict__ W,
                                            const float* __restrict__ bl,
                                            const float* __restrict__ qp,
                                            float* __restrict__ out){
    __shared__ float sW[CC*CC];
    int tid = threadIdx.x;
    for(int i=tid;i<CC*CC;i+=256) sW[i]=W[i];
    __syncthreads();
    int row  = blockIdx.x*8 + (tid>>5);
    int lane = tid&31;
    float xv  = x[row*CC + lane];
    float acc = bl[lane];
    #pragma unroll
    for(int ci=0;ci<CC;ci++)
        acc = fmaf(__shfl_sync(0xffffffffu, xv, ci), sW[ci*CC+lane], acc);
    d_xl[row*CC+lane] = acc;
    if(blockIdx.x < 2){
        int i = blockIdx.x*256 + tid;
        out[BB*QQ*DD + i] = qp[i];
    }
}

// ---------------- fused kernel ---------------------------------------------
// smem layout (floats). Total 24484 floats = 97,936 B -> 2 blocks/SM.
#define OFF_G   0                 // g 205*36=7380 (later reused as sh1 2048)
#define OFF_X   7380              // 16384: select scratch | gather bufs | sM
#define OFF_IND 23764             // 208 ints
#define OFF_Y   23972             // 512
#define SMEM_FLOATS 24484
#define SMEM_BYTES (SMEM_FLOATS*4)

// select-scratch offsets inside X region:
#define XS_ED    0                // 2048
#define XS_FEAT  2048             // 205*32 = 6560
#define XS_D0    8608
#define XS_D1    8813
#define XS_EDK   9018
#define XS_KD    9223
#define XS_W1    9428             // 1024
#define XS_B1    10452
#define XS_HIST  10484            // 256 (uint)
#define XS_RA    10740            // 12
#define XS_RB    10752            // 12
#define XS_SC    10764            // 6

__global__ __launch_bounds__(NT,2) void k_fused(
        const float* __restrict__ pos, const float* __restrict__ qpos,
        const float* __restrict__ rffB,
        const float* __restrict__ W1,  const float* __restrict__ b1,
        const float* __restrict__ qmw, const float* __restrict__ qmo,
        const float* __restrict__ W2,  const float* __restrict__ filt,
        const float* __restrict__ bias,
        const float* __restrict__ Wm1, const float* __restrict__ bm1,
        const float* __restrict__ Wm2, const float* __restrict__ bm2,
        float* __restrict__ out)
{
    extern __shared__ float smem[];
    float* sg  = smem + OFF_G;
    float* px  = smem + OFF_X;
    int*   sind= (int*)(smem + OFF_IND);
    float* sy  = smem + OFF_Y;

    const int q = blockIdx.x, tid = threadIdx.x;
    const int warp = tid>>5, lane = tid&31;
    const float qx = qpos[q*2], qy = qpos[q*2+1];

    // ======================= SELECT PHASE =======================
    {
        float* sed  = px + XS_ED;
        float* sfeat= px + XS_FEAT;
        float* sd0  = px + XS_D0;
        float* sd1  = px + XS_D1;
        float* sedk = px + XS_EDK;
        float* skd  = px + XS_KD;
        float* sW1  = px + XS_W1;
        float* sb1  = px + XS_B1;
        unsigned int* hist = (unsigned int*)(px + XS_HIST);
        float* rbufA= px + XS_RA;
        float* rbufB= px + XS_RB;
        unsigned int* s_prefix = (unsigned int*)(px + XS_SC);
        unsigned int* s_r      = (unsigned int*)(px + XS_SC + 1);
        unsigned int* s_cnt    = (unsigned int*)(px + XS_SC + 2);
        float* s_min = px + XS_SC + 3;
        float* s_max = px + XS_SC + 4;
        float* s_sum = px + XS_SC + 5;

        for(int i=tid;i<CC*CC;i+=NT) sW1[i]=W1[i];
        if(tid<CC) sb1[tid]=b1[tid];

        for(int n=tid;n<NN;n+=NT){
            float2 p = ((const float2*)pos)[n];
            float d0 = qx - p.x; d0 += 0.5f; d0 -= floorf(d0); d0 -= 0.5f;
            float d1 = qy - p.y; d1 += 0.5f; d1 -= floorf(d1); d1 -= 0.5f;
            sed[n] = d0*d0 + d1*d1;
        }
        if(tid==0){ *s_prefix=0u; *s_r=RANK; *s_cnt=0u; }
        __syncthreads();

        // 4-pass MSD radix select on float bits (all >= 0)
        for(int pass=0; pass<4; ++pass){
            const int shift = 24 - 8*pass;
            for(int i=tid;i<256;i+=NT) hist[i]=0u;
            __syncthreads();
            const unsigned int prefix = *s_prefix;
            const unsigned int hm = (pass==0) ? 0u : (0xFFFFFFFFu << (shift+8));
            for(int n=tid;n<NN;n+=NT){
                unsigned int k = __float_as_uint(sed[n]);
                if((k & hm) == prefix) atomicAdd(&hist[(k>>shift)&255u], 1u);
            }
            __syncthreads();
            if(tid==0){
                unsigned int cum=0, rr=*s_r; int bsel=255;
                for(int bkt=0;bkt<256;bkt++){
                    unsigned int c=hist[bkt];
                    if(cum + c > rr){ bsel=bkt; break; }
                    cum += c;
                }
                *s_prefix = prefix | ((unsigned int)bsel << shift);
                *s_r = rr - cum;
            }
            __syncthreads();
        }
        const unsigned int T = *s_prefix;

        for(int n=tid;n<NN;n+=NT){
            unsigned int k = __float_as_uint(sed[n]);
            if(k < T){ unsigned int p = atomicAdd(s_cnt,1u); sind[p]=n; }
        }
        __syncthreads();
        for(int n=tid;n<NN;n+=NT){
            unsigned int k = __float_as_uint(sed[n]);
            if(k == T){ unsigned int p = atomicAdd(s_cnt,1u); if(p<KK) sind[p]=n; }
        }
        __syncthreads();

        for(int k2=tid;k2<KK;k2+=NT){
            int n = sind[k2];
            float2 p = ((const float2*)pos)[n];
            float d0 = qx - p.x; d0 += 0.5f; d0 -= floorf(d0); d0 -= 0.5f;
            float d1 = qy - p.y; d1 += 0.5f; d1 -= floorf(d1); d1 -= 0.5f;
            sd0[k2]=d0; sd1[k2]=d1; sedk[k2]=sed[n];
        }
        __syncthreads();

        float mn = 1e30f, mx = -1e30f;
        for(int k2=tid;k2<KK;k2+=NT){ mn=fminf(mn,sedk[k2]); mx=fmaxf(mx,sedk[k2]); }
        #pragma unroll
        for(int o=16;o>0;o>>=1){
            mn = fminf(mn, __shfl_down_sync(0xffffffffu,mn,o));
            mx = fmaxf(mx, __shfl_down_sync(0xffffffffu,mx,o));
        }
        if(lane==0){ rbufA[warp]=mn; rbufB[warp]=mx; }
        __syncthreads();
        if(tid==0){
            float a=rbufA[0], b=rbufB[0];
            for(int w=1;w<NWARP;w++){ a=fminf(a,rbufA[w]); b=fmaxf(b,rbufB[w]); }
            *s_min=a; *s_max=b;
        }
        __syncthreads();

        const float inv = 1.0f/(*s_max - *s_min + 1e-8f);
        const float smin = *s_min;
        float lsum = 0.0f;
        for(int k2=tid;k2<KK;k2+=NT){
            float w = expf(-(sedk[k2]-smin)*inv);
            skd[k2]=w; lsum+=w;
        }
        #pragma unroll
        for(int o=16;o>0;o>>=1) lsum += __shfl_down_sync(0xffffffffu,lsum,o);
        if(lane==0) rbufA[warp]=lsum;
        __syncthreads();
        if(tid==0){
            float s=0.f; for(int w=0;w<NWARP;w++) s+=rbufA[w];
            *s_sum=s;
        }
        __syncthreads();
        const float invsum = 1.0f/(*s_sum);

        for(int i=tid;i<KK*16;i+=NT){
            int k2=i>>4, j=i&15;
            float pr = 6.28318530717958647692f*(sd0[k2]*rffB[j] + sd1[k2]*rffB[16+j]);
            float s,c; sincosf(pr,&s,&c);
            sfeat[k2*32+j]=s; sfeat[k2*32+16+j]=c;
        }
        __syncthreads();

        // g = gelu((feat@W1+b1)*qmw+qmo)*kd ; ch 32 = kd; pad 33..35
        for(int i=tid;i<KK*CC;i+=NT){
            int k2=i>>5, ii=i&31;
            float acc = sb1[ii];
            const float* fr = &sfeat[k2*32];
            #pragma unroll
            for(int f=0;f<CC;f++) acc = fmaf(fr[f], sW1[f*CC+ii], acc);
            float h = acc*qmw[q*CC+ii] + qmo[q*CC+ii];
            sg[k2*JP + ii] = gelu_f(h) * (skd[k2]*invsum);
        }
        for(int k2=tid;k2<KK;k2+=NT){
            sg[k2*JP+32] = skd[k2]*invsum;
            sg[k2*JP+33] = 0.f; sg[k2*JP+34] = 0.f; sg[k2*JP+35] = 0.f;
        }
        __syncthreads();
    }
    // ======================= M-GEMM PHASE =======================
    // 12 warps x 3 j-rows each (rows 33..35 are zero padding; warp 11 skips store)
    const int jg = warp;       // 0..11
    const int cg = lane;       // 0..31

    float acc[3][8];
    #pragma unroll
    for(int jj=0;jj<3;jj++)
        #pragma unroll
        for(int cc=0;cc<8;cc++) acc[jj][cc]=0.f;

    float* xb0 = px;
    float* xb1 = px + 8192;

    {
        for(int i=tid;i<32*64;i+=NT){
            int kk=i>>6, ch=i&63, b=ch>>3, c4=ch&7;
            int n = sind[kk];
            cp_async16(&xb0[kk*256 + ch*4], (const float4*)&d_xl[((b<<11)+n)*CC] + c4);
        }
        CP_COMMIT();
    }

    const int NCH = (KK + 31)/32;  // 7
    for(int ci=0; ci<NCH; ++ci){
        const int k0 = ci*32;
        const int nk = (KK-k0 < 32) ? (KK-k0) : 32;
        if(ci+1 < NCH){
            const int k0n = k0+32;
            const int nkn = (KK-k0n < 32) ? (KK-k0n) : 32;
            float* dst = (ci&1) ? xb0 : xb1;
            for(int i=tid;i<nkn*64;i+=NT){
                int kk=i>>6, ch=i&63, b=ch>>3, c4=ch&7;
                int n = sind[k0n+kk];
                cp_async16(&dst[kk*256 + ch*4], (const float4*)&d_xl[((b<<11)+n)*CC] + c4);
            }
            CP_COMMIT();
            CP_WAIT(1);
        } else {
            CP_WAIT(0);
        }
        __syncthreads();
        const float4* sx4 = (const float4*)((ci&1) ? xb1 : xb0);
        #pragma unroll 2
        for(int kk=0; kk<nk; ++kk){
            const float* grow = &sg[(k0+kk)*JP + jg*3];
            float g0 = grow[0], g1 = grow[1], g2 = grow[2];
            float4 xa = sx4[kk*64 + cg];
            float4 xc = sx4[kk*64 + 32 + cg];
            acc[0][0] = fmaf(g0, xa.x, acc[0][0]);
            acc[0][1] = fmaf(g0, xa.y, acc[0][1]);
            acc[0][2] = fmaf(g0, xa.z, acc[0][2]);
            acc[0][3] = fmaf(g0, xa.w, acc[0][3]);
            acc[0][4] = fmaf(g0, xc.x, acc[0][4]);
            acc[0][5] = fmaf(g0, xc.y, acc[0][5]);
            acc[0][6] = fmaf(g0, xc.z, acc[0][6]);
            acc[0][7] = fmaf(g0, xc.w, acc[0][7]);
            acc[1][0] = fmaf(g1, xa.x, acc[1][0]);
            acc[1][1] = fmaf(g1, xa.y, acc[1][1]);
            acc[1][2] = fmaf(g1, xa.z, acc[1][2]);
            acc[1][3] = fmaf(g1, xa.w, acc[1][3]);
            acc[1][4] = fmaf(g1, xc.x, acc[1][4]);
            acc[1][5] = fmaf(g1, xc.y, acc[1][5]);
            acc[1][6] = fmaf(g1, xc.z, acc[1][6]);
            acc[1][7] = fmaf(g1, xc.w, acc[1][7]);
            acc[2][0] = fmaf(g2, xa.x, acc[2][0]);
            acc[2][1] = fmaf(g2, xa.y, acc[2][1]);
            acc[2][2] = fmaf(g2, xa.z, acc[2][2]);
            acc[2][3] = fmaf(g2, xa.w, acc[2][3]);
            acc[2][4] = fmaf(g2, xc.x, acc[2][4]);
            acc[2][5] = fmaf(g2, xc.y, acc[2][5]);
            acc[2][6] = fmaf(g2, xc.z, acc[2][6]);
            acc[2][7] = fmaf(g2, xc.w, acc[2][7]);
        }
        __syncthreads();
    }

    // stage M (33 x 256) into smem (aliases gather buffers; all reads done)
    float* sM = px;
    #pragma unroll
    for(int jj=0;jj<3;jj++){
        int j = jg*3 + jj;
        if(j < 33){
            *(float4*)&sM[j*256 + 4*cg]       = make_float4(acc[jj][0],acc[jj][1],acc[jj][2],acc[jj][3]);
            *(float4*)&sM[j*256 + 128 + 4*cg] = make_float4(acc[jj][4],acc[jj][5],acc[jj][6],acc[jj][7]);
        }
    }
    __syncthreads();

    // ======================= W2 EPILOGUE =======================
    // y[b,d] = sum_{j,c} M[j,b*32+c]*W2ext[j,c,d]; coalesced scalar W2 loads
    if(tid < 256){
        const int b_ = tid>>6, d_ = tid&63;
        float a00=0.f,a01=0.f,a02=0.f,a03=0.f;
        float a10=0.f,a11=0.f,a12=0.f,a13=0.f;
        for(int j=0;j<33;j++){
            const float* wrow = (j<32) ? (W2 + j*2048 + d_) : (filt + d_);
            const float4* m0 = (const float4*)&sM[j*256 + b_*32];
            const float4* m1 = (const float4*)&sM[j*256 + 128 + b_*32];
            #pragma unroll
            for(int c4=0;c4<8;c4++){
                float4 mv0 = m0[c4];
                float4 mv1 = m1[c4];
                float w0 = wrow[(4*c4+0)*64];
                float w1 = wrow[(4*c4+1)*64];
                float w2 = wrow[(4*c4+2)*64];
                float w3 = wrow[(4*c4+3)*64];
                a00 = fmaf(mv0.x, w0, a00);
                a01 = fmaf(mv0.y, w1, a01);
                a02 = fmaf(mv0.z, w2, a02);
                a03 = fmaf(mv0.w, w3, a03);
                a10 = fmaf(mv1.x, w0, a10);
                a11 = fmaf(mv1.y, w1, a11);
                a12 = fmaf(mv1.z, w2, a12);
                a13 = fmaf(mv1.w, w3, a13);
            }
        }
        float a0 = (a00+a01)+(a02+a03);
        float a1 = (a10+a11)+(a12+a13);
        sy[b_*64+d_]     = gelu_f(a0 + bias[d_]);
        sy[(b_+4)*64+d_] = gelu_f(a1 + bias[d_]);
    }
    __syncthreads();

    // ======================= MLP =======================
    // h1 = gelu(y @ Wm1 + bm1)   (sh1 aliases sg)
    float* sh1 = sg;
    for(int o=tid; o<BB*256; o+=NT){
        int b = o>>8, i = o&255;
        float a = bm1[i];
        const float4* y4 = (const float4*)&sy[b*64];
        #pragma unroll
        for(int d4=0; d4<16; ++d4){
            float4 yv = y4[d4];
            a = fmaf(yv.x, Wm1[(4*d4+0)*256+i], a);
            a = fmaf(yv.y, Wm1[(4*d4+1)*256+i], a);
            a = fmaf(yv.z, Wm1[(4*d4+2)*256+i], a);
            a = fmaf(yv.w, Wm1[(4*d4+3)*256+i], a);
        }
        sh1[o] = gelu_f(a);
    }
    __syncthreads();

    // out = h1 @ Wm2 + bm2 + y
    for(int o=tid; o<BB*DD; o+=NT){
        int b = o>>6, d = o&63;
        float a0=0.f,a1=0.f,a2=0.f,a3=0.f;
        const float4* h4 = (const float4*)&sh1[b*256];
        #pragma unroll
        for(int i4=0;i4<64;i4++){
            float4 hv = h4[i4];
            a0 = fmaf(hv.x, Wm2[(4*i4+0)*64+d], a0);
            a1 = fmaf(hv.y, Wm2[(4*i4+1)*64+d], a1);
            a2 = fmaf(hv.z, Wm2[(4*i4+2)*64+d], a2);
            a3 = fmaf(hv.w, Wm2[(4*i4+3)*64+d], a3);
        }
        out[(b*QQ + q)*DD + d] = (a0+a1)+(a2+a3) + bm2[d] + sy[o];
    }
}

// ---------------- launch --------------------------------------------------
extern "C" void kernel_launch(void* const* d_in, const int* in_sizes, int n_in,
                              void* d_out, int out_size){
    (void)in_sizes; (void)n_in; (void)out_size;
    const float* x     = (const float*)d_in[0];
    const float* pos   = (const float*)d_in[1];
    const float* qpos  = (const float*)d_in[2];
    const float* qmw   = (const float*)d_in[3];
    const float* qmo   = (const float*)d_in[4];
    const float* W_lin = (const float*)d_in[5];
    const float* b_lin = (const float*)d_in[6];
    const float* rffB  = (const float*)d_in[7];
    const float* W1    = (const float*)d_in[8];
    const float* b1    = (const float*)d_in[9];
    const float* W2    = (const float*)d_in[10];
    const float* filt  = (const float*)d_in[11];
    const float* bias  = (const float*)d_in[12];
    const float* Wm1   = (const float*)d_in[13];
    const float* bm1   = (const float*)d_in[14];
    const float* Wm2   = (const float*)d_in[15];
    const float* bm2   = (const float*)d_in[16];
    float* out = (float*)d_out;

    cudaFuncSetAttribute(k_fused, cudaFuncAttributeMaxDynamicSharedMemorySize, SMEM_BYTES);

    k_xl   <<<BB*NN/8, 256>>>(x, W_lin, b_lin, qpos, out);
    k_fused<<<QQ, NT, SMEM_BYTES>>>(pos, qpos, rffB, W1, b1, qmw, qmo,
                                    W2, filt, bias, Wm1, bm1, Wm2, bm2, out);
}

// round 7
// speedup vs baseline: 2.2542x; 1.2413x over previous
#include <cuda_runtime.h>
#include <math.h>

#define BB 8
#define NN 2048
#define CC 32
#define DD 64
#define QQ 256
#define KK 205
#define JP 36           // padded j dimension (33 -> 36 for float4)
#define RANK (KK-1)
#define NT 288

typedef unsigned long long u64t;

// ---------------- scratch ----------------
__device__ float d_xl[BB*NN*CC];        // 2 MB

__device__ __forceinline__ float gelu_f(float x){
    return 0.5f*x*(1.0f+erff(x*0.70710678118654752440f));
}

__device__ __forceinline__ void cp_async16(float* smem_dst, const float4* gsrc){
    unsigned sm = (unsigned)__cvta_generic_to_shared(smem_dst);
    asm volatile("cp.async.cg.shared.global [%0], [%1], 16;\n" :: "r"(sm), "l"(gsrc));
}
#define CP_COMMIT() asm volatile("cp.async.commit_group;\n")
#define CP_WAIT(n)  asm volatile("cp.async.wait_group %0;\n" :: "n"(n))

// ---- packed fp32x2 helpers (Blackwell FFMA2) ----
__device__ __forceinline__ u64t pack_dup(float x){
    u64t r; unsigned u = __float_as_uint(x);
    asm("mov.b64 %0, {%1,%1};" : "=l"(r) : "r"(u));
    return r;
}
__device__ __forceinline__ u64t pack2(float lo, float hi){
    u64t r; unsigned a = __float_as_uint(lo), b = __float_as_uint(hi);
    asm("mov.b64 %0, {%1,%2};" : "=l"(r) : "r"(a), "r"(b));
    return r;
}
__device__ __forceinline__ void ffma2(u64t& d, u64t a, u64t b){
    asm("fma.rn.f32x2 %0, %1, %2, %0;" : "+l"(d) : "l"(a), "l"(b));
}
__device__ __forceinline__ float2 unpack2(u64t v){
    unsigned lo, hi;
    asm("mov.b64 {%0,%1}, %2;" : "=r"(lo), "=r"(hi) : "l"(v));
    return make_float2(__uint_as_float(lo), __uint_as_float(hi));
}

// ---------------- kernel A: xl = x @ W_lin + b_lin (+ query_pos copy) -----
__global__ __launch_bounds__(256) void k_xl(const float* __restrict__ x,
                                            const float* __restrict__ W,
                                            const float* __restrict__ bl,
                                            const float* __restrict__ qp,
                                            float* __restrict__ out){
    __shared__ float sW[CC*CC];
    int tid = threadIdx.x;
    for(int i=tid;i<CC*CC;i+=256) sW[i]=W[i];
    __syncthreads();
    int row  = blockIdx.x*8 + (tid>>5);
    int lane = tid&31;
    float xv  = x[row*CC + lane];
    float acc = bl[lane];
    #pragma unroll
    for(int ci=0;ci<CC;ci++)
        acc = fmaf(__shfl_sync(0xffffffffu, xv, ci), sW[ci*CC+lane], acc);
    d_xl[row*CC+lane] = acc;
    if(blockIdx.x < 2){
        int i = blockIdx.x*256 + tid;
        out[BB*QQ*DD + i] = qp[i];
    }
}

// ---------------- fused kernel ---------------------------------------------
// smem layout (floats). Total 24484 floats = 97,936 B -> 2 blocks/SM.
#define OFF_G   0                 // g 205*36=7380 (later reused as sh1 2048)
#define OFF_X   7380              // 16384: select scratch | gather bufs | sM
#define OFF_IND 23764             // 208 ints
#define OFF_Y   23972             // 512
#define SMEM_FLOATS 24484
#define SMEM_BYTES (SMEM_FLOATS*4)

// select-scratch offsets inside X region:
#define XS_ED    0                // 2048
#define XS_FEAT  2048             // 205*32 = 6560
#define XS_D0    8608
#define XS_D1    8813
#define XS_EDK   9018
#define XS_KD    9223
#define XS_W1    9428             // 1024
#define XS_B1    10452
#define XS_HIST  10484            // 256 (uint)
#define XS_RA    10740
#define XS_RB    10749
#define XS_SC    10758

__global__ __launch_bounds__(NT,2) void k_fused(
        const float* __restrict__ pos, const float* __restrict__ qpos,
        const float* __restrict__ rffB,
        const float* __restrict__ W1,  const float* __restrict__ b1,
        const float* __restrict__ qmw, const float* __restrict__ qmo,
        const float* __restrict__ W2,  const float* __restrict__ filt,
        const float* __restrict__ bias,
        const float* __restrict__ Wm1, const float* __restrict__ bm1,
        const float* __restrict__ Wm2, const float* __restrict__ bm2,
        float* __restrict__ out)
{
    extern __shared__ float smem[];
    float* sg  = smem + OFF_G;
    float* px  = smem + OFF_X;
    int*   sind= (int*)(smem + OFF_IND);
    float* sy  = smem + OFF_Y;

    const int q = blockIdx.x, tid = threadIdx.x;
    const int warp = tid>>5, lane = tid&31;
    const float qx = qpos[q*2], qy = qpos[q*2+1];

    // ======================= SELECT PHASE =======================
    {
        float* sed  = px + XS_ED;
        float* sfeat= px + XS_FEAT;
        float* sd0  = px + XS_D0;
        float* sd1  = px + XS_D1;
        float* sedk = px + XS_EDK;
        float* skd  = px + XS_KD;
        float* sW1  = px + XS_W1;
        float* sb1  = px + XS_B1;
        unsigned int* hist = (unsigned int*)(px + XS_HIST);
        float* rbufA= px + XS_RA;
        float* rbufB= px + XS_RB;
        unsigned int* s_prefix = (unsigned int*)(px + XS_SC);
        unsigned int* s_r      = (unsigned int*)(px + XS_SC + 1);
        unsigned int* s_cnt    = (unsigned int*)(px + XS_SC + 2);
        float* s_min = px + XS_SC + 3;
        float* s_max = px + XS_SC + 4;
        float* s_sum = px + XS_SC + 5;

        for(int i=tid;i<CC*CC;i+=NT) sW1[i]=W1[i];
        if(tid<CC) sb1[tid]=b1[tid];

        for(int n=tid;n<NN;n+=NT){
            float2 p = ((const float2*)pos)[n];
            float d0 = qx - p.x; d0 += 0.5f; d0 -= floorf(d0); d0 -= 0.5f;
            float d1 = qy - p.y; d1 += 0.5f; d1 -= floorf(d1); d1 -= 0.5f;
            sed[n] = d0*d0 + d1*d1;
        }
        if(tid==0){ *s_prefix=0u; *s_r=RANK; *s_cnt=0u; }
        __syncthreads();

        // 4-pass MSD radix select on float bits (all >= 0)
        for(int pass=0; pass<4; ++pass){
            const int shift = 24 - 8*pass;
            for(int i=tid;i<256;i+=NT) hist[i]=0u;
            __syncthreads();
            const unsigned int prefix = *s_prefix;
            const unsigned int hm = (pass==0) ? 0u : (0xFFFFFFFFu << (shift+8));
            for(int n=tid;n<NN;n+=NT){
                unsigned int k = __float_as_uint(sed[n]);
                if((k & hm) == prefix) atomicAdd(&hist[(k>>shift)&255u], 1u);
            }
            __syncthreads();
            if(tid==0){
                unsigned int cum=0, rr=*s_r; int bsel=255;
                for(int bkt=0;bkt<256;bkt++){
                    unsigned int c=hist[bkt];
                    if(cum + c > rr){ bsel=bkt; break; }
                    cum += c;
                }
                *s_prefix = prefix | ((unsigned int)bsel << shift);
                *s_r = rr - cum;
            }
            __syncthreads();
        }
        const unsigned int T = *s_prefix;

        for(int n=tid;n<NN;n+=NT){
            unsigned int k = __float_as_uint(sed[n]);
            if(k < T){ unsigned int p = atomicAdd(s_cnt,1u); sind[p]=n; }
        }
        __syncthreads();
        for(int n=tid;n<NN;n+=NT){
            unsigned int k = __float_as_uint(sed[n]);
            if(k == T){ unsigned int p = atomicAdd(s_cnt,1u); if(p<KK) sind[p]=n; }
        }
        __syncthreads();

        for(int k2=tid;k2<KK;k2+=NT){
            int n = sind[k2];
            float2 p = ((const float2*)pos)[n];
            float d0 = qx - p.x; d0 += 0.5f; d0 -= floorf(d0); d0 -= 0.5f;
            float d1 = qy - p.y; d1 += 0.5f; d1 -= floorf(d1); d1 -= 0.5f;
            sd0[k2]=d0; sd1[k2]=d1; sedk[k2]=sed[n];
        }
        __syncthreads();

        float mn = 1e30f, mx = -1e30f;
        for(int k2=tid;k2<KK;k2+=NT){ mn=fminf(mn,sedk[k2]); mx=fmaxf(mx,sedk[k2]); }
        #pragma unroll
        for(int o=16;o>0;o>>=1){
            mn = fminf(mn, __shfl_down_sync(0xffffffffu,mn,o));
            mx = fmaxf(mx, __shfl_down_sync(0xffffffffu,mx,o));
        }
        if(lane==0){ rbufA[warp]=mn; rbufB[warp]=mx; }
        __syncthreads();
        if(tid==0){
            float a=rbufA[0], b=rbufB[0];
            for(int w=1;w<9;w++){ a=fminf(a,rbufA[w]); b=fmaxf(b,rbufB[w]); }
            *s_min=a; *s_max=b;
        }
        __syncthreads();

        const float inv = 1.0f/(*s_max - *s_min + 1e-8f);
        const float smin = *s_min;
        float lsum = 0.0f;
        for(int k2=tid;k2<KK;k2+=NT){
            float w = expf(-(sedk[k2]-smin)*inv);
            skd[k2]=w; lsum+=w;
        }
        #pragma unroll
        for(int o=16;o>0;o>>=1) lsum += __shfl_down_sync(0xffffffffu,lsum,o);
        if(lane==0) rbufA[warp]=lsum;
        __syncthreads();
        if(tid==0){
            float s=0.f; for(int w=0;w<9;w++) s+=rbufA[w];
            *s_sum=s;
        }
        __syncthreads();
        const float invsum = 1.0f/(*s_sum);

        for(int i=tid;i<KK*16;i+=NT){
            int k2=i>>4, j=i&15;
            float pr = 6.28318530717958647692f*(sd0[k2]*rffB[j] + sd1[k2]*rffB[16+j]);
            float s,c; sincosf(pr,&s,&c);
            sfeat[k2*32+j]=s; sfeat[k2*32+16+j]=c;
        }
        __syncthreads();

        // g = gelu((feat@W1+b1)*qmw+qmo)*kd ; ch 32 = kd; pad 33..35
        for(int i=tid;i<KK*CC;i+=NT){
            int k2=i>>5, ii=i&31;
            float acc = sb1[ii];
            const float* fr = &sfeat[k2*32];
            #pragma unroll
            for(int f=0;f<CC;f++) acc = fmaf(fr[f], sW1[f*CC+ii], acc);
            float h = acc*qmw[q*CC+ii] + qmo[q*CC+ii];
            sg[k2*JP + ii] = gelu_f(h) * (skd[k2]*invsum);
        }
        for(int k2=tid;k2<KK;k2+=NT){
            sg[k2*JP+32] = skd[k2]*invsum;
            sg[k2*JP+33] = 0.f; sg[k2*JP+34] = 0.f; sg[k2*JP+35] = 0.f;
        }
        __syncthreads();
    }
    // ======================= M-GEMM PHASE (packed f32x2) =======================
    const int jg = tid>>5;     // 0..8
    const int cg = tid&31;     // 0..31

    u64t acc2[4][4];
    #pragma unroll
    for(int jj=0;jj<4;jj++)
        #pragma unroll
        for(int p=0;p<4;p++) acc2[jj][p]=0ull;

    const float4* sg4 = (const float4*)sg;
    float* xb0 = px;
    float* xb1 = px + 8192;

    {
        for(int i=tid;i<32*64;i+=NT){
            int kk=i>>6, ch=i&63, b=ch>>3, c4=ch&7;
            int n = sind[kk];
            cp_async16(&xb0[kk*256 + ch*4], (const float4*)&d_xl[((b<<11)+n)*CC] + c4);
        }
        CP_COMMIT();
    }

    const int NCH = (KK + 31)/32;  // 7
    for(int ci=0; ci<NCH; ++ci){
        const int k0 = ci*32;
        const int nk = (KK-k0 < 32) ? (KK-k0) : 32;
        if(ci+1 < NCH){
            const int k0n = k0+32;
            const int nkn = (KK-k0n < 32) ? (KK-k0n) : 32;
            float* dst = (ci&1) ? xb0 : xb1;
            for(int i=tid;i<nkn*64;i+=NT){
                int kk=i>>6, ch=i&63, b=ch>>3, c4=ch&7;
                int n = sind[k0n+kk];
                cp_async16(&dst[kk*256 + ch*4], (const float4*)&d_xl[((b<<11)+n)*CC] + c4);
            }
            CP_COMMIT();
            CP_WAIT(1);
        } else {
            CP_WAIT(0);
        }
        __syncthreads();
        const ulonglong2* sxu = (const ulonglong2*)((ci&1) ? xb1 : xb0);
        #pragma unroll 2
        for(int kk=0; kk<nk; ++kk){
            float4 g4v = sg4[(k0+kk)*(JP/4) + jg];
            u64t gg0 = pack_dup(g4v.x);
            u64t gg1 = pack_dup(g4v.y);
            u64t gg2 = pack_dup(g4v.z);
            u64t gg3 = pack_dup(g4v.w);
            ulonglong2 xa = sxu[kk*64 + cg];        // cols (4cg,4cg+1),(4cg+2,4cg+3)   b 0..3
            ulonglong2 xc = sxu[kk*64 + 32 + cg];   // cols +128                        b 4..7
            ffma2(acc2[0][0], gg0, xa.x); ffma2(acc2[0][1], gg0, xa.y);
            ffma2(acc2[0][2], gg0, xc.x); ffma2(acc2[0][3], gg0, xc.y);
            ffma2(acc2[1][0], gg1, xa.x); ffma2(acc2[1][1], gg1, xa.y);
            ffma2(acc2[1][2], gg1, xc.x); ffma2(acc2[1][3], gg1, xc.y);
            ffma2(acc2[2][0], gg2, xa.x); ffma2(acc2[2][1], gg2, xa.y);
            ffma2(acc2[2][2], gg2, xc.x); ffma2(acc2[2][3], gg2, xc.y);
            ffma2(acc2[3][0], gg3, xa.x); ffma2(acc2[3][1], gg3, xa.y);
            ffma2(acc2[3][2], gg3, xc.x); ffma2(acc2[3][3], gg3, xc.y);
        }
        __syncthreads();
    }

    // stage M (33 x 256) into smem (aliases gather buffers; all reads done)
    float* sM = px;
    #pragma unroll
    for(int jj=0;jj<4;jj++){
        int j = jg*4 + jj;
        if(j < 33){
            ulonglong2 v0; v0.x = acc2[jj][0]; v0.y = acc2[jj][1];
            ulonglong2 v1; v1.x = acc2[jj][2]; v1.y = acc2[jj][3];
            *(ulonglong2*)&sM[j*256 + 4*cg]       = v0;
            *(ulonglong2*)&sM[j*256 + 128 + 4*cg] = v1;
        }
    }
    __syncthreads();

    // ======================= W2 EPILOGUE (packed f32x2, branch-free) ========
    // y[b,d] = sum_{j,c} M[j,b*32+c]*W2ext[j,c,d]
    if(tid < 256){
        const int b_ = tid>>6, d_ = tid&63;
        u64t A0=0ull, A1=0ull, A2=0ull, A3=0ull;
        const ulonglong2* sMu = (const ulonglong2*)sM;
        #pragma unroll 4
        for(int j=0;j<32;j++){
            const float* wrow = W2 + (j<<11) + d_;
            const int base0 = (j<<4) + (b_<<1);     // ulonglong2 idx: j*64/4... (j*256+b_*32)/16B
            #pragma unroll
            for(int c4=0;c4<8;c4++){
                ulonglong2 p0 = sMu[(j<<6) + (b_<<3) + c4];
                ulonglong2 p1 = sMu[(j<<6) + 32 + (b_<<3) + c4];
                float w0 = wrow[(4*c4+0)*64];
                float w1 = wrow[(4*c4+1)*64];
                float w2 = wrow[(4*c4+2)*64];
                float w3 = wrow[(4*c4+3)*64];
                u64t W01 = pack2(w0,w1);
                u64t W23 = pack2(w2,w3);
                ffma2(A0, p0.x, W01); ffma2(A1, p0.y, W23);
                ffma2(A2, p1.x, W01); ffma2(A3, p1.y, W23);
            }
            (void)base0;
        }
        {   // j = 32: filt row
            const float* wrow = filt + d_;
            #pragma unroll
            for(int c4=0;c4<8;c4++){
                ulonglong2 p0 = sMu[(32<<6) + (b_<<3) + c4];
                ulonglong2 p1 = sMu[(32<<6) + 32 + (b_<<3) + c4];
                float w0 = wrow[(4*c4+0)*64];
                float w1 = wrow[(4*c4+1)*64];
                float w2 = wrow[(4*c4+2)*64];
                float w3 = wrow[(4*c4+3)*64];
                u64t W01 = pack2(w0,w1);
                u64t W23 = pack2(w2,w3);
                ffma2(A0, p0.x, W01); ffma2(A1, p0.y, W23);
                ffma2(A2, p1.x, W01); ffma2(A3, p1.y, W23);
            }
        }
        float2 f0 = unpack2(A0), f1 = unpack2(A1);
        float2 f2 = unpack2(A2), f3 = unpack2(A3);
        float a0 = (f0.x+f0.y)+(f1.x+f1.y);
        float a1 = (f2.x+f2.y)+(f3.x+f3.y);
        sy[b_*64+d_]     = gelu_f(a0 + bias[d_]);
        sy[(b_+4)*64+d_] = gelu_f(a1 + bias[d_]);
    }
    __syncthreads();

    // ======================= MLP =======================
    // h1 = gelu(y @ Wm1 + bm1)   (sh1 aliases sg)
    float* sh1 = sg;
    for(int o=tid; o<BB*256; o+=NT){
        int b = o>>8, i = o&255;
        float a = bm1[i];
        const float4* y4 = (const float4*)&sy[b*64];
        #pragma unroll
        for(int d4=0; d4<16; ++d4){
            float4 yv = y4[d4];
            a = fmaf(yv.x, Wm1[(4*d4+0)*256+i], a);
            a = fmaf(yv.y, Wm1[(4*d4+1)*256+i], a);
            a = fmaf(yv.z, Wm1[(4*d4+2)*256+i], a);
            a = fmaf(yv.w, Wm1[(4*d4+3)*256+i], a);
        }
        sh1[o] = gelu_f(a);
    }
    __syncthreads();

    // out = h1 @ Wm2 + bm2 + y
    for(int o=tid; o<BB*DD; o+=NT){
        int b = o>>6, d = o&63;
        float a0=0.f,a1=0.f,a2=0.f,a3=0.f;
        const float4* h4 = (const float4*)&sh1[b*256];
        #pragma unroll
        for(int i4=0;i4<64;i4++){
            float4 hv = h4[i4];
            a0 = fmaf(hv.x, Wm2[(4*i4+0)*64+d], a0);
            a1 = fmaf(hv.y, Wm2[(4*i4+1)*64+d], a1);
            a2 = fmaf(hv.z, Wm2[(4*i4+2)*64+d], a2);
            a3 = fmaf(hv.w, Wm2[(4*i4+3)*64+d], a3);
        }
        out[(b*QQ + q)*DD + d] = (a0+a1)+(a2+a3) + bm2[d] + sy[o];
    }
}

// ---------------- launch --------------------------------------------------
extern "C" void kernel_launch(void* const* d_in, const int* in_sizes, int n_in,
                              void* d_out, int out_size){
    (void)in_sizes; (void)n_in; (void)out_size;
    const float* x     = (const float*)d_in[0];
    const float* pos   = (const float*)d_in[1];
    const float* qpos  = (const float*)d_in[2];
    const float* qmw   = (const float*)d_in[3];
    const float* qmo   = (const float*)d_in[4];
    const float* W_lin = (const float*)d_in[5];
    const float* b_lin = (const float*)d_in[6];
    const float* rffB  = (const float*)d_in[7];
    const float* W1    = (const float*)d_in[8];
    const float* b1    = (const float*)d_in[9];
    const float* W2    = (const float*)d_in[10];
    const float* filt  = (const float*)d_in[11];
    const float* bias  = (const float*)d_in[12];
    const float* Wm1   = (const float*)d_in[13];
    const float* bm1   = (const float*)d_in[14];
    const float* Wm2   = (const float*)d_in[15];
    const float* bm2   = (const float*)d_in[16];
    float* out = (float*)d_out;

    cudaFuncSetAttribute(k_fused, cudaFuncAttributeMaxDynamicSharedMemorySize, SMEM_BYTES);

    k_xl   <<<BB*NN/8, 256>>>(x, W_lin, b_lin, qpos, out);
    k_fused<<<QQ, NT, SMEM_BYTES>>>(pos, qpos, rffB, W1, b1, qmw, qmo,
                                    W2, filt, bias, Wm1, bm1, Wm2, bm2, out);
}

// round 8
// speedup vs baseline: 2.4890x; 1.1042x over previous
#include <cuda_runtime.h>
#include <math.h>

#define BB 8
#define NN 2048
#define CC 32
#define DD 64
#define QQ 256
#define KK 205
#define JP 36           // padded j dimension (33 -> 36 for float4)
#define RANK (KK-1)
#define NT 288

typedef unsigned long long u64t;

// ---------------- scratch ----------------
__device__ float d_xl[BB*NN*CC];        // 2 MB
__device__ float d_Wm1b[16384];         // Wm1 packed: [d/4][i][4]  (d-quad minor)
__device__ float d_Wm2b[16384];         // Wm2 packed: [i/4][d][4]  (i-quad minor)

__device__ __forceinline__ float gelu_f(float x){
    return 0.5f*x*(1.0f+erff(x*0.70710678118654752440f));
}

__device__ __forceinline__ void cp_async16(float* smem_dst, const float4* gsrc){
    unsigned sm = (unsigned)__cvta_generic_to_shared(smem_dst);
    asm volatile("cp.async.cg.shared.global [%0], [%1], 16;\n" :: "r"(sm), "l"(gsrc));
}
#define CP_COMMIT() asm volatile("cp.async.commit_group;\n")
#define CP_WAIT(n)  asm volatile("cp.async.wait_group %0;\n" :: "n"(n))

// ---- packed fp32x2 helpers (Blackwell FFMA2) ----
__device__ __forceinline__ u64t pack_dup(float x){
    u64t r; unsigned u = __float_as_uint(x);
    asm("mov.b64 %0, {%1,%1};" : "=l"(r) : "r"(u));
    return r;
}
__device__ __forceinline__ u64t pack2(float lo, float hi){
    u64t r; unsigned a = __float_as_uint(lo), b = __float_as_uint(hi);
    asm("mov.b64 %0, {%1,%2};" : "=l"(r) : "r"(a), "r"(b));
    return r;
}
__device__ __forceinline__ void ffma2(u64t& d, u64t a, u64t b){
    asm("fma.rn.f32x2 %0, %1, %2, %0;" : "+l"(d) : "l"(a), "l"(b));
}
__device__ __forceinline__ float2 unpack2(u64t v){
    unsigned lo, hi;
    asm("mov.b64 {%0,%1}, %2;" : "=r"(lo), "=r"(hi) : "l"(v));
    return make_float2(__uint_as_float(lo), __uint_as_float(hi));
}

// ---------------- kernel A: xl, qp copy, Wm packing -----------------------
__global__ __launch_bounds__(256) void k_xl(const float* __restrict__ x,
                                            const float* __restrict__ W,
                                            const float* __restrict__ bl,
                                            const float* __restrict__ qp,
                                            float* __restrict__ out,
                                            const float* __restrict__ Wm1,
                                            const float* __restrict__ Wm2){
    const int bid = blockIdx.x, tid = threadIdx.x;
    if(bid >= 2048){
        if(bid == 2048){
            // Wm1b[(d>>2)*1024 + i*4 + (d&3)] = Wm1[d*256 + i]
            for(int i=tid;i<16384;i+=256){
                int d = i>>8, ii = i&255;
                d_Wm1b[(d>>2)*1024 + ii*4 + (d&3)] = Wm1[i];
            }
        } else {
            // Wm2b[(i>>2)*256 + d*4 + (i&3)] = Wm2[i*64 + d]
            for(int i=tid;i<16384;i+=256){
                int ii = i>>6, d = i&63;
                d_Wm2b[(ii>>2)*256 + d*4 + (ii&3)] = Wm2[i];
            }
        }
        return;
    }
    __shared__ float sW[CC*CC];
    for(int i=tid;i<CC*CC;i+=256) sW[i]=W[i];
    __syncthreads();
    int row  = bid*8 + (tid>>5);
    int lane = tid&31;
    float xv  = x[row*CC + lane];
    float acc = bl[lane];
    #pragma unroll
    for(int ci=0;ci<CC;ci++)
        acc = fmaf(__shfl_sync(0xffffffffu, xv, ci), sW[ci*CC+lane], acc);
    d_xl[row*CC+lane] = acc;
    if(bid < 2){
        int i = bid*256 + tid;
        out[BB*QQ*DD + i] = qp[i];
    }
}

// ---------------- fused kernel ---------------------------------------------
// smem layout (floats). Total 24484 floats = 97,936 B -> 2 blocks/SM.
#define OFF_G   0                 // g 205*36=7380 (later reused as sh1 2048)
#define OFF_X   7380              // 16384: select scratch | gather bufs | sM
#define OFF_IND 23764             // 208 ints
#define OFF_Y   23972             // 512
#define SMEM_FLOATS 24484
#define SMEM_BYTES (SMEM_FLOATS*4)

// select-scratch offsets inside X region:
#define XS_ED    0                // 2048
#define XS_FEAT  2048             // 205*32 = 6560
#define XS_D0    8608
#define XS_D1    8813
#define XS_EDK   9018
#define XS_KD    9223
#define XS_W1    9428             // 1024
#define XS_B1    10452
#define XS_HIST  10484            // 256 (uint)
#define XS_RA    10740
#define XS_RB    10749
#define XS_SC    10758

__global__ __launch_bounds__(NT,2) void k_fused(
        const float* __restrict__ pos, const float* __restrict__ qpos,
        const float* __restrict__ rffB,
        const float* __restrict__ W1,  const float* __restrict__ b1,
        const float* __restrict__ qmw, const float* __restrict__ qmo,
        const float* __restrict__ W2,  const float* __restrict__ filt,
        const float* __restrict__ bias,
        const float* __restrict__ bm1, const float* __restrict__ bm2,
        float* __restrict__ out)
{
    extern __shared__ float smem[];
    float* sg  = smem + OFF_G;
    float* px  = smem + OFF_X;
    int*   sind= (int*)(smem + OFF_IND);
    float* sy  = smem + OFF_Y;

    const int q = blockIdx.x, tid = threadIdx.x;
    const int warp = tid>>5, lane = tid&31;
    const float qx = qpos[q*2], qy = qpos[q*2+1];

    // ======================= SELECT PHASE =======================
    {
        float* sed  = px + XS_ED;
        float* sfeat= px + XS_FEAT;
        float* sd0  = px + XS_D0;
        float* sd1  = px + XS_D1;
        float* sedk = px + XS_EDK;
        float* skd  = px + XS_KD;
        float* sW1  = px + XS_W1;
        float* sb1  = px + XS_B1;
        unsigned int* hist = (unsigned int*)(px + XS_HIST);
        float* rbufA= px + XS_RA;
        float* rbufB= px + XS_RB;
        unsigned int* s_prefix = (unsigned int*)(px + XS_SC);
        unsigned int* s_r      = (unsigned int*)(px + XS_SC + 1);
        unsigned int* s_cnt    = (unsigned int*)(px + XS_SC + 2);
        float* s_min = px + XS_SC + 3;
        float* s_max = px + XS_SC + 4;
        float* s_sum = px + XS_SC + 5;

        for(int i=tid;i<CC*CC;i+=NT) sW1[i]=W1[i];
        if(tid<CC) sb1[tid]=b1[tid];

        for(int n=tid;n<NN;n+=NT){
            float2 p = ((const float2*)pos)[n];
            float d0 = qx - p.x; d0 += 0.5f; d0 -= floorf(d0); d0 -= 0.5f;
            float d1 = qy - p.y; d1 += 0.5f; d1 -= floorf(d1); d1 -= 0.5f;
            sed[n] = d0*d0 + d1*d1;
        }
        if(tid==0){ *s_prefix=0u; *s_r=RANK; *s_cnt=0u; }
        __syncthreads();

        // 4-pass MSD radix select on float bits (all >= 0)
        for(int pass=0; pass<4; ++pass){
            const int shift = 24 - 8*pass;
            for(int i=tid;i<256;i+=NT) hist[i]=0u;
            __syncthreads();
            const unsigned int prefix = *s_prefix;
            const unsigned int hm = (pass==0) ? 0u : (0xFFFFFFFFu << (shift+8));
            // warp-aggregated histogram (uniform trip count for ballot safety)
            for(int base=0; base<NN; base+=NT){
                int n = base + tid;
                bool inb = (n < NN);
                unsigned int k = inb ? __float_as_uint(sed[n]) : 0xFFFFFFFFu;
                bool act = inb && ((k & hm) == prefix);
                unsigned amask = __ballot_sync(0xffffffffu, act);
                if(act){
                    unsigned bkt = (k>>shift)&255u;
                    unsigned peers = __match_any_sync(amask, bkt);
                    if(lane == (int)(__ffs(peers)-1))
                        atomicAdd(&hist[bkt], __popc(peers));
                }
            }
            __syncthreads();
            // warp-parallel bucket selection (warp 0)
            if(warp == 0){
                const unsigned rr = *s_r;
                unsigned cnt[8]; unsigned s = 0;
                const int b0 = lane*8;
                #pragma unroll
                for(int t=0;t<8;t++){ cnt[t] = hist[b0+t]; s += cnt[t]; }
                unsigned excl = s;
                #pragma unroll
                for(int o=1;o<32;o<<=1){
                    unsigned v = __shfl_up_sync(0xffffffffu, excl, o);
                    if(lane >= o) excl += v;
                }
                excl -= s;   // exclusive prefix
                bool sel = (excl <= rr) && (rr < excl + s);
                if(sel){
                    unsigned rem = rr - excl;
                    int t = 0;
                    while(t < 7 && rem >= cnt[t]){ rem -= cnt[t]; t++; }
                    *s_prefix = prefix | ((unsigned)(b0+t) << shift);
                    *s_r = rem;
                }
            }
            __syncthreads();
        }
        const unsigned int T = *s_prefix;

        for(int n=tid;n<NN;n+=NT){
            unsigned int k = __float_as_uint(sed[n]);
            if(k < T){ unsigned int p = atomicAdd(s_cnt,1u); sind[p]=n; }
        }
        __syncthreads();
        for(int n=tid;n<NN;n+=NT){
            unsigned int k = __float_as_uint(sed[n]);
            if(k == T){ unsigned int p = atomicAdd(s_cnt,1u); if(p<KK) sind[p]=n; }
        }
        __syncthreads();

        for(int k2=tid;k2<KK;k2+=NT){
            int n = sind[k2];
            float2 p = ((const float2*)pos)[n];
            float d0 = qx - p.x; d0 += 0.5f; d0 -= floorf(d0); d0 -= 0.5f;
            float d1 = qy - p.y; d1 += 0.5f; d1 -= floorf(d1); d1 -= 0.5f;
            sd0[k2]=d0; sd1[k2]=d1; sedk[k2]=sed[n];
        }
        __syncthreads();

        float mn = 1e30f, mx = -1e30f;
        for(int k2=tid;k2<KK;k2+=NT){ mn=fminf(mn,sedk[k2]); mx=fmaxf(mx,sedk[k2]); }
        #pragma unroll
        for(int o=16;o>0;o>>=1){
            mn = fminf(mn, __shfl_down_sync(0xffffffffu,mn,o));
            mx = fmaxf(mx, __shfl_down_sync(0xffffffffu,mx,o));
        }
        if(lane==0){ rbufA[warp]=mn; rbufB[warp]=mx; }
        __syncthreads();
        if(tid==0){
            float a=rbufA[0], b=rbufB[0];
            for(int w=1;w<9;w++){ a=fminf(a,rbufA[w]); b=fmaxf(b,rbufB[w]); }
            *s_min=a; *s_max=b;
        }
        __syncthreads();

        const float inv = 1.0f/(*s_max - *s_min + 1e-8f);
        const float smin = *s_min;
        float lsum = 0.0f;
        for(int k2=tid;k2<KK;k2+=NT){
            float w = expf(-(sedk[k2]-smin)*inv);
            skd[k2]=w; lsum+=w;
        }
        #pragma unroll
        for(int o=16;o>0;o>>=1) lsum += __shfl_down_sync(0xffffffffu,lsum,o);
        if(lane==0) rbufA[warp]=lsum;
        __syncthreads();
        if(tid==0){
            float s=0.f; for(int w=0;w<9;w++) s+=rbufA[w];
            *s_sum=s;
        }
        __syncthreads();
        const float invsum = 1.0f/(*s_sum);

        for(int i=tid;i<KK*16;i+=NT){
            int k2=i>>4, j=i&15;
            float pr = 6.28318530717958647692f*(sd0[k2]*rffB[j] + sd1[k2]*rffB[16+j]);
            float s,c; sincosf(pr,&s,&c);
            sfeat[k2*32+j]=s; sfeat[k2*32+16+j]=c;
        }
        __syncthreads();

        // g = gelu((feat@W1+b1)*qmw+qmo)*kd ; ch 32 = kd; pad 33..35
        for(int i=tid;i<KK*CC;i+=NT){
            int k2=i>>5, ii=i&31;
            float acc = sb1[ii];
            const float* fr = &sfeat[k2*32];
            #pragma unroll
            for(int f=0;f<CC;f++) acc = fmaf(fr[f], sW1[f*CC+ii], acc);
            float h = acc*qmw[q*CC+ii] + qmo[q*CC+ii];
            sg[k2*JP + ii] = gelu_f(h) * (skd[k2]*invsum);
        }
        for(int k2=tid;k2<KK;k2+=NT){
            sg[k2*JP+32] = skd[k2]*invsum;
            sg[k2*JP+33] = 0.f; sg[k2*JP+34] = 0.f; sg[k2*JP+35] = 0.f;
        }
        __syncthreads();
    }
    // ======================= M-GEMM PHASE (packed f32x2) =======================
    const int jg = tid>>5;     // 0..8
    const int cg = tid&31;     // 0..31

    u64t acc2[4][4];
    #pragma unroll
    for(int jj=0;jj<4;jj++)
        #pragma unroll
        for(int p=0;p<4;p++) acc2[jj][p]=0ull;

    const float4* sg4 = (const float4*)sg;
    float* xb0 = px;
    float* xb1 = px + 8192;

    {
        for(int i=tid;i<32*64;i+=NT){
            int kk=i>>6, ch=i&63, b=ch>>3, c4=ch&7;
            int n = sind[kk];
            cp_async16(&xb0[kk*256 + ch*4], (const float4*)&d_xl[((b<<11)+n)*CC] + c4);
        }
        CP_COMMIT();
    }

    const int NCH = (KK + 31)/32;  // 7
    for(int ci=0; ci<NCH; ++ci){
        const int k0 = ci*32;
        const int nk = (KK-k0 < 32) ? (KK-k0) : 32;
        if(ci+1 < NCH){
            const int k0n = k0+32;
            const int nkn = (KK-k0n < 32) ? (KK-k0n) : 32;
            float* dst = (ci&1) ? xb0 : xb1;
            for(int i=tid;i<nkn*64;i+=NT){
                int kk=i>>6, ch=i&63, b=ch>>3, c4=ch&7;
                int n = sind[k0n+kk];
                cp_async16(&dst[kk*256 + ch*4], (const float4*)&d_xl[((b<<11)+n)*CC] + c4);
            }
            CP_COMMIT();
            CP_WAIT(1);
        } else {
            CP_WAIT(0);
        }
        __syncthreads();
        const ulonglong2* sxu = (const ulonglong2*)((ci&1) ? xb1 : xb0);
        #pragma unroll 2
        for(int kk=0; kk<nk; ++kk){
            float4 g4v = sg4[(k0+kk)*(JP/4) + jg];
            u64t gg0 = pack_dup(g4v.x);
            u64t gg1 = pack_dup(g4v.y);
            u64t gg2 = pack_dup(g4v.z);
            u64t gg3 = pack_dup(g4v.w);
            ulonglong2 xa = sxu[kk*64 + cg];
            ulonglong2 xc = sxu[kk*64 + 32 + cg];
            ffma2(acc2[0][0], gg0, xa.x); ffma2(acc2[0][1], gg0, xa.y);
            ffma2(acc2[0][2], gg0, xc.x); ffma2(acc2[0][3], gg0, xc.y);
            ffma2(acc2[1][0], gg1, xa.x); ffma2(acc2[1][1], gg1, xa.y);
            ffma2(acc2[1][2], gg1, xc.x); ffma2(acc2[1][3], gg1, xc.y);
            ffma2(acc2[2][0], gg2, xa.x); ffma2(acc2[2][1], gg2, xa.y);
            ffma2(acc2[2][2], gg2, xc.x); ffma2(acc2[2][3], gg2, xc.y);
            ffma2(acc2[3][0], gg3, xa.x); ffma2(acc2[3][1], gg3, xa.y);
            ffma2(acc2[3][2], gg3, xc.x); ffma2(acc2[3][3], gg3, xc.y);
        }
        __syncthreads();
    }

    // stage M (33 x 256) into smem (aliases gather buffers; all reads done)
    float* sM = px;
    #pragma unroll
    for(int jj=0;jj<4;jj++){
        int j = jg*4 + jj;
        if(j < 33){
            ulonglong2 v0; v0.x = acc2[jj][0]; v0.y = acc2[jj][1];
            ulonglong2 v1; v1.x = acc2[jj][2]; v1.y = acc2[jj][3];
            *(ulonglong2*)&sM[j*256 + 4*cg]       = v0;
            *(ulonglong2*)&sM[j*256 + 128 + 4*cg] = v1;
        }
    }
    __syncthreads();

    // ======================= W2 EPILOGUE (packed f32x2) ========
    if(tid < 256){
        const int b_ = tid>>6, d_ = tid&63;
        u64t A0=0ull, A1=0ull, A2=0ull, A3=0ull;
        const ulonglong2* sMu = (const ulonglong2*)sM;
        #pragma unroll 4
        for(int j=0;j<32;j++){
            const float* wrow = W2 + (j<<11) + d_;
            #pragma unroll
            for(int c4=0;c4<8;c4++){
                ulonglong2 p0 = sMu[(j<<6) + (b_<<3) + c4];
                ulonglong2 p1 = sMu[(j<<6) + 32 + (b_<<3) + c4];
                float w0 = wrow[(4*c4+0)*64];
                float w1 = wrow[(4*c4+1)*64];
                float w2 = wrow[(4*c4+2)*64];
                float w3 = wrow[(4*c4+3)*64];
                u64t W01 = pack2(w0,w1);
                u64t W23 = pack2(w2,w3);
                ffma2(A0, p0.x, W01); ffma2(A1, p0.y, W23);
                ffma2(A2, p1.x, W01); ffma2(A3, p1.y, W23);
            }
        }
        {   // j = 32: filt row
            const float* wrow = filt + d_;
            #pragma unroll
            for(int c4=0;c4<8;c4++){
                ulonglong2 p0 = sMu[(32<<6) + (b_<<3) + c4];
                ulonglong2 p1 = sMu[(32<<6) + 32 + (b_<<3) + c4];
                float w0 = wrow[(4*c4+0)*64];
                float w1 = wrow[(4*c4+1)*64];
                float w2 = wrow[(4*c4+2)*64];
                float w3 = wrow[(4*c4+3)*64];
                u64t W01 = pack2(w0,w1);
                u64t W23 = pack2(w2,w3);
                ffma2(A0, p0.x, W01); ffma2(A1, p0.y, W23);
                ffma2(A2, p1.x, W01); ffma2(A3, p1.y, W23);
            }
        }
        float2 f0 = unpack2(A0), f1 = unpack2(A1);
        float2 f2 = unpack2(A2), f3 = unpack2(A3);
        float a0 = (f0.x+f0.y)+(f1.x+f1.y);
        float a1 = (f2.x+f2.y)+(f3.x+f3.y);
        sy[b_*64+d_]     = gelu_f(a0 + bias[d_]);
        sy[(b_+4)*64+d_] = gelu_f(a1 + bias[d_]);
    }
    __syncthreads();

    // ======================= MLP (packed weights, de-duplicated) ===========
    // Layer 1: thread i (<256) computes h1[b][i] for ALL 8 batches.
    float* sh1 = sg;   // 2048 floats, overlays dead g
    if(tid < 256){
        const int i = tid;
        const ulonglong2* wu = (const ulonglong2*)d_Wm1b;   // [d4][i] pairs
        const ulonglong2* yu = (const ulonglong2*)sy;       // y[b][d4]
        u64t A[8];
        #pragma unroll
        for(int b=0;b<8;b++) A[b]=0ull;
        #pragma unroll 4
        for(int d4=0; d4<16; ++d4){
            ulonglong2 w = wu[d4*256 + i];     // (w_d0,w_d1),(w_d2,w_d3) coalesced
            #pragma unroll
            for(int b=0;b<8;b++){
                ulonglong2 yv = yu[b*16 + d4]; // broadcast LDS.128
                ffma2(A[b], yv.x, w.x);
                ffma2(A[b], yv.y, w.y);
            }
        }
        const float bi = bm1[i];
        #pragma unroll
        for(int b=0;b<8;b++){
            float2 f = unpack2(A[b]);
            sh1[b*256 + i] = gelu_f(f.x + f.y + bi);
        }
    }
    __syncthreads();

    // Layer 2: thread (<256): d = tid&63, batch pair (2*(tid>>6), 2*(tid>>6)+1)
    if(tid < 256){
        const int d = tid&63;
        const int b0 = (tid>>6)*2, b1 = b0+1;
        const ulonglong2* wu = (const ulonglong2*)d_Wm2b;   // [i4][d] pairs
        const ulonglong2* hu = (const ulonglong2*)sh1;      // h1[b][i4]
        u64t A0=0ull, A1=0ull;
        #pragma unroll 8
        for(int i4=0; i4<64; ++i4){
            ulonglong2 w  = wu[i4*64 + d];     // coalesced
            ulonglong2 h0 = hu[b0*64 + i4];    // broadcast
            ulonglong2 h1v= hu[b1*64 + i4];
            ffma2(A0, h0.x, w.x);  ffma2(A0, h0.y, w.y);
            ffma2(A1, h1v.x, w.x); ffma2(A1, h1v.y, w.y);
        }
        float2 f0 = unpack2(A0), f1 = unpack2(A1);
        const float bd = bm2[d];
        out[(b0*QQ + q)*DD + d] = f0.x + f0.y + bd + sy[b0*64 + d];
        out[(b1*QQ + q)*DD + d] = f1.x + f1.y + bd + sy[b1*64 + d];
    }
}

// ---------------- launch --------------------------------------------------
extern "C" void kernel_launch(void* const* d_in, const int* in_sizes, int n_in,
                              void* d_out, int out_size){
    (void)in_sizes; (void)n_in; (void)out_size;
    const float* x     = (const float*)d_in[0];
    const float* pos   = (const float*)d_in[1];
    const float* qpos  = (const float*)d_in[2];
    const float* qmw   = (const float*)d_in[3];
    const float* qmo   = (const float*)d_in[4];
    const float* W_lin = (const float*)d_in[5];
    const float* b_lin = (const float*)d_in[6];
    const float* rffB  = (const float*)d_in[7];
    const float* W1    = (const float*)d_in[8];
    const float* b1    = (const float*)d_in[9];
    const float* W2    = (const float*)d_in[10];
    const float* filt  = (const float*)d_in[11];
    const float* bias  = (const float*)d_in[12];
    const float* Wm1   = (const float*)d_in[13];
    const float* bm1   = (const float*)d_in[14];
    const float* Wm2   = (const float*)d_in[15];
    const float* bm2   = (const float*)d_in[16];
    float* out = (float*)d_out;

    cudaFuncSetAttribute(k_fused, cudaFuncAttributeMaxDynamicSharedMemorySize, SMEM_BYTES);

    k_xl   <<<2048+2, 256>>>(x, W_lin, b_lin, qpos, out, Wm1, Wm2);
    k_fused<<<QQ, NT, SMEM_BYTES>>>(pos, qpos, rffB, W1, b1, qmw, qmo,
                                    W2, filt, bias, bm1, bm2, out);
}

// round 9
// speedup vs baseline: 2.6494x; 1.0644x over previous
#include <cuda_runtime.h>
#include <math.h>

#define BB 8
#define NN 2048
#define CC 32
#define DD 64
#define QQ 256
#define KK 205
#define JP 36           // padded j dimension (33 -> 36 for float4)
#define RANK (KK-1)
#define NT 288

typedef unsigned long long u64t;

// ---------------- scratch ----------------
__device__ float d_xl[BB*NN*CC];        // 2 MB
__device__ float d_Wm1b[16384];         // Wm1 packed: [d/4][i][4]  (d-quad minor)
__device__ float d_Wm2b[16384];         // Wm2 packed: [i/4][d][4]  (i-quad minor)

__device__ __forceinline__ float gelu_f(float x){
    return 0.5f*x*(1.0f+erff(x*0.70710678118654752440f));
}

__device__ __forceinline__ void cp_async16(float* smem_dst, const float4* gsrc){
    unsigned sm = (unsigned)__cvta_generic_to_shared(smem_dst);
    asm volatile("cp.async.cg.shared.global [%0], [%1], 16;\n" :: "r"(sm), "l"(gsrc));
}
#define CP_COMMIT() asm volatile("cp.async.commit_group;\n")
#define CP_WAIT(n)  asm volatile("cp.async.wait_group %0;\n" :: "n"(n))

// ---- packed fp32x2 helpers (Blackwell FFMA2) ----
__device__ __forceinline__ u64t pack_dup(float x){
    u64t r; unsigned u = __float_as_uint(x);
    asm("mov.b64 %0, {%1,%1};" : "=l"(r) : "r"(u));
    return r;
}
__device__ __forceinline__ u64t pack2(float lo, float hi){
    u64t r; unsigned a = __float_as_uint(lo), b = __float_as_uint(hi);
    asm("mov.b64 %0, {%1,%2};" : "=l"(r) : "r"(a), "r"(b));
    return r;
}
__device__ __forceinline__ void ffma2(u64t& d, u64t a, u64t b){
    asm("fma.rn.f32x2 %0, %1, %2, %0;" : "+l"(d) : "l"(a), "l"(b));
}
__device__ __forceinline__ float2 unpack2(u64t v){
    unsigned lo, hi;
    asm("mov.b64 {%0,%1}, %2;" : "=r"(lo), "=r"(hi) : "l"(v));
    return make_float2(__uint_as_float(lo), __uint_as_float(hi));
}

// ---------------- kernel A: xl, qp copy, Wm packing -----------------------
__global__ __launch_bounds__(256) void k_xl(const float* __restrict__ x,
                                            const float* __restrict__ W,
                                            const float* __restrict__ bl,
                                            const float* __restrict__ qp,
                                            float* __restrict__ out,
                                            const float* __restrict__ Wm1,
                                            const float* __restrict__ Wm2){
    const int bid = blockIdx.x, tid = threadIdx.x;
    if(bid >= 2048){
        if(bid == 2048){
            for(int i=tid;i<16384;i+=256){
                int d = i>>8, ii = i&255;
                d_Wm1b[(d>>2)*1024 + ii*4 + (d&3)] = Wm1[i];
            }
        } else {
            for(int i=tid;i<16384;i+=256){
                int ii = i>>6, d = i&63;
                d_Wm2b[(ii>>2)*256 + d*4 + (ii&3)] = Wm2[i];
            }
        }
        return;
    }
    __shared__ float sW[CC*CC];
    for(int i=tid;i<CC*CC;i+=256) sW[i]=W[i];
    __syncthreads();
    int row  = bid*8 + (tid>>5);
    int lane = tid&31;
    float xv  = x[row*CC + lane];
    float acc = bl[lane];
    #pragma unroll
    for(int ci=0;ci<CC;ci++)
        acc = fmaf(__shfl_sync(0xffffffffu, xv, ci), sW[ci*CC+lane], acc);
    d_xl[row*CC+lane] = acc;
    if(bid < 2){
        int i = bid*256 + tid;
        out[BB*QQ*DD + i] = qp[i];
    }
}

// ---------------- fused kernel ---------------------------------------------
// smem layout (floats). Total 24484 floats = 97,936 B -> 2 blocks/SM.
#define OFF_G   0                 // g 205*36=7380 (later reused as sh1 2048)
#define OFF_X   7380              // 16384: select scratch | gather bufs | sM
#define OFF_IND 23764             // 208 ints
#define OFF_Y   23972             // 512
#define SMEM_FLOATS 24484
#define SMEM_BYTES (SMEM_FLOATS*4)

// select-scratch offsets inside X region:
#define XS_ED    0                // 2048
#define XS_FEAT  2048             // 205*32 = 6560
#define XS_D0    8608
#define XS_D1    8813
#define XS_EDK   9018
#define XS_KD    9223
#define XS_W1    9428             // 1024
#define XS_B1    10452
#define XS_HIST  10484            // 256 (uint)
#define XS_RA    10740
#define XS_RB    10749
#define XS_SC    10758

__global__ __launch_bounds__(NT,2) void k_fused(
        const float* __restrict__ pos, const float* __restrict__ qpos,
        const float* __restrict__ rffB,
        const float* __restrict__ W1,  const float* __restrict__ b1,
        const float* __restrict__ qmw, const float* __restrict__ qmo,
        const float* __restrict__ W2,  const float* __restrict__ filt,
        const float* __restrict__ bias,
        const float* __restrict__ bm1, const float* __restrict__ bm2,
        float* __restrict__ out)
{
    extern __shared__ float smem[];
    float* sg  = smem + OFF_G;
    float* px  = smem + OFF_X;
    int*   sind= (int*)(smem + OFF_IND);
    float* sy  = smem + OFF_Y;

    const int q = blockIdx.x, tid = threadIdx.x;
    const int warp = tid>>5, lane = tid&31;
    const float qx = qpos[q*2], qy = qpos[q*2+1];

    // ======================= SELECT PHASE =======================
    {
        float* sed  = px + XS_ED;
        float* sfeat= px + XS_FEAT;
        float* sd0  = px + XS_D0;
        float* sd1  = px + XS_D1;
        float* sedk = px + XS_EDK;
        float* skd  = px + XS_KD;
        float* sW1  = px + XS_W1;
        float* sb1  = px + XS_B1;
        unsigned int* hist = (unsigned int*)(px + XS_HIST);
        float* rbufA= px + XS_RA;
        float* rbufB= px + XS_RB;
        unsigned int* s_prefix = (unsigned int*)(px + XS_SC);
        unsigned int* s_r      = (unsigned int*)(px + XS_SC + 1);
        unsigned int* s_cnt    = (unsigned int*)(px + XS_SC + 2);
        float* s_min = px + XS_SC + 3;
        float* s_max = px + XS_SC + 4;
        float* s_sum = px + XS_SC + 5;

        for(int i=tid;i<CC*CC;i+=NT) sW1[i]=W1[i];
        if(tid<CC) sb1[tid]=b1[tid];

        for(int n=tid;n<NN;n+=NT){
            float2 p = ((const float2*)pos)[n];
            float d0 = qx - p.x; d0 += 0.5f; d0 -= floorf(d0); d0 -= 0.5f;
            float d1 = qy - p.y; d1 += 0.5f; d1 -= floorf(d1); d1 -= 0.5f;
            sed[n] = d0*d0 + d1*d1;
        }
        if(tid==0){ *s_prefix=0u; *s_r=RANK; *s_cnt=0u; }
        __syncthreads();

        // 4-pass MSD radix select on float bits (all >= 0)
        for(int pass=0; pass<4; ++pass){
            const int shift = 24 - 8*pass;
            for(int i=tid;i<256;i+=NT) hist[i]=0u;
            __syncthreads();
            const unsigned int prefix = *s_prefix;
            const unsigned int hm = (pass==0) ? 0u : (0xFFFFFFFFu << (shift+8));
            for(int base=0; base<NN; base+=NT){
                int n = base + tid;
                bool inb = (n < NN);
                unsigned int k = inb ? __float_as_uint(sed[n]) : 0xFFFFFFFFu;
                bool act = inb && ((k & hm) == prefix);
                unsigned amask = __ballot_sync(0xffffffffu, act);
                if(act){
                    unsigned bkt = (k>>shift)&255u;
                    unsigned peers = __match_any_sync(amask, bkt);
                    if(lane == (int)(__ffs(peers)-1))
                        atomicAdd(&hist[bkt], __popc(peers));
                }
            }
            __syncthreads();
            if(warp == 0){
                const unsigned rr = *s_r;
                unsigned cnt[8]; unsigned s = 0;
                const int b0 = lane*8;
                #pragma unroll
                for(int t=0;t<8;t++){ cnt[t] = hist[b0+t]; s += cnt[t]; }
                unsigned excl = s;
                #pragma unroll
                for(int o=1;o<32;o<<=1){
                    unsigned v = __shfl_up_sync(0xffffffffu, excl, o);
                    if(lane >= o) excl += v;
                }
                excl -= s;
                bool sel = (excl <= rr) && (rr < excl + s);
                if(sel){
                    unsigned rem = rr - excl;
                    int t = 0;
                    while(t < 7 && rem >= cnt[t]){ rem -= cnt[t]; t++; }
                    *s_prefix = prefix | ((unsigned)(b0+t) << shift);
                    *s_r = rem;
                }
            }
            __syncthreads();
        }
        const unsigned int T = *s_prefix;

        for(int n=tid;n<NN;n+=NT){
            unsigned int k = __float_as_uint(sed[n]);
            if(k < T){ unsigned int p = atomicAdd(s_cnt,1u); sind[p]=n; }
        }
        __syncthreads();
        for(int n=tid;n<NN;n+=NT){
            unsigned int k = __float_as_uint(sed[n]);
            if(k == T){ unsigned int p = atomicAdd(s_cnt,1u); if(p<KK) sind[p]=n; }
        }
        __syncthreads();

        for(int k2=tid;k2<KK;k2+=NT){
            int n = sind[k2];
            float2 p = ((const float2*)pos)[n];
            float d0 = qx - p.x; d0 += 0.5f; d0 -= floorf(d0); d0 -= 0.5f;
            float d1 = qy - p.y; d1 += 0.5f; d1 -= floorf(d1); d1 -= 0.5f;
            sd0[k2]=d0; sd1[k2]=d1; sedk[k2]=sed[n];
        }
        __syncthreads();

        float mn = 1e30f, mx = -1e30f;
        for(int k2=tid;k2<KK;k2+=NT){ mn=fminf(mn,sedk[k2]); mx=fmaxf(mx,sedk[k2]); }
        #pragma unroll
        for(int o=16;o>0;o>>=1){
            mn = fminf(mn, __shfl_down_sync(0xffffffffu,mn,o));
            mx = fmaxf(mx, __shfl_down_sync(0xffffffffu,mx,o));
        }
        if(lane==0){ rbufA[warp]=mn; rbufB[warp]=mx; }
        __syncthreads();
        if(tid==0){
            float a=rbufA[0], b=rbufB[0];
            for(int w=1;w<9;w++){ a=fminf(a,rbufA[w]); b=fmaxf(b,rbufB[w]); }
            *s_min=a; *s_max=b;
        }
        __syncthreads();

        const float inv = 1.0f/(*s_max - *s_min + 1e-8f);
        const float smin = *s_min;
        float lsum = 0.0f;
        for(int k2=tid;k2<KK;k2+=NT){
            float w = expf(-(sedk[k2]-smin)*inv);
            skd[k2]=w; lsum+=w;
        }
        #pragma unroll
        for(int o=16;o>0;o>>=1) lsum += __shfl_down_sync(0xffffffffu,lsum,o);
        if(lane==0) rbufA[warp]=lsum;
        __syncthreads();
        if(tid==0){
            float s=0.f; for(int w=0;w<9;w++) s+=rbufA[w];
            *s_sum=s;
        }
        __syncthreads();
        const float invsum = 1.0f/(*s_sum);

        for(int i=tid;i<KK*16;i+=NT){
            int k2=i>>4, j=i&15;
            float pr = 6.28318530717958647692f*(sd0[k2]*rffB[j] + sd1[k2]*rffB[16+j]);
            float s,c; sincosf(pr,&s,&c);
            sfeat[k2*32+j]=s; sfeat[k2*32+16+j]=c;
        }
        __syncthreads();

        // g = gelu((feat@W1+b1)*qmw+qmo)*kd ; paired outputs via FFMA2
        for(int i=tid;i<KK*16;i+=NT){
            int k2=i>>4, iip=(i&15)*2;
            u64t A = *(const u64t*)&sb1[iip];
            const float4* fr4 = (const float4*)&sfeat[k2*32];
            #pragma unroll
            for(int f4=0;f4<8;f4++){
                float4 fv = fr4[f4];
                ffma2(A, pack_dup(fv.x), *(const u64t*)&sW1[(4*f4+0)*CC+iip]);
                ffma2(A, pack_dup(fv.y), *(const u64t*)&sW1[(4*f4+1)*CC+iip]);
                ffma2(A, pack_dup(fv.z), *(const u64t*)&sW1[(4*f4+2)*CC+iip]);
                ffma2(A, pack_dup(fv.w), *(const u64t*)&sW1[(4*f4+3)*CC+iip]);
            }
            float2 ac = unpack2(A);
            float2 qw = *(const float2*)&qmw[q*CC+iip];
            float2 qo = *(const float2*)&qmo[q*CC+iip];
            float h0 = ac.x*qw.x + qo.x;
            float h1 = ac.y*qw.y + qo.y;
            float kd = skd[k2]*invsum;
            *(float2*)&sg[k2*JP + iip] = make_float2(gelu_f(h0)*kd, gelu_f(h1)*kd);
        }
        for(int k2=tid;k2<KK;k2+=NT){
            sg[k2*JP+32] = skd[k2]*invsum;
            sg[k2*JP+33] = 0.f; sg[k2*JP+34] = 0.f; sg[k2*JP+35] = 0.f;
        }
        __syncthreads();
    }
    // ======================= M-GEMM PHASE (packed f32x2, low-wavefront tiling)
    // warps 0-7: (8 j-rows x 128 cols) each: jg = warp>>1, half = warp&1
    // warp 8: kd row (j=32) over all 256 cols
    const int jg = warp>>1, half = warp&1;

    u64t acc2[4][4];
    #pragma unroll
    for(int jj=0;jj<4;jj++)
        #pragma unroll
        for(int p=0;p<4;p++) acc2[jj][p]=0ull;

    float* xb0 = px;
    float* xb1 = px + 8192;

    {
        for(int i=tid;i<32*64;i+=NT){
            int kk=i>>6, ch=i&63, b=ch>>3, c4=ch&7;
            int n = sind[kk];
            cp_async16(&xb0[kk*256 + ch*4], (const float4*)&d_xl[((b<<11)+n)*CC] + c4);
        }
        CP_COMMIT();
    }

    const int NCH = (KK + 31)/32;  // 7
    for(int ci=0; ci<NCH; ++ci){
        const int k0 = ci*32;
        const int nk = (KK-k0 < 32) ? (KK-k0) : 32;
        if(ci+1 < NCH){
            const int k0n = k0+32;
            const int nkn = (KK-k0n < 32) ? (KK-k0n) : 32;
            float* dst = (ci&1) ? xb0 : xb1;
            for(int i=tid;i<nkn*64;i+=NT){
                int kk=i>>6, ch=i&63, b=ch>>3, c4=ch&7;
                int n = sind[k0n+kk];
                cp_async16(&dst[kk*256 + ch*4], (const float4*)&d_xl[((b<<11)+n)*CC] + c4);
            }
            CP_COMMIT();
            CP_WAIT(1);
        } else {
            CP_WAIT(0);
        }
        __syncthreads();
        const float* xbase = (ci&1) ? xb1 : xb0;
        const float4*     sx4 = (const float4*)xbase;
        const ulonglong2* sxu = (const ulonglong2*)xbase;
        if(warp < 8){
            #pragma unroll 2
            for(int kk=0; kk<nk; ++kk){
                const ulonglong2* gu = (const ulonglong2*)&sg[(k0+kk)*JP + jg*8];
                ulonglong2 g01 = gu[0];     // (j0,j1),(j2,j3) broadcast
                ulonglong2 g23 = gu[1];     // (j4,j5),(j6,j7)
                float4 xv = sx4[kk*64 + half*32 + lane];
                u64t x0 = pack_dup(xv.x);
                u64t x1 = pack_dup(xv.y);
                u64t x2 = pack_dup(xv.z);
                u64t x3 = pack_dup(xv.w);
                ffma2(acc2[0][0], g01.x, x0); ffma2(acc2[0][1], g01.x, x1);
                ffma2(acc2[0][2], g01.x, x2); ffma2(acc2[0][3], g01.x, x3);
                ffma2(acc2[1][0], g01.y, x0); ffma2(acc2[1][1], g01.y, x1);
                ffma2(acc2[1][2], g01.y, x2); ffma2(acc2[1][3], g01.y, x3);
                ffma2(acc2[2][0], g23.x, x0); ffma2(acc2[2][1], g23.x, x1);
                ffma2(acc2[2][2], g23.x, x2); ffma2(acc2[2][3], g23.x, x3);
                ffma2(acc2[3][0], g23.y, x0); ffma2(acc2[3][1], g23.y, x1);
                ffma2(acc2[3][2], g23.y, x2); ffma2(acc2[3][3], g23.y, x3);
            }
        } else {
            #pragma unroll 2
            for(int kk=0; kk<nk; ++kk){
                u64t kdd = pack_dup(sg[(k0+kk)*JP + 32]);   // broadcast
                ulonglong2 xa = sxu[kk*64 + lane];
                ulonglong2 xc = sxu[kk*64 + 32 + lane];
                ffma2(acc2[0][0], kdd, xa.x); ffma2(acc2[0][1], kdd, xa.y);
                ffma2(acc2[0][2], kdd, xc.x); ffma2(acc2[0][3], kdd, xc.y);
            }
        }
        __syncthreads();
    }

    // stage M (33 x 256) into smem (aliases gather buffers; all reads done)
    float* sM = px;
    if(warp < 8){
        const int c0 = half*128 + 4*lane;
        #pragma unroll
        for(int jp=0;jp<4;jp++){
            int j = jg*8 + 2*jp;
            float2 a0 = unpack2(acc2[jp][0]);
            float2 a1 = unpack2(acc2[jp][1]);
            float2 a2 = unpack2(acc2[jp][2]);
            float2 a3 = unpack2(acc2[jp][3]);
            *(float4*)&sM[j*256 + c0]     = make_float4(a0.x,a1.x,a2.x,a3.x);
            *(float4*)&sM[(j+1)*256 + c0] = make_float4(a0.y,a1.y,a2.y,a3.y);
        }
    } else {
        ulonglong2 v0; v0.x = acc2[0][0]; v0.y = acc2[0][1];
        ulonglong2 v1; v1.x = acc2[0][2]; v1.y = acc2[0][3];
        *(ulonglong2*)&sM[32*256 + 4*lane]       = v0;
        *(ulonglong2*)&sM[32*256 + 128 + 4*lane] = v1;
    }
    __syncthreads();

    // ======================= W2 EPILOGUE (packed f32x2) ========
    if(tid < 256){
        const int b_ = tid>>6, d_ = tid&63;
        u64t A0=0ull, A1=0ull, A2=0ull, A3=0ull;
        const ulonglong2* sMu = (const ulonglong2*)sM;
        #pragma unroll 4
        for(int j=0;j<32;j++){
            const float* wrow = W2 + (j<<11) + d_;
            #pragma unroll
            for(int c4=0;c4<8;c4++){
                ulonglong2 p0 = sMu[(j<<6) + (b_<<3) + c4];
                ulonglong2 p1 = sMu[(j<<6) + 32 + (b_<<3) + c4];
                float w0 = wrow[(4*c4+0)*64];
                float w1 = wrow[(4*c4+1)*64];
                float w2 = wrow[(4*c4+2)*64];
                float w3 = wrow[(4*c4+3)*64];
                u64t W01 = pack2(w0,w1);
                u64t W23 = pack2(w2,w3);
                ffma2(A0, p0.x, W01); ffma2(A1, p0.y, W23);
                ffma2(A2, p1.x, W01); ffma2(A3, p1.y, W23);
            }
        }
        {   // j = 32: filt row
            const float* wrow = filt + d_;
            #pragma unroll
            for(int c4=0;c4<8;c4++){
                ulonglong2 p0 = sMu[(32<<6) + (b_<<3) + c4];
                ulonglong2 p1 = sMu[(32<<6) + 32 + (b_<<3) + c4];
                float w0 = wrow[(4*c4+0)*64];
                float w1 = wrow[(4*c4+1)*64];
                float w2 = wrow[(4*c4+2)*64];
                float w3 = wrow[(4*c4+3)*64];
                u64t W01 = pack2(w0,w1);
                u64t W23 = pack2(w2,w3);
                ffma2(A0, p0.x, W01); ffma2(A1, p0.y, W23);
                ffma2(A2, p1.x, W01); ffma2(A3, p1.y, W23);
            }
        }
        float2 f0 = unpack2(A0), f1 = unpack2(A1);
        float2 f2 = unpack2(A2), f3 = unpack2(A3);
        float a0 = (f0.x+f0.y)+(f1.x+f1.y);
        float a1 = (f2.x+f2.y)+(f3.x+f3.y);
        sy[b_*64+d_]     = gelu_f(a0 + bias[d_]);
        sy[(b_+4)*64+d_] = gelu_f(a1 + bias[d_]);
    }
    __syncthreads();

    // ======================= MLP (packed weights, de-duplicated) ===========
    float* sh1 = sg;   // 2048 floats, overlays dead g
    if(tid < 256){
        const int i = tid;
        const ulonglong2* wu = (const ulonglong2*)d_Wm1b;
        const ulonglong2* yu = (const ulonglong2*)sy;
        u64t A[8];
        #pragma unroll
        for(int b=0;b<8;b++) A[b]=0ull;
        #pragma unroll 4
        for(int d4=0; d4<16; ++d4){
            ulonglong2 w = wu[d4*256 + i];
            #pragma unroll
            for(int b=0;b<8;b++){
                ulonglong2 yv = yu[b*16 + d4];
                ffma2(A[b], yv.x, w.x);
                ffma2(A[b], yv.y, w.y);
            }
        }
        const float bi = bm1[i];
        #pragma unroll
        for(int b=0;b<8;b++){
            float2 f = unpack2(A[b]);
            sh1[b*256 + i] = gelu_f(f.x + f.y + bi);
        }
    }
    __syncthreads();

    if(tid < 256){
        const int d = tid&63;
        const int b0 = (tid>>6)*2, b1 = b0+1;
        const ulonglong2* wu = (const ulonglong2*)d_Wm2b;
        const ulonglong2* hu = (const ulonglong2*)sh1;
        u64t A0=0ull, A1=0ull;
        #pragma unroll 8
        for(int i4=0; i4<64; ++i4){
            ulonglong2 w  = wu[i4*64 + d];
            ulonglong2 h0 = hu[b0*64 + i4];
            ulonglong2 h1v= hu[b1*64 + i4];
            ffma2(A0, h0.x, w.x);  ffma2(A0, h0.y, w.y);
            ffma2(A1, h1v.x, w.x); ffma2(A1, h1v.y, w.y);
        }
        float2 f0 = unpack2(A0), f1 = unpack2(A1);
        const float bd = bm2[d];
        out[(b0*QQ + q)*DD + d] = f0.x + f0.y + bd + sy[b0*64 + d];
        out[(b1*QQ + q)*DD + d] = f1.x + f1.y + bd + sy[b1*64 + d];
    }
}

// ---------------- launch --------------------------------------------------
extern "C" void kernel_launch(void* const* d_in, const int* in_sizes, int n_in,
                              void* d_out, int out_size){
    (void)in_sizes; (void)n_in; (void)out_size;
    const float* x     = (const float*)d_in[0];
    const float* pos   = (const float*)d_in[1];
    const float* qpos  = (const float*)d_in[2];
    const float* qmw   = (const float*)d_in[3];
    const float* qmo   = (const float*)d_in[4];
    const float* W_lin = (const float*)d_in[5];
    const float* b_lin = (const float*)d_in[6];
    const float* rffB  = (const float*)d_in[7];
    const float* W1    = (const float*)d_in[8];
    const float* b1    = (const float*)d_in[9];
    const float* W2    = (const float*)d_in[10];
    const float* filt  = (const float*)d_in[11];
    const float* bias  = (const float*)d_in[12];
    const float* Wm1   = (const float*)d_in[13];
    const float* bm1   = (const float*)d_in[14];
    const float* Wm2   = (const float*)d_in[15];
    const float* bm2   = (const float*)d_in[16];
    float* out = (float*)d_out;

    cudaFuncSetAttribute(k_fused, cudaFuncAttributeMaxDynamicSharedMemorySize, SMEM_BYTES);

    k_xl   <<<2048+2, 256>>>(x, W_lin, b_lin, qpos, out, Wm1, Wm2);
    k_fused<<<QQ, NT, SMEM_BYTES>>>(pos, qpos, rffB, W1, b1, qmw, qmo,
                                    W2, filt, bias, bm1, bm2, out);
}

// round 10
// speedup vs baseline: 2.7391x; 1.0339x over previous
#include <cuda_runtime.h>
#include <math.h>

#define BB 8
#define NN 2048
#define CC 32
#define DD 64
#define QQ 256
#define KK 205
#define JP 36           // padded j dimension (33 -> 36 for float4)
#define RANK (KK-1)
#define NT 288

typedef unsigned long long u64t;

// ---------------- scratch ----------------
__device__ float d_xl[BB*NN*CC];                  // 2 MB
__device__ __align__(16) float d_Wm1b[16384];     // Wm1 packed: [d/4][i][4]
__device__ __align__(16) float d_Wm2b[16384];     // Wm2 packed: [i/4][d][4]
__device__ __align__(16) float d_W2p[33*2048];    // W2ext packed: [j][c4][d][4]

__device__ __forceinline__ float gelu_f(float x){
    return 0.5f*x*(1.0f+erff(x*0.70710678118654752440f));
}

__device__ __forceinline__ void cp_async16(float* smem_dst, const float4* gsrc){
    unsigned sm = (unsigned)__cvta_generic_to_shared(smem_dst);
    asm volatile("cp.async.cg.shared.global [%0], [%1], 16;\n" :: "r"(sm), "l"(gsrc));
}
#define CP_COMMIT() asm volatile("cp.async.commit_group;\n")
#define CP_WAIT(n)  asm volatile("cp.async.wait_group %0;\n" :: "n"(n))

// ---- packed fp32x2 helpers (Blackwell FFMA2) ----
__device__ __forceinline__ u64t pack_dup(float x){
    u64t r; unsigned u = __float_as_uint(x);
    asm("mov.b64 %0, {%1,%1};" : "=l"(r) : "r"(u));
    return r;
}
__device__ __forceinline__ void ffma2(u64t& d, u64t a, u64t b){
    asm("fma.rn.f32x2 %0, %1, %2, %0;" : "+l"(d) : "l"(a), "l"(b));
}
__device__ __forceinline__ float2 unpack2(u64t v){
    unsigned lo, hi;
    asm("mov.b64 {%0,%1}, %2;" : "=r"(lo), "=r"(hi) : "l"(v));
    return make_float2(__uint_as_float(lo), __uint_as_float(hi));
}

// ---------------- kernel A: xl, qp copy, weight packing -------------------
// blocks 0..511:   xl (32 rows each)
// block  512:      Wm1b pack,  block 513: Wm2b pack
// blocks 514..529: W2p pack (4224 elements each)
__global__ __launch_bounds__(256) void k_xl(const float* __restrict__ x,
                                            const float* __restrict__ W,
                                            const float* __restrict__ bl,
                                            const float* __restrict__ qp,
                                            float* __restrict__ out,
                                            const float* __restrict__ Wm1,
                                            const float* __restrict__ Wm2,
                                            const float* __restrict__ W2,
                                            const float* __restrict__ filt){
    const int bid = blockIdx.x, tid = threadIdx.x;
    if(bid >= 512){
        if(bid == 512){
            for(int i=tid;i<16384;i+=256){
                int d = i>>8, ii = i&255;
                d_Wm1b[(d>>2)*1024 + ii*4 + (d&3)] = Wm1[i];
            }
        } else if(bid == 513){
            for(int i=tid;i<16384;i+=256){
                int ii = i>>6, d = i&63;
                d_Wm2b[(ii>>2)*256 + d*4 + (ii&3)] = Wm2[i];
            }
        } else {
            // W2p[i], i = (((j*8)+c4)*64+d)*4+t  = W2ext[j][4*c4+t][d]
            int i0 = (bid-514)*4224;
            for(int i=i0+tid; i<i0+4224 && i<33*2048; i+=256){
                int t = i&3, d = (i>>2)&63, c4 = (i>>8)&7, j = i>>11;
                int c = 4*c4+t;
                d_W2p[i] = (j<32) ? W2[(j<<11)+(c<<6)+d] : filt[(c<<6)+d];
            }
        }
        return;
    }
    __shared__ float sW[CC*CC];
    for(int i=tid;i<CC*CC;i+=256) sW[i]=W[i];
    __syncthreads();
    const int lane = tid&31;
    const int rbase = bid*32 + (tid>>5)*4;
    #pragma unroll
    for(int r=0;r<4;r++){
        int row = rbase + r;
        float xv  = x[row*CC + lane];
        float acc = bl[lane];
        #pragma unroll
        for(int ci=0;ci<CC;ci++)
            acc = fmaf(__shfl_sync(0xffffffffu, xv, ci), sW[ci*CC+lane], acc);
        d_xl[row*CC+lane] = acc;
    }
    if(bid < 2){
        int i = bid*256 + tid;
        out[BB*QQ*DD + i] = qp[i];
    }
}

// ---------------- fused kernel ---------------------------------------------
// smem layout (floats). Total 24484 floats = 97,936 B -> 2 blocks/SM.
#define OFF_G   0                 // g 205*36=7380 (later reused as sh1 2048)
#define OFF_X   7380              // 16384: select scratch | gather bufs | sM
#define OFF_IND 23764             // 208 ints
#define OFF_Y   23972             // 512
#define SMEM_FLOATS 24484
#define SMEM_BYTES (SMEM_FLOATS*4)

// select-scratch offsets inside X region:
#define XS_ED    0                // 2048
#define XS_FEAT  2048             // 205*32 = 6560
#define XS_D0    8608
#define XS_D1    8813
#define XS_EDK   9018
#define XS_KD    9223
#define XS_W1    9428             // 1024
#define XS_B1    10452
#define XS_HIST  10484            // 256 (uint)
#define XS_RA    10740
#define XS_RB    10749
#define XS_SC    10758

__global__ __launch_bounds__(NT,2) void k_fused(
        const float* __restrict__ pos, const float* __restrict__ qpos,
        const float* __restrict__ rffB,
        const float* __restrict__ W1,  const float* __restrict__ b1,
        const float* __restrict__ qmw, const float* __restrict__ qmo,
        const float* __restrict__ bias,
        const float* __restrict__ bm1, const float* __restrict__ bm2,
        float* __restrict__ out)
{
    extern __shared__ float smem[];
    float* sg  = smem + OFF_G;
    float* px  = smem + OFF_X;
    int*   sind= (int*)(smem + OFF_IND);
    float* sy  = smem + OFF_Y;

    const int q = blockIdx.x, tid = threadIdx.x;
    const int warp = tid>>5, lane = tid&31;
    const float qx = qpos[q*2], qy = qpos[q*2+1];

    // ======================= SELECT PHASE =======================
    {
        float* sed  = px + XS_ED;
        float* sfeat= px + XS_FEAT;
        float* sd0  = px + XS_D0;
        float* sd1  = px + XS_D1;
        float* sedk = px + XS_EDK;
        float* skd  = px + XS_KD;
        float* sW1  = px + XS_W1;
        float* sb1  = px + XS_B1;
        unsigned int* hist = (unsigned int*)(px + XS_HIST);
        float* rbufA= px + XS_RA;
        float* rbufB= px + XS_RB;
        unsigned int* s_prefix = (unsigned int*)(px + XS_SC);
        unsigned int* s_r      = (unsigned int*)(px + XS_SC + 1);
        unsigned int* s_cnt    = (unsigned int*)(px + XS_SC + 2);
        float* s_min = px + XS_SC + 3;
        float* s_max = px + XS_SC + 4;
        float* s_sum = px + XS_SC + 5;

        for(int i=tid;i<CC*CC;i+=NT) sW1[i]=W1[i];
        if(tid<CC) sb1[tid]=b1[tid];

        for(int n=tid;n<NN;n+=NT){
            float2 p = ((const float2*)pos)[n];
            float d0 = qx - p.x; d0 += 0.5f; d0 -= floorf(d0); d0 -= 0.5f;
            float d1 = qy - p.y; d1 += 0.5f; d1 -= floorf(d1); d1 -= 0.5f;
            sed[n] = d0*d0 + d1*d1;
        }
        if(tid==0){ *s_prefix=0u; *s_r=RANK; *s_cnt=0u; }
        __syncthreads();

        // 4-pass MSD radix select on float bits (all >= 0)
        for(int pass=0; pass<4; ++pass){
            const int shift = 24 - 8*pass;
            for(int i=tid;i<256;i+=NT) hist[i]=0u;
            __syncthreads();
            const unsigned int prefix = *s_prefix;
            const unsigned int hm = (pass==0) ? 0u : (0xFFFFFFFFu << (shift+8));
            for(int base=0; base<NN; base+=NT){
                int n = base + tid;
                bool inb = (n < NN);
                unsigned int k = inb ? __float_as_uint(sed[n]) : 0xFFFFFFFFu;
                bool act = inb && ((k & hm) == prefix);
                unsigned amask = __ballot_sync(0xffffffffu, act);
                if(act){
                    unsigned bkt = (k>>shift)&255u;
                    unsigned peers = __match_any_sync(amask, bkt);
                    if(lane == (int)(__ffs(peers)-1))
                        atomicAdd(&hist[bkt], __popc(peers));
                }
            }
            __syncthreads();
            if(warp == 0){
                const unsigned rr = *s_r;
                unsigned cnt[8]; unsigned s = 0;
                const int b0 = lane*8;
                #pragma unroll
                for(int t=0;t<8;t++){ cnt[t] = hist[b0+t]; s += cnt[t]; }
                unsigned excl = s;
                #pragma unroll
                for(int o=1;o<32;o<<=1){
                    unsigned v = __shfl_up_sync(0xffffffffu, excl, o);
                    if(lane >= o) excl += v;
                }
                excl -= s;
                bool sel = (excl <= rr) && (rr < excl + s);
                if(sel){
                    unsigned rem = rr - excl;
                    int t = 0;
                    while(t < 7 && rem >= cnt[t]){ rem -= cnt[t]; t++; }
                    *s_prefix = prefix | ((unsigned)(b0+t) << shift);
                    *s_r = rem;
                }
            }
            __syncthreads();
        }
        const unsigned int T = *s_prefix;

        for(int n=tid;n<NN;n+=NT){
            unsigned int k = __float_as_uint(sed[n]);
            if(k < T){ unsigned int p = atomicAdd(s_cnt,1u); sind[p]=n; }
        }
        __syncthreads();
        for(int n=tid;n<NN;n+=NT){
            unsigned int k = __float_as_uint(sed[n]);
            if(k == T){ unsigned int p = atomicAdd(s_cnt,1u); if(p<KK) sind[p]=n; }
        }
        __syncthreads();

        for(int k2=tid;k2<KK;k2+=NT){
            int n = sind[k2];
            float2 p = ((const float2*)pos)[n];
            float d0 = qx - p.x; d0 += 0.5f; d0 -= floorf(d0); d0 -= 0.5f;
            float d1 = qy - p.y; d1 += 0.5f; d1 -= floorf(d1); d1 -= 0.5f;
            sd0[k2]=d0; sd1[k2]=d1; sedk[k2]=sed[n];
        }
        __syncthreads();

        float mn = 1e30f, mx = -1e30f;
        for(int k2=tid;k2<KK;k2+=NT){ mn=fminf(mn,sedk[k2]); mx=fmaxf(mx,sedk[k2]); }
        #pragma unroll
        for(int o=16;o>0;o>>=1){
            mn = fminf(mn, __shfl_down_sync(0xffffffffu,mn,o));
            mx = fmaxf(mx, __shfl_down_sync(0xffffffffu,mx,o));
        }
        if(lane==0){ rbufA[warp]=mn; rbufB[warp]=mx; }
        __syncthreads();
        if(tid==0){
            float a=rbufA[0], b=rbufB[0];
            for(int w=1;w<9;w++){ a=fminf(a,rbufA[w]); b=fmaxf(b,rbufB[w]); }
            *s_min=a; *s_max=b;
        }
        __syncthreads();

        const float inv = 1.0f/(*s_max - *s_min + 1e-8f);
        const float smin = *s_min;
        float lsum = 0.0f;
        for(int k2=tid;k2<KK;k2+=NT){
            float w = expf(-(sedk[k2]-smin)*inv);
            skd[k2]=w; lsum+=w;
        }
        #pragma unroll
        for(int o=16;o>0;o>>=1) lsum += __shfl_down_sync(0xffffffffu,lsum,o);
        if(lane==0) rbufA[warp]=lsum;
        __syncthreads();
        if(tid==0){
            float s=0.f; for(int w=0;w<9;w++) s+=rbufA[w];
            *s_sum=s;
        }
        __syncthreads();
        const float invsum = 1.0f/(*s_sum);

        for(int i=tid;i<KK*16;i+=NT){
            int k2=i>>4, j=i&15;
            float pr = 6.28318530717958647692f*(sd0[k2]*rffB[j] + sd1[k2]*rffB[16+j]);
            float s,c; sincosf(pr,&s,&c);
            sfeat[k2*32+j]=s; sfeat[k2*32+16+j]=c;
        }
        __syncthreads();

        // g = gelu((feat@W1+b1)*qmw+qmo)*kd ; paired outputs via FFMA2
        for(int i=tid;i<KK*16;i+=NT){
            int k2=i>>4, iip=(i&15)*2;
            u64t A = *(const u64t*)&sb1[iip];
            const float4* fr4 = (const float4*)&sfeat[k2*32];
            #pragma unroll
            for(int f4=0;f4<8;f4++){
                float4 fv = fr4[f4];
                ffma2(A, pack_dup(fv.x), *(const u64t*)&sW1[(4*f4+0)*CC+iip]);
                ffma2(A, pack_dup(fv.y), *(const u64t*)&sW1[(4*f4+1)*CC+iip]);
                ffma2(A, pack_dup(fv.z), *(const u64t*)&sW1[(4*f4+2)*CC+iip]);
                ffma2(A, pack_dup(fv.w), *(const u64t*)&sW1[(4*f4+3)*CC+iip]);
            }
            float2 ac = unpack2(A);
            float2 qw = *(const float2*)&qmw[q*CC+iip];
            float2 qo = *(const float2*)&qmo[q*CC+iip];
            float h0 = ac.x*qw.x + qo.x;
            float h1 = ac.y*qw.y + qo.y;
            float kd = skd[k2]*invsum;
            *(float2*)&sg[k2*JP + iip] = make_float2(gelu_f(h0)*kd, gelu_f(h1)*kd);
        }
        for(int k2=tid;k2<KK;k2+=NT){
            sg[k2*JP+32] = skd[k2]*invsum;
            sg[k2*JP+33] = 0.f; sg[k2*JP+34] = 0.f; sg[k2*JP+35] = 0.f;
        }
        __syncthreads();
    }
    // ======================= M-GEMM PHASE (packed f32x2, low-wavefront tiling)
    const int jg = warp>>1, half = warp&1;

    u64t acc2[4][4];
    #pragma unroll
    for(int jj=0;jj<4;jj++)
        #pragma unroll
        for(int p=0;p<4;p++) acc2[jj][p]=0ull;

    float* xb0 = px;
    float* xb1 = px + 8192;

    {
        for(int i=tid;i<32*64;i+=NT){
            int kk=i>>6, ch=i&63, b=ch>>3, c4=ch&7;
            int n = sind[kk];
            cp_async16(&xb0[kk*256 + ch*4], (const float4*)&d_xl[((b<<11)+n)*CC] + c4);
        }
        CP_COMMIT();
    }

    const int NCH = (KK + 31)/32;  // 7
    for(int ci=0; ci<NCH; ++ci){
        const int k0 = ci*32;
        const int nk = (KK-k0 < 32) ? (KK-k0) : 32;
        if(ci+1 < NCH){
            const int k0n = k0+32;
            const int nkn = (KK-k0n < 32) ? (KK-k0n) : 32;
            float* dst = (ci&1) ? xb0 : xb1;
            for(int i=tid;i<nkn*64;i+=NT){
                int kk=i>>6, ch=i&63, b=ch>>3, c4=ch&7;
                int n = sind[k0n+kk];
                cp_async16(&dst[kk*256 + ch*4], (const float4*)&d_xl[((b<<11)+n)*CC] + c4);
            }
            CP_COMMIT();
            CP_WAIT(1);
        } else {
            CP_WAIT(0);
        }
        __syncthreads();
        const float* xbase = (ci&1) ? xb1 : xb0;
        const float4*     sx4 = (const float4*)xbase;
        const ulonglong2* sxu = (const ulonglong2*)xbase;
        if(warp < 8){
            #pragma unroll 2
            for(int kk=0; kk<nk; ++kk){
                const ulonglong2* gu = (const ulonglong2*)&sg[(k0+kk)*JP + jg*8];
                ulonglong2 g01 = gu[0];
                ulonglong2 g23 = gu[1];
                float4 xv = sx4[kk*64 + half*32 + lane];
                u64t x0 = pack_dup(xv.x);
                u64t x1 = pack_dup(xv.y);
                u64t x2 = pack_dup(xv.z);
                u64t x3 = pack_dup(xv.w);
                ffma2(acc2[0][0], g01.x, x0); ffma2(acc2[0][1], g01.x, x1);
                ffma2(acc2[0][2], g01.x, x2); ffma2(acc2[0][3], g01.x, x3);
                ffma2(acc2[1][0], g01.y, x0); ffma2(acc2[1][1], g01.y, x1);
                ffma2(acc2[1][2], g01.y, x2); ffma2(acc2[1][3], g01.y, x3);
                ffma2(acc2[2][0], g23.x, x0); ffma2(acc2[2][1], g23.x, x1);
                ffma2(acc2[2][2], g23.x, x2); ffma2(acc2[2][3], g23.x, x3);
                ffma2(acc2[3][0], g23.y, x0); ffma2(acc2[3][1], g23.y, x1);
                ffma2(acc2[3][2], g23.y, x2); ffma2(acc2[3][3], g23.y, x3);
            }
        } else {
            #pragma unroll 2
            for(int kk=0; kk<nk; ++kk){
                u64t kdd = pack_dup(sg[(k0+kk)*JP + 32]);
                ulonglong2 xa = sxu[kk*64 + lane];
                ulonglong2 xc = sxu[kk*64 + 32 + lane];
                ffma2(acc2[0][0], kdd, xa.x); ffma2(acc2[0][1], kdd, xa.y);
                ffma2(acc2[0][2], kdd, xc.x); ffma2(acc2[0][3], kdd, xc.y);
            }
        }
        __syncthreads();
    }

    // stage M (33 x 256) into smem (aliases gather buffers; all reads done)
    float* sM = px;
    if(warp < 8){
        const int c0 = half*128 + 4*lane;
        #pragma unroll
        for(int jp=0;jp<4;jp++){
            int j = jg*8 + 2*jp;
            float2 a0 = unpack2(acc2[jp][0]);
            float2 a1 = unpack2(acc2[jp][1]);
            float2 a2 = unpack2(acc2[jp][2]);
            float2 a3 = unpack2(acc2[jp][3]);
            *(float4*)&sM[j*256 + c0]     = make_float4(a0.x,a1.x,a2.x,a3.x);
            *(float4*)&sM[(j+1)*256 + c0] = make_float4(a0.y,a1.y,a2.y,a3.y);
        }
    } else {
        ulonglong2 v0; v0.x = acc2[0][0]; v0.y = acc2[0][1];
        ulonglong2 v1; v1.x = acc2[0][2]; v1.y = acc2[0][3];
        *(ulonglong2*)&sM[32*256 + 4*lane]       = v0;
        *(ulonglong2*)&sM[32*256 + 128 + 4*lane] = v1;
    }
    __syncthreads();

    // ======================= W2 EPILOGUE (packed weights, LDG.128) ========
    if(tid < 256){
        const int b_ = tid>>6, d_ = tid&63;
        u64t A0=0ull, A1=0ull, A2=0ull, A3=0ull;
        const ulonglong2* sMu = (const ulonglong2*)sM;
        const ulonglong2* wp  = (const ulonglong2*)d_W2p;   // [(j*8+c4)*64+d]
        #pragma unroll 3
        for(int j=0;j<33;j++){
            #pragma unroll
            for(int c4=0;c4<8;c4++){
                ulonglong2 wv = wp[((j<<3)+c4)*64 + d_];
                ulonglong2 p0 = sMu[(j<<6) + (b_<<3) + c4];
                ulonglong2 p1 = sMu[(j<<6) + 32 + (b_<<3) + c4];
                ffma2(A0, p0.x, wv.x); ffma2(A1, p0.y, wv.y);
                ffma2(A2, p1.x, wv.x); ffma2(A3, p1.y, wv.y);
            }
        }
        float2 f0 = unpack2(A0), f1 = unpack2(A1);
        float2 f2 = unpack2(A2), f3 = unpack2(A3);
        float a0 = (f0.x+f0.y)+(f1.x+f1.y);
        float a1 = (f2.x+f2.y)+(f3.x+f3.y);
        sy[b_*64+d_]     = gelu_f(a0 + bias[d_]);
        sy[(b_+4)*64+d_] = gelu_f(a1 + bias[d_]);
    }
    __syncthreads();

    // ======================= MLP (packed weights, de-duplicated) ===========
    float* sh1 = sg;   // 2048 floats, overlays dead g
    if(tid < 256){
        const int i = tid;
        const ulonglong2* wu = (const ulonglong2*)d_Wm1b;
        const ulonglong2* yu = (const ulonglong2*)sy;
        u64t A[8];
        #pragma unroll
        for(int b=0;b<8;b++) A[b]=0ull;
        #pragma unroll 4
        for(int d4=0; d4<16; ++d4){
            ulonglong2 w = wu[d4*256 + i];
            #pragma unroll
            for(int b=0;b<8;b++){
                ulonglong2 yv = yu[b*16 + d4];
                ffma2(A[b], yv.x, w.x);
                ffma2(A[b], yv.y, w.y);
            }
        }
        const float bi = bm1[i];
        #pragma unroll
        for(int b=0;b<8;b++){
            float2 f = unpack2(A[b]);
            sh1[b*256 + i] = gelu_f(f.x + f.y + bi);
        }
    }
    __syncthreads();

    if(tid < 256){
        const int d = tid&63;
        const int b0 = (tid>>6)*2, b1 = b0+1;
        const ulonglong2* wu = (const ulonglong2*)d_Wm2b;
        const ulonglong2* hu = (const ulonglong2*)sh1;
        u64t A0=0ull, A1=0ull;
        #pragma unroll 8
        for(int i4=0; i4<64; ++i4){
            ulonglong2 w  = wu[i4*64 + d];
            ulonglong2 h0 = hu[b0*64 + i4];
            ulonglong2 h1v= hu[b1*64 + i4];
            ffma2(A0, h0.x, w.x);  ffma2(A0, h0.y, w.y);
            ffma2(A1, h1v.x, w.x); ffma2(A1, h1v.y, w.y);
        }
        float2 f0 = unpack2(A0), f1 = unpack2(A1);
        const float bd = bm2[d];
        out[(b0*QQ + q)*DD + d] = f0.x + f0.y + bd + sy[b0*64 + d];
        out[(b1*QQ + q)*DD + d] = f1.x + f1.y + bd + sy[b1*64 + d];
    }
}

// ---------------- launch --------------------------------------------------
extern "C" void kernel_launch(void* const* d_in, const int* in_sizes, int n_in,
                              void* d_out, int out_size){
    (void)in_sizes; (void)n_in; (void)out_size;
    const float* x     = (const float*)d_in[0];
    const float* pos   = (const float*)d_in[1];
    const float* qpos  = (const float*)d_in[2];
    const float* qmw   = (const float*)d_in[3];
    const float* qmo   = (const float*)d_in[4];
    const float* W_lin = (const float*)d_in[5];
    const float* b_lin = (const float*)d_in[6];
    const float* rffB  = (const float*)d_in[7];
    const float* W1    = (const float*)d_in[8];
    const float* b1    = (const float*)d_in[9];
    const float* W2    = (const float*)d_in[10];
    const float* filt  = (const float*)d_in[11];
    const float* bias  = (const float*)d_in[12];
    const float* Wm1   = (const float*)d_in[13];
    const float* bm1   = (const float*)d_in[14];
    const float* Wm2   = (const float*)d_in[15];
    const float* bm2   = (const float*)d_in[16];
    float* out = (float*)d_out;

    cudaFuncSetAttribute(k_fused, cudaFuncAttributeMaxDynamicSharedMemorySize, SMEM_BYTES);

    k_xl   <<<512+2+16, 256>>>(x, W_lin, b_lin, qpos, out, Wm1, Wm2, W2, filt);
    k_fused<<<QQ, NT, SMEM_BYTES>>>(pos, qpos, rffB, W1, b1, qmw, qmo,
                                    bias, bm1, bm2, out);
}

// round 11
// speedup vs baseline: 2.8049x; 1.0240x over previous
#include <cuda_runtime.h>
#include <math.h>

#define BB 8
#define NN 2048
#define CC 32
#define DD 64
#define QQ 256
#define KK 205
#define JP 36           // padded j dimension (36 for 16B row alignment)
#define RANK (KK-1)
#define NT 288

typedef unsigned long long u64t;

// ---------------- scratch ----------------
__device__ float d_xl[BB*NN*CC];                  // 2 MB
__device__ __align__(16) float d_Wm1b[16384];     // Wm1 packed: [d/4][i][4]
__device__ __align__(16) float d_Wm2b[16384];     // Wm2 packed: [i/4][d][4]
// W2ext packed for j-partitioned epilogue:
// d_W2q[((j*16+c2)*32+ln)*4 + t]:
//   t0 = W2ext[j][2c2  ][ln]      t1 = W2ext[j][2c2+1][ln+32]
//   t2 = W2ext[j][2c2+1][ln]      t3 = W2ext[j][2c2  ][ln+32]
__device__ __align__(16) float d_W2q[33*2048];

__device__ __forceinline__ float gelu_f(float x){
    return 0.5f*x*(1.0f+erff(x*0.70710678118654752440f));
}

__device__ __forceinline__ void cp_async16(float* smem_dst, const float4* gsrc){
    unsigned sm = (unsigned)__cvta_generic_to_shared(smem_dst);
    asm volatile("cp.async.cg.shared.global [%0], [%1], 16;\n" :: "r"(sm), "l"(gsrc));
}
#define CP_COMMIT() asm volatile("cp.async.commit_group;\n")
#define CP_WAIT(n)  asm volatile("cp.async.wait_group %0;\n" :: "n"(n))

// ---- packed fp32x2 helpers (Blackwell FFMA2) ----
__device__ __forceinline__ u64t pack_dup(float x){
    u64t r; unsigned u = __float_as_uint(x);
    asm("mov.b64 %0, {%1,%1};" : "=l"(r) : "r"(u));
    return r;
}
__device__ __forceinline__ u64t pack2(float lo, float hi){
    u64t r; unsigned a = __float_as_uint(lo), b = __float_as_uint(hi);
    asm("mov.b64 %0, {%1,%2};" : "=l"(r) : "r"(a), "r"(b));
    return r;
}
__device__ __forceinline__ void ffma2(u64t& d, u64t a, u64t b){
    asm("fma.rn.f32x2 %0, %1, %2, %0;" : "+l"(d) : "l"(a), "l"(b));
}
__device__ __forceinline__ float2 unpack2(u64t v){
    unsigned lo, hi;
    asm("mov.b64 {%0,%1}, %2;" : "=r"(lo), "=r"(hi) : "l"(v));
    return make_float2(__uint_as_float(lo), __uint_as_float(hi));
}
__device__ __forceinline__ u64t swap_halves(u64t v){
    unsigned lo, hi; u64t r;
    asm("mov.b64 {%0,%1}, %2;" : "=r"(lo), "=r"(hi) : "l"(v));
    asm("mov.b64 %0, {%1,%2};" : "=l"(r) : "r"(hi), "r"(lo));
    return r;
}

// ---------------- kernel A: xl, qp copy, weight packing -------------------
// blocks 0..511: xl (32 rows each); 512: Wm1b; 513: Wm2b; 514..529: W2q
__global__ __launch_bounds__(256) void k_xl(const float* __restrict__ x,
                                            const float* __restrict__ W,
                                            const float* __restrict__ bl,
                                            const float* __restrict__ qp,
                                            float* __restrict__ out,
                                            const float* __restrict__ Wm1,
                                            const float* __restrict__ Wm2,
                                            const float* __restrict__ W2,
                                            const float* __restrict__ filt){
    const int bid = blockIdx.x, tid = threadIdx.x;
    if(bid >= 512){
        if(bid == 512){
            for(int i=tid;i<16384;i+=256){
                int d = i>>8, ii = i&255;
                d_Wm1b[(d>>2)*1024 + ii*4 + (d&3)] = Wm1[i];
            }
        } else if(bid == 513){
            for(int i=tid;i<16384;i+=256){
                int ii = i>>6, d = i&63;
                d_Wm2b[(ii>>2)*256 + d*4 + (ii&3)] = Wm2[i];
            }
        } else {
            int i0 = (bid-514)*4224;
            for(int i=i0+tid; i<i0+4224; i+=256){
                int t = i&3, ln = (i>>2)&31, c2 = (i>>7)&15, j = i>>11;
                int c = 2*c2 + (((t&1)^(t>>1))&1);
                int d = ln + 32*(t&1);
                d_W2q[i] = (j<32) ? W2[(j<<11)+(c<<6)+d] : filt[(c<<6)+d];
            }
        }
        return;
    }
    __shared__ float sW[CC*CC];
    for(int i=tid;i<CC*CC;i+=256) sW[i]=W[i];
    __syncthreads();
    const int lane = tid&31;
    const int rbase = bid*32 + (tid>>5)*4;
    #pragma unroll
    for(int r=0;r<4;r++){
        int row = rbase + r;
        float xv  = x[row*CC + lane];
        float acc = bl[lane];
        #pragma unroll
        for(int ci=0;ci<CC;ci++)
            acc = fmaf(__shfl_sync(0xffffffffu, xv, ci), sW[ci*CC+lane], acc);
        d_xl[row*CC+lane] = acc;
    }
    if(bid < 2){
        int i = bid*256 + tid;
        out[BB*QQ*DD + i] = qp[i];
    }
}

// ---------------- fused kernel ---------------------------------------------
// smem layout (floats). Total 24484 floats = 97,936 B -> 2 blocks/SM.
#define OFF_G   0                 // g 205*36=7380 (later: epilogue partials, sh1)
#define OFF_X   7380              // 16384: select scratch | gather bufs | sM
#define OFF_IND 23764             // 208 ints
#define OFF_Y   23972             // 512
#define SMEM_FLOATS 24484
#define SMEM_BYTES (SMEM_FLOATS*4)

// select-scratch offsets inside X region:
#define XS_ED    0                // 2048
#define XS_FEAT  2048             // 205*32 = 6560
#define XS_D0    8608
#define XS_D1    8813
#define XS_EDK   9018
#define XS_KD    9223
#define XS_W1    9428             // 1024
#define XS_B1    10452
#define XS_HIST  10484            // 256 (uint)
#define XS_RA    10740
#define XS_RB    10749
#define XS_SC    10758

__global__ __launch_bounds__(NT,2) void k_fused(
        const float* __restrict__ pos, const float* __restrict__ qpos,
        const float* __restrict__ rffB,
        const float* __restrict__ W1,  const float* __restrict__ b1,
        const float* __restrict__ qmw, const float* __restrict__ qmo,
        const float* __restrict__ bias,
        const float* __restrict__ bm1, const float* __restrict__ bm2,
        float* __restrict__ out)
{
    extern __shared__ float smem[];
    float* sg  = smem + OFF_G;
    float* px  = smem + OFF_X;
    int*   sind= (int*)(smem + OFF_IND);
    float* sy  = smem + OFF_Y;

    const int q = blockIdx.x, tid = threadIdx.x;
    const int warp = tid>>5, lane = tid&31;
    const float qx = qpos[q*2], qy = qpos[q*2+1];

    // ======================= SELECT PHASE =======================
    {
        float* sed  = px + XS_ED;
        float* sfeat= px + XS_FEAT;
        float* sd0  = px + XS_D0;
        float* sd1  = px + XS_D1;
        float* sedk = px + XS_EDK;
        float* skd  = px + XS_KD;
        float* sW1  = px + XS_W1;
        float* sb1  = px + XS_B1;
        unsigned int* hist = (unsigned int*)(px + XS_HIST);
        float* rbufA= px + XS_RA;
        float* rbufB= px + XS_RB;
        unsigned int* s_prefix = (unsigned int*)(px + XS_SC);
        unsigned int* s_r      = (unsigned int*)(px + XS_SC + 1);
        unsigned int* s_cnt    = (unsigned int*)(px + XS_SC + 2);
        float* s_min = px + XS_SC + 3;
        float* s_max = px + XS_SC + 4;
        float* s_sum = px + XS_SC + 5;

        for(int i=tid;i<CC*CC;i+=NT) sW1[i]=W1[i];
        if(tid<CC) sb1[tid]=b1[tid];

        for(int n=tid;n<NN;n+=NT){
            float2 p = ((const float2*)pos)[n];
            float d0 = qx - p.x; d0 += 0.5f; d0 -= floorf(d0); d0 -= 0.5f;
            float d1 = qy - p.y; d1 += 0.5f; d1 -= floorf(d1); d1 -= 0.5f;
            sed[n] = d0*d0 + d1*d1;
        }
        if(tid==0){ *s_prefix=0u; *s_r=RANK; *s_cnt=0u; }
        __syncthreads();

        // 4-pass MSD radix select on float bits (all >= 0)
        for(int pass=0; pass<4; ++pass){
            const int shift = 24 - 8*pass;
            for(int i=tid;i<256;i+=NT) hist[i]=0u;
            __syncthreads();
            const unsigned int prefix = *s_prefix;
            const unsigned int hm = (pass==0) ? 0u : (0xFFFFFFFFu << (shift+8));
            for(int base=0; base<NN; base+=NT){
                int n = base + tid;
                bool inb = (n < NN);
                unsigned int k = inb ? __float_as_uint(sed[n]) : 0xFFFFFFFFu;
                bool act = inb && ((k & hm) == prefix);
                unsigned amask = __ballot_sync(0xffffffffu, act);
                if(act){
                    unsigned bkt = (k>>shift)&255u;
                    unsigned peers = __match_any_sync(amask, bkt);
                    if(lane == (int)(__ffs(peers)-1))
                        atomicAdd(&hist[bkt], __popc(peers));
                }
            }
            __syncthreads();
            if(warp == 0){
                const unsigned rr = *s_r;
                unsigned cnt[8]; unsigned s = 0;
                const int b0 = lane*8;
                #pragma unroll
                for(int t=0;t<8;t++){ cnt[t] = hist[b0+t]; s += cnt[t]; }
                unsigned excl = s;
                #pragma unroll
                for(int o=1;o<32;o<<=1){
                    unsigned v = __shfl_up_sync(0xffffffffu, excl, o);
                    if(lane >= o) excl += v;
                }
                excl -= s;
                bool sel = (excl <= rr) && (rr < excl + s);
                if(sel){
                    unsigned rem = rr - excl;
                    int t = 0;
                    while(t < 7 && rem >= cnt[t]){ rem -= cnt[t]; t++; }
                    *s_prefix = prefix | ((unsigned)(b0+t) << shift);
                    *s_r = rem;
                }
            }
            __syncthreads();
        }
        const unsigned int T = *s_prefix;

        for(int n=tid;n<NN;n+=NT){
            unsigned int k = __float_as_uint(sed[n]);
            if(k < T){ unsigned int p = atomicAdd(s_cnt,1u); sind[p]=n; }
        }
        __syncthreads();
        for(int n=tid;n<NN;n+=NT){
            unsigned int k = __float_as_uint(sed[n]);
            if(k == T){ unsigned int p = atomicAdd(s_cnt,1u); if(p<KK) sind[p]=n; }
        }
        __syncthreads();

        for(int k2=tid;k2<KK;k2+=NT){
            int n = sind[k2];
            float2 p = ((const float2*)pos)[n];
            float d0 = qx - p.x; d0 += 0.5f; d0 -= floorf(d0); d0 -= 0.5f;
            float d1 = qy - p.y; d1 += 0.5f; d1 -= floorf(d1); d1 -= 0.5f;
            sd0[k2]=d0; sd1[k2]=d1; sedk[k2]=sed[n];
        }
        __syncthreads();

        float mn = 1e30f, mx = -1e30f;
        for(int k2=tid;k2<KK;k2+=NT){ mn=fminf(mn,sedk[k2]); mx=fmaxf(mx,sedk[k2]); }
        #pragma unroll
        for(int o=16;o>0;o>>=1){
            mn = fminf(mn, __shfl_down_sync(0xffffffffu,mn,o));
            mx = fmaxf(mx, __shfl_down_sync(0xffffffffu,mx,o));
        }
        if(lane==0){ rbufA[warp]=mn; rbufB[warp]=mx; }
        __syncthreads();
        if(tid==0){
            float a=rbufA[0], b=rbufB[0];
            for(int w=1;w<9;w++){ a=fminf(a,rbufA[w]); b=fmaxf(b,rbufB[w]); }
            *s_min=a; *s_max=b;
        }
        __syncthreads();

        const float inv = 1.0f/(*s_max - *s_min + 1e-8f);
        const float smin = *s_min;
        float lsum = 0.0f;
        for(int k2=tid;k2<KK;k2+=NT){
            float w = expf(-(sedk[k2]-smin)*inv);
            skd[k2]=w; lsum+=w;
        }
        #pragma unroll
        for(int o=16;o>0;o>>=1) lsum += __shfl_down_sync(0xffffffffu,lsum,o);
        if(lane==0) rbufA[warp]=lsum;
        __syncthreads();
        if(tid==0){
            float s=0.f; for(int w=0;w<9;w++) s+=rbufA[w];
            *s_sum=s;
        }
        __syncthreads();
        const float invsum = 1.0f/(*s_sum);

        for(int i=tid;i<KK*16;i+=NT){
            int k2=i>>4, j=i&15;
            float pr = 6.28318530717958647692f*(sd0[k2]*rffB[j] + sd1[k2]*rffB[16+j]);
            float s,c; sincosf(pr,&s,&c);
            sfeat[k2*32+j]=s; sfeat[k2*32+16+j]=c;
        }
        __syncthreads();

        // g = gelu((feat@W1+b1)*qmw+qmo)*kd ; paired outputs via FFMA2
        for(int i=tid;i<KK*16;i+=NT){
            int k2=i>>4, iip=(i&15)*2;
            u64t A = *(const u64t*)&sb1[iip];
            const float4* fr4 = (const float4*)&sfeat[k2*32];
            #pragma unroll
            for(int f4=0;f4<8;f4++){
                float4 fv = fr4[f4];
                ffma2(A, pack_dup(fv.x), *(const u64t*)&sW1[(4*f4+0)*CC+iip]);
                ffma2(A, pack_dup(fv.y), *(const u64t*)&sW1[(4*f4+1)*CC+iip]);
                ffma2(A, pack_dup(fv.z), *(const u64t*)&sW1[(4*f4+2)*CC+iip]);
                ffma2(A, pack_dup(fv.w), *(const u64t*)&sW1[(4*f4+3)*CC+iip]);
            }
            float2 ac = unpack2(A);
            float2 qw = *(const float2*)&qmw[q*CC+iip];
            float2 qo = *(const float2*)&qmo[q*CC+iip];
            float h0 = ac.x*qw.x + qo.x;
            float h1 = ac.y*qw.y + qo.y;
            float kd = skd[k2]*invsum;
            *(float2*)&sg[k2*JP + iip] = make_float2(gelu_f(h0)*kd, gelu_f(h1)*kd);
        }
        for(int k2=tid;k2<KK;k2+=NT){
            sg[k2*JP+32] = skd[k2]*invsum;
        }
        __syncthreads();
    }
    // ======================= M-GEMM PHASE (packed f32x2, low-wavefront tiling)
    const int jg = warp>>1, half = warp&1;

    u64t acc2[4][4];
    #pragma unroll
    for(int jj=0;jj<4;jj++)
        #pragma unroll
        for(int p=0;p<4;p++) acc2[jj][p]=0ull;

    float* xb0 = px;
    float* xb1 = px + 8192;

    {
        for(int i=tid;i<32*64;i+=NT){
            int kk=i>>6, ch=i&63, b=ch>>3, c4=ch&7;
            int n = sind[kk];
            cp_async16(&xb0[kk*256 + ch*4], (const float4*)&d_xl[((b<<11)+n)*CC] + c4);
        }
        CP_COMMIT();
    }

    const int NCH = (KK + 31)/32;  // 7
    for(int ci=0; ci<NCH; ++ci){
        const int k0 = ci*32;
        const int nk = (KK-k0 < 32) ? (KK-k0) : 32;
        if(ci+1 < NCH){
            const int k0n = k0+32;
            const int nkn = (KK-k0n < 32) ? (KK-k0n) : 32;
            float* dst = (ci&1) ? xb0 : xb1;
            for(int i=tid;i<nkn*64;i+=NT){
                int kk=i>>6, ch=i&63, b=ch>>3, c4=ch&7;
                int n = sind[k0n+kk];
                cp_async16(&dst[kk*256 + ch*4], (const float4*)&d_xl[((b<<11)+n)*CC] + c4);
            }
            CP_COMMIT();
            CP_WAIT(1);
        } else {
            CP_WAIT(0);
        }
        __syncthreads();
        const float* xbase = (ci&1) ? xb1 : xb0;
        const float4*     sx4 = (const float4*)xbase;
        const ulonglong2* sxu = (const ulonglong2*)xbase;
        if(warp < 8){
            #pragma unroll 2
            for(int kk=0; kk<nk; ++kk){
                const ulonglong2* gu = (const ulonglong2*)&sg[(k0+kk)*JP + jg*8];
                ulonglong2 g01 = gu[0];
                ulonglong2 g23 = gu[1];
                float4 xv = sx4[kk*64 + half*32 + lane];
                u64t x0 = pack_dup(xv.x);
                u64t x1 = pack_dup(xv.y);
                u64t x2 = pack_dup(xv.z);
                u64t x3 = pack_dup(xv.w);
                ffma2(acc2[0][0], g01.x, x0); ffma2(acc2[0][1], g01.x, x1);
                ffma2(acc2[0][2], g01.x, x2); ffma2(acc2[0][3], g01.x, x3);
                ffma2(acc2[1][0], g01.y, x0); ffma2(acc2[1][1], g01.y, x1);
                ffma2(acc2[1][2], g01.y, x2); ffma2(acc2[1][3], g01.y, x3);
                ffma2(acc2[2][0], g23.x, x0); ffma2(acc2[2][1], g23.x, x1);
                ffma2(acc2[2][2], g23.x, x2); ffma2(acc2[2][3], g23.x, x3);
                ffma2(acc2[3][0], g23.y, x0); ffma2(acc2[3][1], g23.y, x1);
                ffma2(acc2[3][2], g23.y, x2); ffma2(acc2[3][3], g23.y, x3);
            }
        } else {
            #pragma unroll 2
            for(int kk=0; kk<nk; ++kk){
                u64t kdd = pack_dup(sg[(k0+kk)*JP + 32]);
                ulonglong2 xa = sxu[kk*64 + lane];
                ulonglong2 xc = sxu[kk*64 + 32 + lane];
                ffma2(acc2[0][0], kdd, xa.x); ffma2(acc2[0][1], kdd, xa.y);
                ffma2(acc2[0][2], kdd, xc.x); ffma2(acc2[0][3], kdd, xc.y);
            }
        }
        __syncthreads();
    }

    // stage M (33 x 256) into smem (aliases gather buffers; all reads done)
    float* sM = px;
    if(warp < 8){
        const int c0 = half*128 + 4*lane;
        #pragma unroll
        for(int jp=0;jp<4;jp++){
            int j = jg*8 + 2*jp;
            float2 a0 = unpack2(acc2[jp][0]);
            float2 a1 = unpack2(acc2[jp][1]);
            float2 a2 = unpack2(acc2[jp][2]);
            float2 a3 = unpack2(acc2[jp][3]);
            *(float4*)&sM[j*256 + c0]     = make_float4(a0.x,a1.x,a2.x,a3.x);
            *(float4*)&sM[(j+1)*256 + c0] = make_float4(a0.y,a1.y,a2.y,a3.y);
        }
    } else {
        ulonglong2 v0; v0.x = acc2[0][0]; v0.y = acc2[0][1];
        ulonglong2 v1; v1.x = acc2[0][2]; v1.y = acc2[0][3];
        *(ulonglong2*)&sM[32*256 + 4*lane]       = v0;
        *(ulonglong2*)&sM[32*256 + 128 + 4*lane] = v1;
    }
    __syncthreads();

    // ======================= W2 EPILOGUE (j-partitioned + reduction) ========
    // Each warp handles its j-slice over ALL 512 outputs; acc = (d, d+32) pairs.
    // Even-c terms in accA, odd-c in accB (halves swapped); partials reduced in smem.
    float* sp = sg;   // 9*512 partials, overlays dead g
    {
        const int j0 = (warp<8) ? warp*4 : 32;
        const int nj = (warp<8) ? 4 : 1;
        u64t accA[8], accB[8];
        #pragma unroll
        for(int b=0;b<8;b++){ accA[b]=0ull; accB[b]=0ull; }
        const ulonglong2* wq = (const ulonglong2*)d_W2q;
        for(int jj=0;jj<nj;jj++){
            const int j = j0+jj;
            const u64t* m2 = (const u64t*)&sM[j*256];   // m2[b*16+c2]
            #pragma unroll 4
            for(int c2=0;c2<16;c2++){
                ulonglong2 wv = wq[(j*16+c2)*32 + lane];
                #pragma unroll
                for(int b=0;b<8;b++){
                    u64t m = m2[b*16+c2];
                    ffma2(accA[b], m, wv.x);
                    ffma2(accB[b], swap_halves(m), wv.y);
                }
            }
        }
        #pragma unroll
        for(int b=0;b<8;b++){
            float2 fa = unpack2(accA[b]);
            float2 fb = unpack2(accB[b]);
            sp[warp*512 + b*64 + lane]      = fa.x + fb.x;
            sp[warp*512 + b*64 + lane + 32] = fa.y + fb.y;
        }
    }
    __syncthreads();
    for(int o=tid; o<BB*DD; o+=NT){
        float s = 0.f;
        #pragma unroll
        for(int w=0;w<9;w++) s += sp[w*512+o];
        sy[o] = gelu_f(s + bias[o&63]);
    }
    __syncthreads();

    // ======================= MLP (packed weights, de-duplicated) ===========
    float* sh1 = sg;   // 2048 floats, overlays dead partials
    if(tid < 256){
        const int i = tid;
        const ulonglong2* wu = (const ulonglong2*)d_Wm1b;
        const ulonglong2* yu = (const ulonglong2*)sy;
        u64t A[8];
        #pragma unroll
        for(int b=0;b<8;b++) A[b]=0ull;
        #pragma unroll 4
        for(int d4=0; d4<16; ++d4){
            ulonglong2 w = wu[d4*256 + i];
            #pragma unroll
            for(int b=0;b<8;b++){
                ulonglong2 yv = yu[b*16 + d4];
                ffma2(A[b], yv.x, w.x);
                ffma2(A[b], yv.y, w.y);
            }
        }
        const float bi = bm1[i];
        #pragma unroll
        for(int b=0;b<8;b++){
            float2 f = unpack2(A[b]);
            sh1[b*256 + i] = gelu_f(f.x + f.y + bi);
        }
    }
    __syncthreads();

    if(tid < 256){
        const int d = tid&63;
        const int b0 = (tid>>6)*2, b1 = b0+1;
        const ulonglong2* wu = (const ulonglong2*)d_Wm2b;
        const ulonglong2* hu = (const ulonglong2*)sh1;
        u64t A0=0ull, A1=0ull;
        #pragma unroll 8
        for(int i4=0; i4<64; ++i4){
            ulonglong2 w  = wu[i4*64 + d];
            ulonglong2 h0 = hu[b0*64 + i4];
            ulonglong2 h1v= hu[b1*64 + i4];
            ffma2(A0, h0.x, w.x);  ffma2(A0, h0.y, w.y);
            ffma2(A1, h1v.x, w.x); ffma2(A1, h1v.y, w.y);
        }
        float2 f0 = unpack2(A0), f1 = unpack2(A1);
        const float bd = bm2[d];
        out[(b0*QQ + q)*DD + d] = f0.x + f0.y + bd + sy[b0*64 + d];
        out[(b1*QQ + q)*DD + d] = f1.x + f1.y + bd + sy[b1*64 + d];
    }
}

// ---------------- launch --------------------------------------------------
extern "C" void kernel_launch(void* const* d_in, const int* in_sizes, int n_in,
                              void* d_out, int out_size){
    (void)in_sizes; (void)n_in; (void)out_size;
    const float* x     = (const float*)d_in[0];
    const float* pos   = (const float*)d_in[1];
    const float* qpos  = (const float*)d_in[2];
    const float* qmw   = (const float*)d_in[3];
    const float* qmo   = (const float*)d_in[4];
    const float* W_lin = (const float*)d_in[5];
    const float* b_lin = (const float*)d_in[6];
    const float* rffB  = (const float*)d_in[7];
    const float* W1    = (const float*)d_in[8];
    const float* b1    = (const float*)d_in[9];
    const float* W2    = (const float*)d_in[10];
    const float* filt  = (const float*)d_in[11];
    const float* bias  = (const float*)d_in[12];
    const float* Wm1   = (const float*)d_in[13];
    const float* bm1   = (const float*)d_in[14];
    const float* Wm2   = (const float*)d_in[15];
    const float* bm2   = (const float*)d_in[16];
    float* out = (float*)d_out;

    cudaFuncSetAttribute(k_fused, cudaFuncAttributeMaxDynamicSharedMemorySize, SMEM_BYTES);

    k_xl   <<<512+2+16, 256>>>(x, W_lin, b_lin, qpos, out, Wm1, Wm2, W2, filt);
    k_fused<<<QQ, NT, SMEM_BYTES>>>(pos, qpos, rffB, W1, b1, qmw, qmo,
                                    bias, bm1, bm2, out);
}

// round 12
// speedup vs baseline: 2.8795x; 1.0266x over previous
#include <cuda_runtime.h>
#include <math.h>

#define BB 8
#define NN 2048
#define CC 32
#define DD 64
#define QQ 256
#define KK 205
#define JP 36           // padded j dimension (36 for 16B row alignment)
#define RANK (KK-1)
#define NT 288

typedef unsigned long long u64t;

// ---------------- scratch ----------------
__device__ float d_xl[BB*NN*CC];                  // 2 MB
__device__ __align__(16) float d_Wm1b[16384];     // Wm1 packed: [d/4][i][4]
__device__ __align__(16) float d_Wm2b[16384];     // Wm2 packed: [i/4][d][4]
// W2ext packed for j-partitioned epilogue (cross-lane variant, NO swaps):
// d_W2q[((j*16+c2)*32+ln)*4 + t]:
//   t0 = W2ext[j][2c2  ][ln]      t1 = W2ext[j][2c2+1][ln+32]
//   t2 = W2ext[j][2c2  ][ln+32]   t3 = W2ext[j][2c2+1][ln]
__device__ __align__(16) float d_W2q[33*2048];

__device__ __forceinline__ float gelu_f(float x){
    return 0.5f*x*(1.0f+erff(x*0.70710678118654752440f));
}

__device__ __forceinline__ void cp_async16(float* smem_dst, const float4* gsrc){
    unsigned sm = (unsigned)__cvta_generic_to_shared(smem_dst);
    asm volatile("cp.async.cg.shared.global [%0], [%1], 16;\n" :: "r"(sm), "l"(gsrc));
}
#define CP_COMMIT() asm volatile("cp.async.commit_group;\n")
#define CP_WAIT(n)  asm volatile("cp.async.wait_group %0;\n" :: "n"(n))

// ---- packed fp32x2 helpers (Blackwell FFMA2) ----
__device__ __forceinline__ u64t pack_dup(float x){
    u64t r; unsigned u = __float_as_uint(x);
    asm("mov.b64 %0, {%1,%1};" : "=l"(r) : "r"(u));
    return r;
}
__device__ __forceinline__ void ffma2(u64t& d, u64t a, u64t b){
    asm("fma.rn.f32x2 %0, %1, %2, %0;" : "+l"(d) : "l"(a), "l"(b));
}
__device__ __forceinline__ float2 unpack2(u64t v){
    unsigned lo, hi;
    asm("mov.b64 {%0,%1}, %2;" : "=r"(lo), "=r"(hi) : "l"(v));
    return make_float2(__uint_as_float(lo), __uint_as_float(hi));
}

// ---------------- kernel A: xl, qp copy, weight packing -------------------
// blocks 0..511: xl (32 rows each); 512: Wm1b; 513: Wm2b; 514..529: W2q
__global__ __launch_bounds__(256) void k_xl(const float* __restrict__ x,
                                            const float* __restrict__ W,
                                            const float* __restrict__ bl,
                                            const float* __restrict__ qp,
                                            float* __restrict__ out,
                                            const float* __restrict__ Wm1,
                                            const float* __restrict__ Wm2,
                                            const float* __restrict__ W2,
                                            const float* __restrict__ filt){
    const int bid = blockIdx.x, tid = threadIdx.x;
    if(bid >= 512){
        if(bid == 512){
            for(int i=tid;i<16384;i+=256){
                int d = i>>8, ii = i&255;
                d_Wm1b[(d>>2)*1024 + ii*4 + (d&3)] = Wm1[i];
            }
        } else if(bid == 513){
            for(int i=tid;i<16384;i+=256){
                int ii = i>>6, d = i&63;
                d_Wm2b[(ii>>2)*256 + d*4 + (ii&3)] = Wm2[i];
            }
        } else {
            int i0 = (bid-514)*4224;
            for(int i=i0+tid; i<i0+4224; i+=256){
                int t = i&3, ln = (i>>2)&31, c2 = (i>>7)&15, j = i>>11;
                int c = 2*c2 + (t&1);
                int d = ln + 32*(((t+1)>>1)&1);
                d_W2q[i] = (j<32) ? W2[(j<<11)+(c<<6)+d] : filt[(c<<6)+d];
            }
        }
        return;
    }
    __shared__ float sW[CC*CC];
    for(int i=tid;i<CC*CC;i+=256) sW[i]=W[i];
    __syncthreads();
    const int lane = tid&31;
    const int rbase = bid*32 + (tid>>5)*4;
    #pragma unroll
    for(int r=0;r<4;r++){
        int row = rbase + r;
        float xv  = x[row*CC + lane];
        float acc = bl[lane];
        #pragma unroll
        for(int ci=0;ci<CC;ci++)
            acc = fmaf(__shfl_sync(0xffffffffu, xv, ci), sW[ci*CC+lane], acc);
        d_xl[row*CC+lane] = acc;
    }
    if(bid < 2){
        int i = bid*256 + tid;
        out[BB*QQ*DD + i] = qp[i];
    }
}

// ---------------- fused kernel ---------------------------------------------
// smem layout (floats). Total 24484 floats = 97,936 B -> 2 blocks/SM.
#define OFF_G   0                 // g 205*36=7380 (later: epilogue partials, sh1)
#define OFF_X   7380              // 16384: select scratch | gather bufs | sM
#define OFF_IND 23764             // 208 ints
#define OFF_Y   23972             // 512
#define SMEM_FLOATS 24484
#define SMEM_BYTES (SMEM_FLOATS*4)

// select-scratch offsets inside X region:
#define XS_ED    0                // 2048
#define XS_FEAT  2048             // 205*32 = 6560
#define XS_D0    8608
#define XS_D1    8813
#define XS_EDK   9018
#define XS_KD    9223
#define XS_W1    9428             // 1024
#define XS_B1    10452
#define XS_HIST  10484            // 256 (uint)
#define XS_RA    10740
#define XS_RB    10749
#define XS_SC    10758

__global__ __launch_bounds__(NT,2) void k_fused(
        const float* __restrict__ pos, const float* __restrict__ qpos,
        const float* __restrict__ rffB,
        const float* __restrict__ W1,  const float* __restrict__ b1,
        const float* __restrict__ qmw, const float* __restrict__ qmo,
        const float* __restrict__ bias,
        const float* __restrict__ bm1, const float* __restrict__ bm2,
        float* __restrict__ out)
{
    extern __shared__ float smem[];
    float* sg  = smem + OFF_G;
    float* px  = smem + OFF_X;
    int*   sind= (int*)(smem + OFF_IND);
    float* sy  = smem + OFF_Y;

    const int q = blockIdx.x, tid = threadIdx.x;
    const int warp = tid>>5, lane = tid&31;
    const float qx = qpos[q*2], qy = qpos[q*2+1];

    // ======================= SELECT PHASE =======================
    {
        float* sed  = px + XS_ED;
        float* sfeat= px + XS_FEAT;
        float* sd0  = px + XS_D0;
        float* sd1  = px + XS_D1;
        float* sedk = px + XS_EDK;
        float* skd  = px + XS_KD;
        float* sW1  = px + XS_W1;
        float* sb1  = px + XS_B1;
        unsigned int* hist = (unsigned int*)(px + XS_HIST);
        float* rbufA= px + XS_RA;
        float* rbufB= px + XS_RB;
        unsigned int* s_prefix = (unsigned int*)(px + XS_SC);
        unsigned int* s_r      = (unsigned int*)(px + XS_SC + 1);
        unsigned int* s_cnt    = (unsigned int*)(px + XS_SC + 2);
        float* s_min = px + XS_SC + 3;
        float* s_max = px + XS_SC + 4;
        float* s_sum = px + XS_SC + 5;

        for(int i=tid;i<CC*CC;i+=NT) sW1[i]=W1[i];
        if(tid<CC) sb1[tid]=b1[tid];

        for(int n=tid;n<NN;n+=NT){
            float2 p = ((const float2*)pos)[n];
            float d0 = qx - p.x; d0 += 0.5f; d0 -= floorf(d0); d0 -= 0.5f;
            float d1 = qy - p.y; d1 += 0.5f; d1 -= floorf(d1); d1 -= 0.5f;
            sed[n] = d0*d0 + d1*d1;
        }
        if(tid==0){ *s_prefix=0u; *s_r=RANK; *s_cnt=0u; }
        __syncthreads();

        // ---- pass 0: warp-aggregated histogram (dense, conflicting) ----
        for(int i=tid;i<256;i+=NT) hist[i]=0u;
        __syncthreads();
        for(int base=0; base<NN; base+=NT){
            int n = base + tid;
            bool inb = (n < NN);
            unsigned int k = inb ? __float_as_uint(sed[n]) : 0xFFFFFFFFu;
            unsigned amask = __ballot_sync(0xffffffffu, inb);
            if(inb){
                unsigned bkt = (k>>24)&255u;
                unsigned peers = __match_any_sync(amask, bkt);
                if(lane == (int)(__ffs(peers)-1))
                    atomicAdd(&hist[bkt], __popc(peers));
            }
        }
        __syncthreads();
        if(warp == 0){
            const unsigned rr = *s_r;
            unsigned cnt[8]; unsigned s = 0;
            const int b0 = lane*8;
            #pragma unroll
            for(int t=0;t<8;t++){ cnt[t] = hist[b0+t]; s += cnt[t]; }
            unsigned excl = s;
            #pragma unroll
            for(int o=1;o<32;o<<=1){
                unsigned v = __shfl_up_sync(0xffffffffu, excl, o);
                if(lane >= o) excl += v;
            }
            excl -= s;
            bool sel = (excl <= rr) && (rr < excl + s);
            if(sel){
                unsigned rem = rr - excl;
                int t = 0;
                while(t < 7 && rem >= cnt[t]){ rem -= cnt[t]; t++; }
                *s_prefix = (unsigned)(b0+t) << 24;
                *s_r = rem;
            }
        }
        __syncthreads();

        // ---- passes 1-3: sparse, plain predicated atomics ----
        for(int pass=1; pass<4; ++pass){
            const int shift = 24 - 8*pass;
            for(int i=tid;i<256;i+=NT) hist[i]=0u;
            __syncthreads();
            const unsigned int prefix = *s_prefix;
            const unsigned int hm = 0xFFFFFFFFu << (shift+8);
            for(int n=tid;n<NN;n+=NT){
                unsigned int k = __float_as_uint(sed[n]);
                if((k & hm) == prefix) atomicAdd(&hist[(k>>shift)&255u], 1u);
            }
            __syncthreads();
            if(warp == 0){
                const unsigned rr = *s_r;
                unsigned cnt[8]; unsigned s = 0;
                const int b0 = lane*8;
                #pragma unroll
                for(int t=0;t<8;t++){ cnt[t] = hist[b0+t]; s += cnt[t]; }
                unsigned excl = s;
                #pragma unroll
                for(int o=1;o<32;o<<=1){
                    unsigned v = __shfl_up_sync(0xffffffffu, excl, o);
                    if(lane >= o) excl += v;
                }
                excl -= s;
                bool sel = (excl <= rr) && (rr < excl + s);
                if(sel){
                    unsigned rem = rr - excl;
                    int t = 0;
                    while(t < 7 && rem >= cnt[t]){ rem -= cnt[t]; t++; }
                    *s_prefix = prefix | ((unsigned)(b0+t) << shift);
                    *s_r = rem;
                }
            }
            __syncthreads();
        }
        const unsigned int T = *s_prefix;

        for(int n=tid;n<NN;n+=NT){
            unsigned int k = __float_as_uint(sed[n]);
            if(k < T){ unsigned int p = atomicAdd(s_cnt,1u); sind[p]=n; }
        }
        __syncthreads();
        for(int n=tid;n<NN;n+=NT){
            unsigned int k = __float_as_uint(sed[n]);
            if(k == T){ unsigned int p = atomicAdd(s_cnt,1u); if(p<KK) sind[p]=n; }
        }
        __syncthreads();

        for(int k2=tid;k2<KK;k2+=NT){
            int n = sind[k2];
            float2 p = ((const float2*)pos)[n];
            float d0 = qx - p.x; d0 += 0.5f; d0 -= floorf(d0); d0 -= 0.5f;
            float d1 = qy - p.y; d1 += 0.5f; d1 -= floorf(d1); d1 -= 0.5f;
            sd0[k2]=d0; sd1[k2]=d1; sedk[k2]=sed[n];
        }
        __syncthreads();

        float mn = 1e30f, mx = -1e30f;
        for(int k2=tid;k2<KK;k2+=NT){ mn=fminf(mn,sedk[k2]); mx=fmaxf(mx,sedk[k2]); }
        #pragma unroll
        for(int o=16;o>0;o>>=1){
            mn = fminf(mn, __shfl_down_sync(0xffffffffu,mn,o));
            mx = fmaxf(mx, __shfl_down_sync(0xffffffffu,mx,o));
        }
        if(lane==0){ rbufA[warp]=mn; rbufB[warp]=mx; }
        __syncthreads();
        if(tid==0){
            float a=rbufA[0], b=rbufB[0];
            for(int w=1;w<9;w++){ a=fminf(a,rbufA[w]); b=fmaxf(b,rbufB[w]); }
            *s_min=a; *s_max=b;
        }
        __syncthreads();

        const float inv = 1.0f/(*s_max - *s_min + 1e-8f);
        const float smin = *s_min;
        float lsum = 0.0f;
        for(int k2=tid;k2<KK;k2+=NT){
            float w = expf(-(sedk[k2]-smin)*inv);
            skd[k2]=w; lsum+=w;
        }
        #pragma unroll
        for(int o=16;o>0;o>>=1) lsum += __shfl_down_sync(0xffffffffu,lsum,o);
        if(lane==0) rbufA[warp]=lsum;
        __syncthreads();
        if(tid==0){
            float s=0.f; for(int w=0;w<9;w++) s+=rbufA[w];
            *s_sum=s;
        }
        __syncthreads();
        const float invsum = 1.0f/(*s_sum);

        for(int i=tid;i<KK*16;i+=NT){
            int k2=i>>4, j=i&15;
            float pr = 6.28318530717958647692f*(sd0[k2]*rffB[j] + sd1[k2]*rffB[16+j]);
            float s,c; __sincosf(pr,&s,&c);
            sfeat[k2*32+j]=s; sfeat[k2*32+16+j]=c;
        }
        __syncthreads();

        // g = gelu((feat@W1+b1)*qmw+qmo)*kd ; paired outputs via FFMA2
        for(int i=tid;i<KK*16;i+=NT){
            int k2=i>>4, iip=(i&15)*2;
            u64t A = *(const u64t*)&sb1[iip];
            const float4* fr4 = (const float4*)&sfeat[k2*32];
            #pragma unroll
            for(int f4=0;f4<8;f4++){
                float4 fv = fr4[f4];
                ffma2(A, pack_dup(fv.x), *(const u64t*)&sW1[(4*f4+0)*CC+iip]);
                ffma2(A, pack_dup(fv.y), *(const u64t*)&sW1[(4*f4+1)*CC+iip]);
                ffma2(A, pack_dup(fv.z), *(const u64t*)&sW1[(4*f4+2)*CC+iip]);
                ffma2(A, pack_dup(fv.w), *(const u64t*)&sW1[(4*f4+3)*CC+iip]);
            }
            float2 ac = unpack2(A);
            float2 qw = *(const float2*)&qmw[q*CC+iip];
            float2 qo = *(const float2*)&qmo[q*CC+iip];
            float h0 = ac.x*qw.x + qo.x;
            float h1 = ac.y*qw.y + qo.y;
            float kd = skd[k2]*invsum;
            *(float2*)&sg[k2*JP + iip] = make_float2(gelu_f(h0)*kd, gelu_f(h1)*kd);
        }
        for(int k2=tid;k2<KK;k2+=NT){
            sg[k2*JP+32] = skd[k2]*invsum;
        }
        __syncthreads();
    }
    // ======================= M-GEMM PHASE (packed f32x2, low-wavefront tiling)
    const int jg = warp>>1, half = warp&1;

    u64t acc2[4][4];
    #pragma unroll
    for(int jj=0;jj<4;jj++)
        #pragma unroll
        for(int p=0;p<4;p++) acc2[jj][p]=0ull;

    float* xb0 = px;
    float* xb1 = px + 8192;

    {
        for(int i=tid;i<32*64;i+=NT){
            int kk=i>>6, ch=i&63, b=ch>>3, c4=ch&7;
            int n = sind[kk];
            cp_async16(&xb0[kk*256 + ch*4], (const float4*)&d_xl[((b<<11)+n)*CC] + c4);
        }
        CP_COMMIT();
    }

    const int NCH = (KK + 31)/32;  // 7
    for(int ci=0; ci<NCH; ++ci){
        const int k0 = ci*32;
        const int nk = (KK-k0 < 32) ? (KK-k0) : 32;
        if(ci+1 < NCH){
            const int k0n = k0+32;
            const int nkn = (KK-k0n < 32) ? (KK-k0n) : 32;
            float* dst = (ci&1) ? xb0 : xb1;
            for(int i=tid;i<nkn*64;i+=NT){
                int kk=i>>6, ch=i&63, b=ch>>3, c4=ch&7;
                int n = sind[k0n+kk];
                cp_async16(&dst[kk*256 + ch*4], (const float4*)&d_xl[((b<<11)+n)*CC] + c4);
            }
            CP_COMMIT();
            CP_WAIT(1);
        } else {
            CP_WAIT(0);
        }
        __syncthreads();
        const float* xbase = (ci&1) ? xb1 : xb0;
        const float4*     sx4 = (const float4*)xbase;
        const ulonglong2* sxu = (const ulonglong2*)xbase;
        if(warp < 8){
            #pragma unroll 2
            for(int kk=0; kk<nk; ++kk){
                const ulonglong2* gu = (const ulonglong2*)&sg[(k0+kk)*JP + jg*8];
                ulonglong2 g01 = gu[0];
                ulonglong2 g23 = gu[1];
                float4 xv = sx4[kk*64 + half*32 + lane];
                u64t x0 = pack_dup(xv.x);
                u64t x1 = pack_dup(xv.y);
                u64t x2 = pack_dup(xv.z);
                u64t x3 = pack_dup(xv.w);
                ffma2(acc2[0][0], g01.x, x0); ffma2(acc2[0][1], g01.x, x1);
                ffma2(acc2[0][2], g01.x, x2); ffma2(acc2[0][3], g01.x, x3);
                ffma2(acc2[1][0], g01.y, x0); ffma2(acc2[1][1], g01.y, x1);
                ffma2(acc2[1][2], g01.y, x2); ffma2(acc2[1][3], g01.y, x3);
                ffma2(acc2[2][0], g23.x, x0); ffma2(acc2[2][1], g23.x, x1);
                ffma2(acc2[2][2], g23.x, x2); ffma2(acc2[2][3], g23.x, x3);
                ffma2(acc2[3][0], g23.y, x0); ffma2(acc2[3][1], g23.y, x1);
                ffma2(acc2[3][2], g23.y, x2); ffma2(acc2[3][3], g23.y, x3);
            }
        } else {
            #pragma unroll 2
            for(int kk=0; kk<nk; ++kk){
                u64t kdd = pack_dup(sg[(k0+kk)*JP + 32]);
                ulonglong2 xa = sxu[kk*64 + lane];
                ulonglong2 xc = sxu[kk*64 + 32 + lane];
                ffma2(acc2[0][0], kdd, xa.x); ffma2(acc2[0][1], kdd, xa.y);
                ffma2(acc2[0][2], kdd, xc.x); ffma2(acc2[0][3], kdd, xc.y);
            }
        }
        __syncthreads();
    }

    // stage M (33 x 256) into smem (aliases gather buffers; all reads done)
    float* sM = px;
    if(warp < 8){
        const int c0 = half*128 + 4*lane;
        #pragma unroll
        for(int jp=0;jp<4;jp++){
            int j = jg*8 + 2*jp;
            float2 a0 = unpack2(acc2[jp][0]);
            float2 a1 = unpack2(acc2[jp][1]);
            float2 a2 = unpack2(acc2[jp][2]);
            float2 a3 = unpack2(acc2[jp][3]);
            *(float4*)&sM[j*256 + c0]     = make_float4(a0.x,a1.x,a2.x,a3.x);
            *(float4*)&sM[(j+1)*256 + c0] = make_float4(a0.y,a1.y,a2.y,a3.y);
        }
    } else {
        ulonglong2 v0; v0.x = acc2[0][0]; v0.y = acc2[0][1];
        ulonglong2 v1; v1.x = acc2[0][2]; v1.y = acc2[0][3];
        *(ulonglong2*)&sM[32*256 + 4*lane]       = v0;
        *(ulonglong2*)&sM[32*256 + 128 + 4*lane] = v1;
    }
    __syncthreads();

    // ======================= W2 EPILOGUE (j-partitioned, swap-free) ========
    // accA = (even-c terms of d, odd-c terms of d+32)
    // accB = (even-c terms of d+32, odd-c terms of d)   [cross-lane packing]
    float* sp = sg;   // 9*512 partials, overlays dead g
    {
        const int j0 = (warp<8) ? warp*4 : 32;
        const int nj = (warp<8) ? 4 : 1;
        u64t accA[8], accB[8];
        #pragma unroll
        for(int b=0;b<8;b++){ accA[b]=0ull; accB[b]=0ull; }
        const ulonglong2* wq = (const ulonglong2*)d_W2q;
        for(int jj=0;jj<nj;jj++){
            const int j = j0+jj;
            const u64t* m2 = (const u64t*)&sM[j*256];   // m2[b*16+c2]
            #pragma unroll 4
            for(int c2=0;c2<16;c2++){
                ulonglong2 wv = wq[(j*16+c2)*32 + lane];
                #pragma unroll
                for(int b=0;b<8;b++){
                    u64t m = m2[b*16+c2];
                    ffma2(accA[b], m, wv.x);
                    ffma2(accB[b], m, wv.y);
                }
            }
        }
        #pragma unroll
        for(int b=0;b<8;b++){
            float2 fa = unpack2(accA[b]);
            float2 fb = unpack2(accB[b]);
            sp[warp*512 + b*64 + lane]      = fa.x + fb.y;
            sp[warp*512 + b*64 + lane + 32] = fb.x + fa.y;
        }
    }
    __syncthreads();
    for(int o=tid; o<BB*DD; o+=NT){
        float s = 0.f;
        #pragma unroll
        for(int w=0;w<9;w++) s += sp[w*512+o];
        sy[o] = gelu_f(s + bias[o&63]);
    }
    __syncthreads();

    // ======================= MLP (packed weights, de-duplicated) ===========
    float* sh1 = sg;   // 2048 floats, overlays dead partials
    if(tid < 256){
        const int i = tid;
        const ulonglong2* wu = (const ulonglong2*)d_Wm1b;
        const ulonglong2* yu = (const ulonglong2*)sy;
        u64t A[8];
        #pragma unroll
        for(int b=0;b<8;b++) A[b]=0ull;
        #pragma unroll 4
        for(int d4=0; d4<16; ++d4){
            ulonglong2 w = wu[d4*256 + i];
            #pragma unroll
            for(int b=0;b<8;b++){
                ulonglong2 yv = yu[b*16 + d4];
                ffma2(A[b], yv.x, w.x);
                ffma2(A[b], yv.y, w.y);
            }
        }
        const float bi = bm1[i];
        #pragma unroll
        for(int b=0;b<8;b++){
            float2 f = unpack2(A[b]);
            sh1[b*256 + i] = gelu_f(f.x + f.y + bi);
        }
    }
    __syncthreads();

    if(tid < 256){
        const int d = tid&63;
        const int b0 = (tid>>6)*2, b1 = b0+1;
        const ulonglong2* wu = (const ulonglong2*)d_Wm2b;
        const ulonglong2* hu = (const ulonglong2*)sh1;
        u64t A0=0ull, A1=0ull;
        #pragma unroll 8
        for(int i4=0; i4<64; ++i4){
            ulonglong2 w  = wu[i4*64 + d];
            ulonglong2 h0 = hu[b0*64 + i4];
            ulonglong2 h1v= hu[b1*64 + i4];
            ffma2(A0, h0.x, w.x);  ffma2(A0, h0.y, w.y);
            ffma2(A1, h1v.x, w.x); ffma2(A1, h1v.y, w.y);
        }
        float2 f0 = unpack2(A0), f1 = unpack2(A1);
        const float bd = bm2[d];
        out[(b0*QQ + q)*DD + d] = f0.x + f0.y + bd + sy[b0*64 + d];
        out[(b1*QQ + q)*DD + d] = f1.x + f1.y + bd + sy[b1*64 + d];
    }
}

// ---------------- launch --------------------------------------------------
extern "C" void kernel_launch(void* const* d_in, const int* in_sizes, int n_in,
                              void* d_out, int out_size){
    (void)in_sizes; (void)n_in; (void)out_size;
    const float* x     = (const float*)d_in[0];
    const float* pos   = (const float*)d_in[1];
    const float* qpos  = (const float*)d_in[2];
    const float* qmw   = (const float*)d_in[3];
    const float* qmo   = (const float*)d_in[4];
    const float* W_lin = (const float*)d_in[5];
    const float* b_lin = (const float*)d_in[6];
    const float* rffB  = (const float*)d_in[7];
    const float* W1    = (const float*)d_in[8];
    const float* b1    = (const float*)d_in[9];
    const float* W2    = (const float*)d_in[10];
    const float* filt  = (const float*)d_in[11];
    const float* bias  = (const float*)d_in[12];
    const float* Wm1   = (const float*)d_in[13];
    const float* bm1   = (const float*)d_in[14];
    const float* Wm2   = (const float*)d_in[15];
    const float* bm2   = (const float*)d_in[16];
    float* out = (float*)d_out;

    cudaFuncSetAttribute(k_fused, cudaFuncAttributeMaxDynamicSharedMemorySize, SMEM_BYTES);

    k_xl   <<<512+2+16, 256>>>(x, W_lin, b_lin, qpos, out, Wm1, Wm2, W2, filt);
    k_fused<<<QQ, NT, SMEM_BYTES>>>(pos, qpos, rffB, W1, b1, qmw, qmo,
                                    bias, bm1, bm2, out);
}

// round 13
// speedup vs baseline: 2.9475x; 1.0236x over previous
#include <cuda_runtime.h>
#include <math.h>

#define BB 8
#define NN 2048
#define CC 32
#define DD 64
#define QQ 256
#define KK 205
#define JP 36           // padded j dimension (36 for 16B row alignment)
#define RANK (KK-1)
#define NT 288

typedef unsigned long long u64t;

// ---------------- scratch ----------------
__device__ float d_xl[BB*NN*CC];                  // 2 MB
__device__ __align__(16) float d_Wm1b[16384];     // Wm1 packed: [d/4][i][4]
__device__ __align__(16) float d_Wm2b[16384];     // Wm2 packed: [i/4][d][4]
// W2ext packed for j-partitioned epilogue (cross-lane variant, NO swaps):
// d_W2q[((j*16+c2)*32+ln)*4 + t]:
//   t0 = W2ext[j][2c2  ][ln]      t1 = W2ext[j][2c2+1][ln+32]
//   t2 = W2ext[j][2c2  ][ln+32]   t3 = W2ext[j][2c2+1][ln]
__device__ __align__(16) float d_W2q[33*2048];

__device__ __forceinline__ float gelu_f(float x){
    return 0.5f*x*(1.0f+erff(x*0.70710678118654752440f));
}

__device__ __forceinline__ void cp_async16(float* smem_dst, const float4* gsrc){
    unsigned sm = (unsigned)__cvta_generic_to_shared(smem_dst);
    asm volatile("cp.async.cg.shared.global [%0], [%1], 16;\n" :: "r"(sm), "l"(gsrc));
}
#define CP_COMMIT() asm volatile("cp.async.commit_group;\n")
#define CP_WAIT(n)  asm volatile("cp.async.wait_group %0;\n" :: "n"(n))

// ---- packed fp32x2 helpers (Blackwell FFMA2) ----
__device__ __forceinline__ u64t pack_dup(float x){
    u64t r; unsigned u = __float_as_uint(x);
    asm("mov.b64 %0, {%1,%1};" : "=l"(r) : "r"(u));
    return r;
}
__device__ __forceinline__ void ffma2(u64t& d, u64t a, u64t b){
    asm("fma.rn.f32x2 %0, %1, %2, %0;" : "+l"(d) : "l"(a), "l"(b));
}
__device__ __forceinline__ float2 unpack2(u64t v){
    unsigned lo, hi;
    asm("mov.b64 {%0,%1}, %2;" : "=r"(lo), "=r"(hi) : "l"(v));
    return make_float2(__uint_as_float(lo), __uint_as_float(hi));
}

// ---------------- kernel A: xl, qp copy, weight packing -------------------
// blocks 0..127: xl (128 rows each); 128: Wm1b; 129: Wm2b; 130..145: W2q
__global__ __launch_bounds__(256) void k_xl(const float* __restrict__ x,
                                            const float* __restrict__ W,
                                            const float* __restrict__ bl,
                                            const float* __restrict__ qp,
                                            float* __restrict__ out,
                                            const float* __restrict__ Wm1,
                                            const float* __restrict__ Wm2,
                                            const float* __restrict__ W2,
                                            const float* __restrict__ filt){
    const int bid = blockIdx.x, tid = threadIdx.x;
    if(bid >= 128){
        const int tb = bid - 128;
        if(tb == 0){
            for(int i=tid;i<16384;i+=256){
                int d = i>>8, ii = i&255;
                d_Wm1b[(d>>2)*1024 + ii*4 + (d&3)] = Wm1[i];
            }
        } else if(tb == 1){
            for(int i=tid;i<16384;i+=256){
                int ii = i>>6, d = i&63;
                d_Wm2b[(ii>>2)*256 + d*4 + (ii&3)] = Wm2[i];
            }
        } else {
            int i0 = (tb-2)*4224;
            for(int i=i0+tid; i<i0+4224; i+=256){
                int t = i&3, ln = (i>>2)&31, c2 = (i>>7)&15, j = i>>11;
                int c = 2*c2 + (t&1);
                int d = ln + 32*(((t+1)>>1)&1);
                d_W2q[i] = (j<32) ? W2[(j<<11)+(c<<6)+d] : filt[(c<<6)+d];
            }
        }
        return;
    }
    __shared__ float sW[CC*CC];
    for(int i=tid;i<CC*CC;i+=256) sW[i]=W[i];
    __syncthreads();
    const int lane = tid&31;
    const int rbase = bid*128 + (tid>>5)*16;
    #pragma unroll 4
    for(int r=0;r<16;r++){
        int row = rbase + r;
        float xv  = x[row*CC + lane];
        float acc = bl[lane];
        #pragma unroll
        for(int ci=0;ci<CC;ci++)
            acc = fmaf(__shfl_sync(0xffffffffu, xv, ci), sW[ci*CC+lane], acc);
        d_xl[row*CC+lane] = acc;
    }
    if(bid < 2){
        int i = bid*256 + tid;
        out[BB*QQ*DD + i] = qp[i];
    }
}

// ---------------- fused kernel ---------------------------------------------
// smem layout (floats). Total 24484 floats = 97,936 B -> 2 blocks/SM.
#define OFF_G   0                 // g 205*36=7380 (later: epilogue partials, sh1)
#define OFF_X   7380              // 16384: select scratch | gather bufs | sM
#define OFF_IND 23764             // 208 ints
#define OFF_Y   23972             // 512
#define SMEM_FLOATS 24484
#define SMEM_BYTES (SMEM_FLOATS*4)

// select-scratch offsets inside X region:
#define XS_ED    0                // 2048
#define XS_FEAT  2048             // 205*32 = 6560
#define XS_D0    8608
#define XS_D1    8813
#define XS_EDK   9018
#define XS_KD    9223
#define XS_W1    9428             // 1024
#define XS_B1    10452
#define XS_HIST  10484            // 256 (uint)
#define XS_RA    10740
#define XS_RB    10749
#define XS_SC    10758

__global__ __launch_bounds__(NT,2) void k_fused(
        const float* __restrict__ pos, const float* __restrict__ qpos,
        const float* __restrict__ rffB,
        const float* __restrict__ W1,  const float* __restrict__ b1,
        const float* __restrict__ qmw, const float* __restrict__ qmo,
        const float* __restrict__ bias,
        const float* __restrict__ bm1, const float* __restrict__ bm2,
        float* __restrict__ out)
{
    extern __shared__ float smem[];
    float* sg  = smem + OFF_G;
    float* px  = smem + OFF_X;
    int*   sind= (int*)(smem + OFF_IND);
    float* sy  = smem + OFF_Y;

    const int q = blockIdx.x, tid = threadIdx.x;
    const int warp = tid>>5, lane = tid&31;
    const float qx = qpos[q*2], qy = qpos[q*2+1];

    // ======================= SELECT PHASE =======================
    {
        float* sed  = px + XS_ED;
        float* sfeat= px + XS_FEAT;
        float* sd0  = px + XS_D0;
        float* sd1  = px + XS_D1;
        float* sedk = px + XS_EDK;
        float* skd  = px + XS_KD;
        float* sW1  = px + XS_W1;
        float* sb1  = px + XS_B1;
        unsigned int* hist = (unsigned int*)(px + XS_HIST);
        float* rbufA= px + XS_RA;
        float* rbufB= px + XS_RB;
        unsigned int* s_prefix = (unsigned int*)(px + XS_SC);
        unsigned int* s_r      = (unsigned int*)(px + XS_SC + 1);
        unsigned int* s_cnt    = (unsigned int*)(px + XS_SC + 2);
        float* s_min = px + XS_SC + 3;
        float* s_max = px + XS_SC + 4;
        float* s_sum = px + XS_SC + 5;

        for(int i=tid;i<CC*CC;i+=NT) sW1[i]=W1[i];
        if(tid<CC) sb1[tid]=b1[tid];
        for(int i=tid;i<256;i+=NT) hist[i]=0u;
        if(tid==0){ *s_prefix=0u; *s_r=RANK; *s_cnt=0u; }
        __syncthreads();

        // ---- edist + fused pass-0 histogram (warp-aggregated) ----
        for(int base=0; base<NN; base+=NT){
            int n = base + tid;
            bool inb = (n < NN);
            unsigned int k = 0xFFFFFFFFu;
            if(inb){
                float2 p = ((const float2*)pos)[n];
                float d0 = qx - p.x; d0 += 0.5f; d0 -= floorf(d0); d0 -= 0.5f;
                float d1 = qy - p.y; d1 += 0.5f; d1 -= floorf(d1); d1 -= 0.5f;
                float e = d0*d0 + d1*d1;
                sed[n] = e;
                k = __float_as_uint(e);
            }
            unsigned amask = __ballot_sync(0xffffffffu, inb);
            if(inb){
                unsigned bkt = (k>>24)&255u;
                unsigned peers = __match_any_sync(amask, bkt);
                if(lane == (int)(__ffs(peers)-1))
                    atomicAdd(&hist[bkt], __popc(peers));
            }
        }
        __syncthreads();
        if(warp == 0){
            const unsigned rr = *s_r;
            unsigned cnt[8]; unsigned s = 0;
            const int b0 = lane*8;
            #pragma unroll
            for(int t=0;t<8;t++){ cnt[t] = hist[b0+t]; s += cnt[t]; }
            unsigned excl = s;
            #pragma unroll
            for(int o=1;o<32;o<<=1){
                unsigned v = __shfl_up_sync(0xffffffffu, excl, o);
                if(lane >= o) excl += v;
            }
            excl -= s;
            bool sel = (excl <= rr) && (rr < excl + s);
            if(sel){
                unsigned rem = rr - excl;
                int t = 0;
                while(t < 7 && rem >= cnt[t]){ rem -= cnt[t]; t++; }
                *s_prefix = (unsigned)(b0+t) << 24;
                *s_r = rem;
            }
        }
        __syncthreads();

        // ---- passes 1-3: sparse, plain predicated atomics ----
        for(int pass=1; pass<4; ++pass){
            const int shift = 24 - 8*pass;
            for(int i=tid;i<256;i+=NT) hist[i]=0u;
            __syncthreads();
            const unsigned int prefix = *s_prefix;
            const unsigned int hm = 0xFFFFFFFFu << (shift+8);
            for(int n=tid;n<NN;n+=NT){
                unsigned int k = __float_as_uint(sed[n]);
                if((k & hm) == prefix) atomicAdd(&hist[(k>>shift)&255u], 1u);
            }
            __syncthreads();
            if(warp == 0){
                const unsigned rr = *s_r;
                unsigned cnt[8]; unsigned s = 0;
                const int b0 = lane*8;
                #pragma unroll
                for(int t=0;t<8;t++){ cnt[t] = hist[b0+t]; s += cnt[t]; }
                unsigned excl = s;
                #pragma unroll
                for(int o=1;o<32;o<<=1){
                    unsigned v = __shfl_up_sync(0xffffffffu, excl, o);
                    if(lane >= o) excl += v;
                }
                excl -= s;
                bool sel = (excl <= rr) && (rr < excl + s);
                if(sel){
                    unsigned rem = rr - excl;
                    int t = 0;
                    while(t < 7 && rem >= cnt[t]){ rem -= cnt[t]; t++; }
                    *s_prefix = prefix | ((unsigned)(b0+t) << shift);
                    *s_r = rem;
                }
            }
            __syncthreads();
        }
        const unsigned int T = *s_prefix;

        for(int n=tid;n<NN;n+=NT){
            unsigned int k = __float_as_uint(sed[n]);
            if(k < T){ unsigned int p = atomicAdd(s_cnt,1u); sind[p]=n; }
        }
        __syncthreads();
        for(int n=tid;n<NN;n+=NT){
            unsigned int k = __float_as_uint(sed[n]);
            if(k == T){ unsigned int p = atomicAdd(s_cnt,1u); if(p<KK) sind[p]=n; }
        }
        __syncthreads();

        for(int k2=tid;k2<KK;k2+=NT){
            int n = sind[k2];
            float2 p = ((const float2*)pos)[n];
            float d0 = qx - p.x; d0 += 0.5f; d0 -= floorf(d0); d0 -= 0.5f;
            float d1 = qy - p.y; d1 += 0.5f; d1 -= floorf(d1); d1 -= 0.5f;
            sd0[k2]=d0; sd1[k2]=d1; sedk[k2]=sed[n];
        }
        __syncthreads();

        float mn = 1e30f, mx = -1e30f;
        for(int k2=tid;k2<KK;k2+=NT){ mn=fminf(mn,sedk[k2]); mx=fmaxf(mx,sedk[k2]); }
        #pragma unroll
        for(int o=16;o>0;o>>=1){
            mn = fminf(mn, __shfl_down_sync(0xffffffffu,mn,o));
            mx = fmaxf(mx, __shfl_down_sync(0xffffffffu,mx,o));
        }
        if(lane==0){ rbufA[warp]=mn; rbufB[warp]=mx; }
        __syncthreads();
        if(tid==0){
            float a=rbufA[0], b=rbufB[0];
            for(int w=1;w<9;w++){ a=fminf(a,rbufA[w]); b=fmaxf(b,rbufB[w]); }
            *s_min=a; *s_max=b;
        }
        __syncthreads();

        const float inv = 1.0f/(*s_max - *s_min + 1e-8f);
        const float smin = *s_min;
        float lsum = 0.0f;
        for(int k2=tid;k2<KK;k2+=NT){
            float w = expf(-(sedk[k2]-smin)*inv);
            skd[k2]=w; lsum+=w;
        }
        #pragma unroll
        for(int o=16;o>0;o>>=1) lsum += __shfl_down_sync(0xffffffffu,lsum,o);
        if(lane==0) rbufA[warp]=lsum;
        __syncthreads();
        if(tid==0){
            float s=0.f; for(int w=0;w<9;w++) s+=rbufA[w];
            *s_sum=s;
        }
        __syncthreads();
        const float invsum = 1.0f/(*s_sum);

        for(int i=tid;i<KK*16;i+=NT){
            int k2=i>>4, j=i&15;
            float pr = 6.28318530717958647692f*(sd0[k2]*rffB[j] + sd1[k2]*rffB[16+j]);
            float s,c; __sincosf(pr,&s,&c);
            sfeat[k2*32+j]=s; sfeat[k2*32+16+j]=c;
        }
        __syncthreads();

        // g = gelu((feat@W1+b1)*qmw+qmo)*kd ; paired outputs via FFMA2
        for(int i=tid;i<KK*16;i+=NT){
            int k2=i>>4, iip=(i&15)*2;
            u64t A = *(const u64t*)&sb1[iip];
            const float4* fr4 = (const float4*)&sfeat[k2*32];
            #pragma unroll
            for(int f4=0;f4<8;f4++){
                float4 fv = fr4[f4];
                ffma2(A, pack_dup(fv.x), *(const u64t*)&sW1[(4*f4+0)*CC+iip]);
                ffma2(A, pack_dup(fv.y), *(const u64t*)&sW1[(4*f4+1)*CC+iip]);
                ffma2(A, pack_dup(fv.z), *(const u64t*)&sW1[(4*f4+2)*CC+iip]);
                ffma2(A, pack_dup(fv.w), *(const u64t*)&sW1[(4*f4+3)*CC+iip]);
            }
            float2 ac = unpack2(A);
            float2 qw = *(const float2*)&qmw[q*CC+iip];
            float2 qo = *(const float2*)&qmo[q*CC+iip];
            float h0 = ac.x*qw.x + qo.x;
            float h1 = ac.y*qw.y + qo.y;
            float kd = skd[k2]*invsum;
            *(float2*)&sg[k2*JP + iip] = make_float2(gelu_f(h0)*kd, gelu_f(h1)*kd);
        }
        for(int k2=tid;k2<KK;k2+=NT){
            sg[k2*JP+32] = skd[k2]*invsum;
        }
        __syncthreads();
    }
    // ======================= M-GEMM PHASE (packed f32x2, low-wavefront tiling)
    const int jg = warp>>1, half = warp&1;

    u64t acc2[4][4];
    #pragma unroll
    for(int jj=0;jj<4;jj++)
        #pragma unroll
        for(int p=0;p<4;p++) acc2[jj][p]=0ull;

    float* xb0 = px;
    float* xb1 = px + 8192;

    {
        for(int i=tid;i<32*64;i+=NT){
            int kk=i>>6, ch=i&63, b=ch>>3, c4=ch&7;
            int n = sind[kk];
            cp_async16(&xb0[kk*256 + ch*4], (const float4*)&d_xl[((b<<11)+n)*CC] + c4);
        }
        CP_COMMIT();
    }

    const int NCH = (KK + 31)/32;  // 7
    for(int ci=0; ci<NCH; ++ci){
        const int k0 = ci*32;
        const int nk = (KK-k0 < 32) ? (KK-k0) : 32;
        if(ci+1 < NCH){
            const int k0n = k0+32;
            const int nkn = (KK-k0n < 32) ? (KK-k0n) : 32;
            float* dst = (ci&1) ? xb0 : xb1;
            for(int i=tid;i<nkn*64;i+=NT){
                int kk=i>>6, ch=i&63, b=ch>>3, c4=ch&7;
                int n = sind[k0n+kk];
                cp_async16(&dst[kk*256 + ch*4], (const float4*)&d_xl[((b<<11)+n)*CC] + c4);
            }
            CP_COMMIT();
            CP_WAIT(1);
        } else {
            CP_WAIT(0);
        }
        __syncthreads();
        const float* xbase = (ci&1) ? xb1 : xb0;
        const float4*     sx4 = (const float4*)xbase;
        const ulonglong2* sxu = (const ulonglong2*)xbase;
        if(warp < 8){
            #pragma unroll 2
            for(int kk=0; kk<nk; ++kk){
                const ulonglong2* gu = (const ulonglong2*)&sg[(k0+kk)*JP + jg*8];
                ulonglong2 g01 = gu[0];
                ulonglong2 g23 = gu[1];
                float4 xv = sx4[kk*64 + half*32 + lane];
                u64t x0 = pack_dup(xv.x);
                u64t x1 = pack_dup(xv.y);
                u64t x2 = pack_dup(xv.z);
                u64t x3 = pack_dup(xv.w);
                ffma2(acc2[0][0], g01.x, x0); ffma2(acc2[0][1], g01.x, x1);
                ffma2(acc2[0][2], g01.x, x2); ffma2(acc2[0][3], g01.x, x3);
                ffma2(acc2[1][0], g01.y, x0); ffma2(acc2[1][1], g01.y, x1);
                ffma2(acc2[1][2], g01.y, x2); ffma2(acc2[1][3], g01.y, x3);
                ffma2(acc2[2][0], g23.x, x0); ffma2(acc2[2][1], g23.x, x1);
                ffma2(acc2[2][2], g23.x, x2); ffma2(acc2[2][3], g23.x, x3);
                ffma2(acc2[3][0], g23.y, x0); ffma2(acc2[3][1], g23.y, x1);
                ffma2(acc2[3][2], g23.y, x2); ffma2(acc2[3][3], g23.y, x3);
            }
        } else {
            #pragma unroll 2
            for(int kk=0; kk<nk; ++kk){
                u64t kdd = pack_dup(sg[(k0+kk)*JP + 32]);
                ulonglong2 xa = sxu[kk*64 + lane];
                ulonglong2 xc = sxu[kk*64 + 32 + lane];
                ffma2(acc2[0][0], kdd, xa.x); ffma2(acc2[0][1], kdd, xa.y);
                ffma2(acc2[0][2], kdd, xc.x); ffma2(acc2[0][3], kdd, xc.y);
            }
        }
        __syncthreads();
    }

    // stage M (33 x 256) into smem (aliases gather buffers; all reads done)
    float* sM = px;
    if(warp < 8){
        const int c0 = half*128 + 4*lane;
        #pragma unroll
        for(int jp=0;jp<4;jp++){
            int j = jg*8 + 2*jp;
            float2 a0 = unpack2(acc2[jp][0]);
            float2 a1 = unpack2(acc2[jp][1]);
            float2 a2 = unpack2(acc2[jp][2]);
            float2 a3 = unpack2(acc2[jp][3]);
            *(float4*)&sM[j*256 + c0]     = make_float4(a0.x,a1.x,a2.x,a3.x);
            *(float4*)&sM[(j+1)*256 + c0] = make_float4(a0.y,a1.y,a2.y,a3.y);
        }
    } else {
        ulonglong2 v0; v0.x = acc2[0][0]; v0.y = acc2[0][1];
        ulonglong2 v1; v1.x = acc2[0][2]; v1.y = acc2[0][3];
        *(ulonglong2*)&sM[32*256 + 4*lane]       = v0;
        *(ulonglong2*)&sM[32*256 + 128 + 4*lane] = v1;
    }
    __syncthreads();

    // ======================= W2 EPILOGUE (unit-balanced, swap-free) ========
    // 528 (j,c2) units spread evenly over 9 warps; accA=(d|even-c, d+32|odd-c),
    // accB=(d+32|even-c, d|odd-c). Partials reduced across warps in smem.
    float* sp = sg;   // 9*512 partials, overlays dead g
    {
        const int u0 = (warp*528)/9;
        const int u1 = ((warp+1)*528)/9;
        u64t accA[8], accB[8];
        #pragma unroll
        for(int b=0;b<8;b++){ accA[b]=0ull; accB[b]=0ull; }
        const ulonglong2* wq = (const ulonglong2*)d_W2q;
        const u64t* m2b = (const u64t*)sM;
        for(int u=u0; u<u1; ++u){
            const int j = u>>4, c2 = u&15;
            const u64t* m2 = m2b + j*128;     // sM[j*256] as u64 pairs
            ulonglong2 wv = wq[u*32 + lane];
            #pragma unroll
            for(int b=0;b<8;b++){
                u64t m = m2[b*16+c2];
                ffma2(accA[b], m, wv.x);
                ffma2(accB[b], m, wv.y);
            }
        }
        #pragma unroll
        for(int b=0;b<8;b++){
            float2 fa = unpack2(accA[b]);
            float2 fb = unpack2(accB[b]);
            sp[warp*512 + b*64 + lane]      = fa.x + fb.y;
            sp[warp*512 + b*64 + lane + 32] = fb.x + fa.y;
        }
    }
    __syncthreads();
    for(int o=tid; o<BB*DD; o+=NT){
        float s = 0.f;
        #pragma unroll
        for(int w=0;w<9;w++) s += sp[w*512+o];
        sy[o] = gelu_f(s + bias[o&63]);
    }
    __syncthreads();

    // ======================= MLP (packed weights, de-duplicated) ===========
    float* sh1 = sg;   // 2048 floats, overlays dead partials
    if(tid < 256){
        const int i = tid;
        const ulonglong2* wu = (const ulonglong2*)d_Wm1b;
        const ulonglong2* yu = (const ulonglong2*)sy;
        u64t A[8];
        #pragma unroll
        for(int b=0;b<8;b++) A[b]=0ull;
        #pragma unroll 4
        for(int d4=0; d4<16; ++d4){
            ulonglong2 w = wu[d4*256 + i];
            #pragma unroll
            for(int b=0;b<8;b++){
                ulonglong2 yv = yu[b*16 + d4];
                ffma2(A[b], yv.x, w.x);
                ffma2(A[b], yv.y, w.y);
            }
        }
        const float bi = bm1[i];
        #pragma unroll
        for(int b=0;b<8;b++){
            float2 f = unpack2(A[b]);
            sh1[b*256 + i] = gelu_f(f.x + f.y + bi);
        }
    }
    __syncthreads();

    if(tid < 256){
        const int d = tid&63;
        const int b0 = (tid>>6)*2, b1 = b0+1;
        const ulonglong2* wu = (const ulonglong2*)d_Wm2b;
        const ulonglong2* hu = (const ulonglong2*)sh1;
        u64t A0=0ull, A1=0ull;
        #pragma unroll 8
        for(int i4=0; i4<64; ++i4){
            ulonglong2 w  = wu[i4*64 + d];
            ulonglong2 h0 = hu[b0*64 + i4];
            ulonglong2 h1v= hu[b1*64 + i4];
            ffma2(A0, h0.x, w.x);  ffma2(A0, h0.y, w.y);
            ffma2(A1, h1v.x, w.x); ffma2(A1, h1v.y, w.y);
        }
        float2 f0 = unpack2(A0), f1 = unpack2(A1);
        const float bd = bm2[d];
        out[(b0*QQ + q)*DD + d] = f0.x + f0.y + bd + sy[b0*64 + d];
        out[(b1*QQ + q)*DD + d] = f1.x + f1.y + bd + sy[b1*64 + d];
    }
}

// ---------------- launch --------------------------------------------------
extern "C" void kernel_launch(void* const* d_in, const int* in_sizes, int n_in,
                              void* d_out, int out_size){
    (void)in_sizes; (void)n_in; (void)out_size;
    const float* x     = (const float*)d_in[0];
    const float* pos   = (const float*)d_in[1];
    const float* qpos  = (const float*)d_in[2];
    const float* qmw   = (const float*)d_in[3];
    const float* qmo   = (const float*)d_in[4];
    const float* W_lin = (const float*)d_in[5];
    const float* b_lin = (const float*)d_in[6];
    const float* rffB  = (const float*)d_in[7];
    const float* W1    = (const float*)d_in[8];
    const float* b1    = (const float*)d_in[9];
    const float* W2    = (const float*)d_in[10];
    const float* filt  = (const float*)d_in[11];
    const float* bias  = (const float*)d_in[12];
    const float* Wm1   = (const float*)d_in[13];
    const float* bm1   = (const float*)d_in[14];
    const float* Wm2   = (const float*)d_in[15];
    const float* bm2   = (const float*)d_in[16];
    float* out = (float*)d_out;

    cudaFuncSetAttribute(k_fused, cudaFuncAttributeMaxDynamicSharedMemorySize, SMEM_BYTES);

    k_xl   <<<128+2+16, 256>>>(x, W_lin, b_lin, qpos, out, Wm1, Wm2, W2, filt);
    k_fused<<<QQ, NT, SMEM_BYTES>>>(pos, qpos, rffB, W1, b1, qmw, qmo,
                                    bias, bm1, bm2, out);
}

// round 14
// speedup vs baseline: 3.2653x; 1.1078x over previous
#include <cuda_runtime.h>
#include <math.h>

#define BB 8
#define NN 2048
#define CC 32
#define DD 64
#define QQ 256
#define KK 205
#define JP 36           // padded j dimension (36 for 16B row alignment)
#define RANK (KK-1)
#define NT 288

typedef unsigned long long u64t;

// ---------------- scratch ----------------
__device__ float d_xl[BB*NN*CC];                  // 2 MB
__device__ __align__(16) float d_Wm1b[16384];     // Wm1 packed: [d/4][i][4]
__device__ __align__(16) float d_Wm2b[16384];     // Wm2 packed: [i/4][d][4]
// W2ext packed for j-partitioned epilogue (cross-lane variant, NO swaps)
__device__ __align__(16) float d_W2q[33*2048];

__device__ __forceinline__ float gelu_f(float x){
    return 0.5f*x*(1.0f+erff(x*0.70710678118654752440f));
}

__device__ __forceinline__ void cp_async16(float* smem_dst, const float4* gsrc){
    unsigned sm = (unsigned)__cvta_generic_to_shared(smem_dst);
    asm volatile("cp.async.cg.shared.global [%0], [%1], 16;\n" :: "r"(sm), "l"(gsrc));
}
#define CP_COMMIT() asm volatile("cp.async.commit_group;\n")
#define CP_WAIT(n)  asm volatile("cp.async.wait_group %0;\n" :: "n"(n))

// ---- packed fp32x2 helpers (Blackwell FFMA2) ----
__device__ __forceinline__ u64t pack_dup(float x){
    u64t r; unsigned u = __float_as_uint(x);
    asm("mov.b64 %0, {%1,%1};" : "=l"(r) : "r"(u));
    return r;
}
__device__ __forceinline__ void ffma2(u64t& d, u64t a, u64t b){
    asm("fma.rn.f32x2 %0, %1, %2, %0;" : "+l"(d) : "l"(a), "l"(b));
}
__device__ __forceinline__ float2 unpack2(u64t v){
    unsigned lo, hi;
    asm("mov.b64 {%0,%1}, %2;" : "=r"(lo), "=r"(hi) : "l"(v));
    return make_float2(__uint_as_float(lo), __uint_as_float(hi));
}

// ---------------- kernel A: xl, qp copy, weight packing -------------------
// blocks 0..127: xl (128 rows each); 128: Wm1b; 129: Wm2b; 130..145: W2q
__global__ __launch_bounds__(256) void k_xl(const float* __restrict__ x,
                                            const float* __restrict__ W,
                                            const float* __restrict__ bl,
                                            const float* __restrict__ qp,
                                            float* __restrict__ out,
                                            const float* __restrict__ Wm1,
                                            const float* __restrict__ Wm2,
                                            const float* __restrict__ W2,
                                            const float* __restrict__ filt){
    const int bid = blockIdx.x, tid = threadIdx.x;
    if(bid >= 128){
        const int tb = bid - 128;
        if(tb == 0){
            for(int i=tid;i<16384;i+=256){
                int d = i>>8, ii = i&255;
                d_Wm1b[(d>>2)*1024 + ii*4 + (d&3)] = Wm1[i];
            }
        } else if(tb == 1){
            for(int i=tid;i<16384;i+=256){
                int ii = i>>6, d = i&63;
                d_Wm2b[(ii>>2)*256 + d*4 + (ii&3)] = Wm2[i];
            }
        } else {
            int i0 = (tb-2)*4224;
            for(int i=i0+tid; i<i0+4224; i+=256){
                int t = i&3, ln = (i>>2)&31, c2 = (i>>7)&15, j = i>>11;
                int c = 2*c2 + (t&1);
                int d = ln + 32*(((t+1)>>1)&1);
                d_W2q[i] = (j<32) ? W2[(j<<11)+(c<<6)+d] : filt[(c<<6)+d];
            }
        }
        return;
    }
    __shared__ float sW[CC*CC];
    for(int i=tid;i<CC*CC;i+=256) sW[i]=W[i];
    __syncthreads();
    const int lane = tid&31;
    const int rbase = bid*128 + (tid>>5)*16;
    #pragma unroll 4
    for(int r=0;r<16;r++){
        int row = rbase + r;
        float xv  = x[row*CC + lane];
        float acc = bl[lane];
        #pragma unroll
        for(int ci=0;ci<CC;ci++)
            acc = fmaf(__shfl_sync(0xffffffffu, xv, ci), sW[ci*CC+lane], acc);
        d_xl[row*CC+lane] = acc;
    }
    if(bid < 2){
        int i = bid*256 + tid;
        out[BB*QQ*DD + i] = qp[i];
    }
}

// ---------------- fused kernel ---------------------------------------------
// smem layout (floats). Total 26652 floats = 106,608 B -> 2 blocks/SM (213 KB).
#define OFF_G   0                 // g 205*36=7380 (later: epilogue partials, sh1)
#define OFF_X   7380              // 16384: sed+sfeat (low) | x gather buffers | sM
#define OFF_IND 23764             // 208 ints
#define OFF_Y   23972             // 512
#define OFF_EXT 24484             // extension: persistent select scratch
#define XE_D0   (OFF_EXT+0)       // 208
#define XE_D1   (OFF_EXT+208)
#define XE_EDK  (OFF_EXT+416)
#define XE_KD   (OFF_EXT+624)
#define XE_W1   (OFF_EXT+832)     // 1024
#define XE_B1   (OFF_EXT+1856)    // 32
#define XE_HIST (OFF_EXT+1888)    // 256 (uint)
#define XE_RA   (OFF_EXT+2144)    // 9
#define XE_RB   (OFF_EXT+2153)    // 9
#define XE_SC   (OFF_EXT+2162)    // 6
#define SMEM_FLOATS (OFF_EXT+2168)
#define SMEM_BYTES (SMEM_FLOATS*4)

__global__ __launch_bounds__(NT,2) void k_fused(
        const float* __restrict__ pos, const float* __restrict__ qpos,
        const float* __restrict__ rffB,
        const float* __restrict__ W1,  const float* __restrict__ b1,
        const float* __restrict__ qmw, const float* __restrict__ qmo,
        const float* __restrict__ bias,
        const float* __restrict__ bm1, const float* __restrict__ bm2,
        float* __restrict__ out)
{
    extern __shared__ float smem[];
    float* sg  = smem + OFF_G;
    float* px  = smem + OFF_X;
    int*   sind= (int*)(smem + OFF_IND);
    float* sy  = smem + OFF_Y;

    const int q = blockIdx.x, tid = threadIdx.x;
    const int warp = tid>>5, lane = tid&31;
    const float qx = qpos[q*2], qy = qpos[q*2+1];

    float* xbE = px + 8192;    // even-chunk gather buffer
    float* xbO = px;           // odd-chunk gather buffer (overlays sed/sfeat)

    // ======================= SELECT PHASE =======================
    {
        float* sed  = px;                    // 2048, dead after sedk gather
        float* sfeat= px;                    // 205*32=6560, written after sed dies
        float* sd0  = smem + XE_D0;
        float* sd1  = smem + XE_D1;
        float* sedk = smem + XE_EDK;
        float* skd  = smem + XE_KD;
        float* sW1  = smem + XE_W1;
        float* sb1  = smem + XE_B1;
        unsigned int* hist = (unsigned int*)(smem + XE_HIST);
        float* rbufA= smem + XE_RA;
        float* rbufB= smem + XE_RB;
        unsigned int* s_prefix = (unsigned int*)(smem + XE_SC);
        unsigned int* s_r      = (unsigned int*)(smem + XE_SC + 1);
        unsigned int* s_cnt    = (unsigned int*)(smem + XE_SC + 2);
        float* s_min = smem + XE_SC + 3;
        float* s_max = smem + XE_SC + 4;
        float* s_sum = smem + XE_SC + 5;

        for(int i=tid;i<CC*CC;i+=NT) sW1[i]=W1[i];
        if(tid<CC) sb1[tid]=b1[tid];
        for(int i=tid;i<256;i+=NT) hist[i]=0u;
        if(tid==0){ *s_prefix=0u; *s_r=RANK; *s_cnt=0u; }
        __syncthreads();

        // ---- edist + fused pass-0 histogram (warp-aggregated) ----
        for(int base=0; base<NN; base+=NT){
            int n = base + tid;
            bool inb = (n < NN);
            unsigned int k = 0xFFFFFFFFu;
            if(inb){
                float2 p = ((const float2*)pos)[n];
                float d0 = qx - p.x; d0 += 0.5f; d0 -= floorf(d0); d0 -= 0.5f;
                float d1 = qy - p.y; d1 += 0.5f; d1 -= floorf(d1); d1 -= 0.5f;
                float e = d0*d0 + d1*d1;
                sed[n] = e;
                k = __float_as_uint(e);
            }
            unsigned amask = __ballot_sync(0xffffffffu, inb);
            if(inb){
                unsigned bkt = (k>>24)&255u;
                unsigned peers = __match_any_sync(amask, bkt);
                if(lane == (int)(__ffs(peers)-1))
                    atomicAdd(&hist[bkt], __popc(peers));
            }
        }
        __syncthreads();
        if(warp == 0){
            const unsigned rr = *s_r;
            unsigned cnt[8]; unsigned s = 0;
            const int b0 = lane*8;
            #pragma unroll
            for(int t=0;t<8;t++){ cnt[t] = hist[b0+t]; s += cnt[t]; }
            unsigned excl = s;
            #pragma unroll
            for(int o=1;o<32;o<<=1){
                unsigned v = __shfl_up_sync(0xffffffffu, excl, o);
                if(lane >= o) excl += v;
            }
            excl -= s;
            bool sel = (excl <= rr) && (rr < excl + s);
            if(sel){
                unsigned rem = rr - excl;
                int t = 0;
                while(t < 7 && rem >= cnt[t]){ rem -= cnt[t]; t++; }
                *s_prefix = (unsigned)(b0+t) << 24;
                *s_r = rem;
            }
        }
        __syncthreads();

        // ---- passes 1-3: sparse, plain predicated atomics ----
        for(int pass=1; pass<4; ++pass){
            const int shift = 24 - 8*pass;
            for(int i=tid;i<256;i+=NT) hist[i]=0u;
            __syncthreads();
            const unsigned int prefix = *s_prefix;
            const unsigned int hm = 0xFFFFFFFFu << (shift+8);
            for(int n=tid;n<NN;n+=NT){
                unsigned int k = __float_as_uint(sed[n]);
                if((k & hm) == prefix) atomicAdd(&hist[(k>>shift)&255u], 1u);
            }
            __syncthreads();
            if(warp == 0){
                const unsigned rr = *s_r;
                unsigned cnt[8]; unsigned s = 0;
                const int b0 = lane*8;
                #pragma unroll
                for(int t=0;t<8;t++){ cnt[t] = hist[b0+t]; s += cnt[t]; }
                unsigned excl = s;
                #pragma unroll
                for(int o=1;o<32;o<<=1){
                    unsigned v = __shfl_up_sync(0xffffffffu, excl, o);
                    if(lane >= o) excl += v;
                }
                excl -= s;
                bool sel = (excl <= rr) && (rr < excl + s);
                if(sel){
                    unsigned rem = rr - excl;
                    int t = 0;
                    while(t < 7 && rem >= cnt[t]){ rem -= cnt[t]; t++; }
                    *s_prefix = prefix | ((unsigned)(b0+t) << shift);
                    *s_r = rem;
                }
            }
            __syncthreads();
        }
        const unsigned int T = *s_prefix;

        for(int n=tid;n<NN;n+=NT){
            unsigned int k = __float_as_uint(sed[n]);
            if(k < T){ unsigned int p = atomicAdd(s_cnt,1u); sind[p]=n; }
        }
        __syncthreads();
        for(int n=tid;n<NN;n+=NT){
            unsigned int k = __float_as_uint(sed[n]);
            if(k == T){ unsigned int p = atomicAdd(s_cnt,1u); if(p<KK) sind[p]=n; }
        }
        __syncthreads();

        // gather dist/edist for selected set (sed dies after this)
        for(int k2=tid;k2<KK;k2+=NT){
            int n = sind[k2];
            float2 p = ((const float2*)pos)[n];
            float d0 = qx - p.x; d0 += 0.5f; d0 -= floorf(d0); d0 -= 0.5f;
            float d1 = qy - p.y; d1 += 0.5f; d1 -= floorf(d1); d1 -= 0.5f;
            sd0[k2]=d0; sd1[k2]=d1; sedk[k2]=sed[n];
        }
        __syncthreads();

        // ---- EARLY chunk-0 gather into xbE (px+8192; nothing live there) ----
        for(int i=tid;i<32*64;i+=NT){
            int kk=i>>6, ch=i&63, b=ch>>3, c4=ch&7;
            int n = sind[kk];
            cp_async16(&xbE[kk*256 + ch*4], (const float4*)&d_xl[((b<<11)+n)*CC] + c4);
        }
        CP_COMMIT();

        float mn = 1e30f, mx = -1e30f;
        for(int k2=tid;k2<KK;k2+=NT){ mn=fminf(mn,sedk[k2]); mx=fmaxf(mx,sedk[k2]); }
        #pragma unroll
        for(int o=16;o>0;o>>=1){
            mn = fminf(mn, __shfl_down_sync(0xffffffffu,mn,o));
            mx = fmaxf(mx, __shfl_down_sync(0xffffffffu,mx,o));
        }
        if(lane==0){ rbufA[warp]=mn; rbufB[warp]=mx; }
        __syncthreads();
        if(tid==0){
            float a=rbufA[0], b=rbufB[0];
            for(int w=1;w<9;w++){ a=fminf(a,rbufA[w]); b=fmaxf(b,rbufB[w]); }
            *s_min=a; *s_max=b;
        }
        __syncthreads();

        const float inv = 1.0f/(*s_max - *s_min + 1e-8f);
        const float smin = *s_min;
        float lsum = 0.0f;
        for(int k2=tid;k2<KK;k2+=NT){
            float w = __expf(-(sedk[k2]-smin)*inv);
            skd[k2]=w; lsum+=w;
        }
        #pragma unroll
        for(int o=16;o>0;o>>=1) lsum += __shfl_down_sync(0xffffffffu,lsum,o);
        if(lane==0) rbufA[warp]=lsum;
        __syncthreads();
        if(tid==0){
            float s=0.f; for(int w=0;w<9;w++) s+=rbufA[w];
            *s_sum=s;
        }
        __syncthreads();
        const float invsum = 1.0f/(*s_sum);

        // RFF features into sfeat (= px[0..6560), sed dead)
        for(int i=tid;i<KK*16;i+=NT){
            int k2=i>>4, j=i&15;
            float pr = 6.28318530717958647692f*(sd0[k2]*rffB[j] + sd1[k2]*rffB[16+j]);
            float s,c; __sincosf(pr,&s,&c);
            sfeat[k2*32+j]=s; sfeat[k2*32+16+j]=c;
        }
        __syncthreads();

        // g-phase: k2-inner, W1 hoisted (iip fixed per thread: 288 % 16 == 0)
        {
            const int iip = (tid&15)*2;
            const int k2b = tid>>4;             // 0..17; k2 = k2b + 18*t
            u64t A[12];
            u64t binit = *(const u64t*)&sb1[iip];
            #pragma unroll
            for(int t=0;t<12;t++) A[t]=binit;
            #pragma unroll
            for(int f4=0; f4<8; ++f4){
                u64t w0 = *(const u64t*)&sW1[(4*f4+0)*CC+iip];
                u64t w1 = *(const u64t*)&sW1[(4*f4+1)*CC+iip];
                u64t w2 = *(const u64t*)&sW1[(4*f4+2)*CC+iip];
                u64t w3 = *(const u64t*)&sW1[(4*f4+3)*CC+iip];
                #pragma unroll
                for(int t=0;t<12;t++){
                    int k2 = k2b + 18*t;
                    if(k2 < KK){
                        float4 fv = *(const float4*)&sfeat[k2*32 + 4*f4];
                        ffma2(A[t], pack_dup(fv.x), w0);
                        ffma2(A[t], pack_dup(fv.y), w1);
                        ffma2(A[t], pack_dup(fv.z), w2);
                        ffma2(A[t], pack_dup(fv.w), w3);
                    }
                }
            }
            float2 qw = *(const float2*)&qmw[q*CC+iip];
            float2 qo = *(const float2*)&qmo[q*CC+iip];
            #pragma unroll
            for(int t=0;t<12;t++){
                int k2 = k2b + 18*t;
                if(k2 < KK){
                    float2 ac = unpack2(A[t]);
                    float h0 = ac.x*qw.x + qo.x;
                    float h1 = ac.y*qw.y + qo.y;
                    float kd = skd[k2]*invsum;
                    *(float2*)&sg[k2*JP + iip] = make_float2(gelu_f(h0)*kd, gelu_f(h1)*kd);
                }
            }
        }
        for(int k2=tid;k2<KK;k2+=NT){
            sg[k2*JP+32] = skd[k2]*invsum;
        }
        __syncthreads();
    }
    // ======================= M-GEMM PHASE (packed f32x2, low-wavefront tiling)
    // even chunks in xbE (px+8192), odd chunks in xbO (px); chunk 0 already in flight
    const int jg = warp>>1, half = warp&1;

    u64t acc2[4][4];
    #pragma unroll
    for(int jj=0;jj<4;jj++)
        #pragma unroll
        for(int p=0;p<4;p++) acc2[jj][p]=0ull;

    const int NCH = (KK + 31)/32;  // 7
    for(int ci=0; ci<NCH; ++ci){
        const int k0 = ci*32;
        const int nk = (KK-k0 < 32) ? (KK-k0) : 32;
        if(ci+1 < NCH){
            const int k0n = k0+32;
            const int nkn = (KK-k0n < 32) ? (KK-k0n) : 32;
            float* dst = (ci&1) ? xbE : xbO;
            for(int i=tid;i<nkn*64;i+=NT){
                int kk=i>>6, ch=i&63, b=ch>>3, c4=ch&7;
                int n = sind[k0n+kk];
                cp_async16(&dst[kk*256 + ch*4], (const float4*)&d_xl[((b<<11)+n)*CC] + c4);
            }
            CP_COMMIT();
            CP_WAIT(1);
        } else {
            CP_WAIT(0);
        }
        __syncthreads();
        const float* xbase = (ci&1) ? xbO : xbE;
        const float4*     sx4 = (const float4*)xbase;
        const ulonglong2* sxu = (const ulonglong2*)xbase;
        if(warp < 8){
            #pragma unroll 2
            for(int kk=0; kk<nk; ++kk){
                const ulonglong2* gu = (const ulonglong2*)&sg[(k0+kk)*JP + jg*8];
                ulonglong2 g01 = gu[0];
                ulonglong2 g23 = gu[1];
                float4 xv = sx4[kk*64 + half*32 + lane];
                u64t x0 = pack_dup(xv.x);
                u64t x1 = pack_dup(xv.y);
                u64t x2 = pack_dup(xv.z);
                u64t x3 = pack_dup(xv.w);
                ffma2(acc2[0][0], g01.x, x0); ffma2(acc2[0][1], g01.x, x1);
                ffma2(acc2[0][2], g01.x, x2); ffma2(acc2[0][3], g01.x, x3);
                ffma2(acc2[1][0], g01.y, x0); ffma2(acc2[1][1], g01.y, x1);
                ffma2(acc2[1][2], g01.y, x2); ffma2(acc2[1][3], g01.y, x3);
                ffma2(acc2[2][0], g23.x, x0); ffma2(acc2[2][1], g23.x, x1);
                ffma2(acc2[2][2], g23.x, x2); ffma2(acc2[2][3], g23.x, x3);
                ffma2(acc2[3][0], g23.y, x0); ffma2(acc2[3][1], g23.y, x1);
                ffma2(acc2[3][2], g23.y, x2); ffma2(acc2[3][3], g23.y, x3);
            }
        } else {
            #pragma unroll 2
            for(int kk=0; kk<nk; ++kk){
                u64t kdd = pack_dup(sg[(k0+kk)*JP + 32]);
                ulonglong2 xa = sxu[kk*64 + lane];
                ulonglong2 xc = sxu[kk*64 + 32 + lane];
                ffma2(acc2[0][0], kdd, xa.x); ffma2(acc2[0][1], kdd, xa.y);
                ffma2(acc2[0][2], kdd, xc.x); ffma2(acc2[0][3], kdd, xc.y);
            }
        }
        __syncthreads();
    }

    // stage M (33 x 256) into smem (aliases gather buffers; all reads done)
    float* sM = px;
    if(warp < 8){
        const int c0 = half*128 + 4*lane;
        #pragma unroll
        for(int jp=0;jp<4;jp++){
            int j = jg*8 + 2*jp;
            float2 a0 = unpack2(acc2[jp][0]);
            float2 a1 = unpack2(acc2[jp][1]);
            float2 a2 = unpack2(acc2[jp][2]);
            float2 a3 = unpack2(acc2[jp][3]);
            *(float4*)&sM[j*256 + c0]     = make_float4(a0.x,a1.x,a2.x,a3.x);
            *(float4*)&sM[(j+1)*256 + c0] = make_float4(a0.y,a1.y,a2.y,a3.y);
        }
    } else {
        ulonglong2 v0; v0.x = acc2[0][0]; v0.y = acc2[0][1];
        ulonglong2 v1; v1.x = acc2[0][2]; v1.y = acc2[0][3];
        *(ulonglong2*)&sM[32*256 + 4*lane]       = v0;
        *(ulonglong2*)&sM[32*256 + 128 + 4*lane] = v1;
    }
    __syncthreads();

    // ======================= W2 EPILOGUE (unit-balanced, swap-free) ========
    float* sp = sg;   // 9*512 partials, overlays dead g
    {
        const int u0 = (warp*528)/9;
        const int u1 = ((warp+1)*528)/9;
        u64t accA[8], accB[8];
        #pragma unroll
        for(int b=0;b<8;b++){ accA[b]=0ull; accB[b]=0ull; }
        const ulonglong2* wq = (const ulonglong2*)d_W2q;
        const u64t* m2b = (const u64t*)sM;
        for(int u=u0; u<u1; ++u){
            const int j = u>>4, c2 = u&15;
            const u64t* m2 = m2b + j*128;
            ulonglong2 wv = wq[u*32 + lane];
            #pragma unroll
            for(int b=0;b<8;b++){
                u64t m = m2[b*16+c2];
                ffma2(accA[b], m, wv.x);
                ffma2(accB[b], m, wv.y);
            }
        }
        #pragma unroll
        for(int b=0;b<8;b++){
            float2 fa = unpack2(accA[b]);
            float2 fb = unpack2(accB[b]);
            sp[warp*512 + b*64 + lane]      = fa.x + fb.y;
            sp[warp*512 + b*64 + lane + 32] = fb.x + fa.y;
        }
    }
    __syncthreads();
    for(int o=tid; o<BB*DD; o+=NT){
        float s = 0.f;
        #pragma unroll
        for(int w=0;w<9;w++) s += sp[w*512+o];
        sy[o] = gelu_f(s + bias[o&63]);
    }
    __syncthreads();

    // ======================= MLP (packed weights, de-duplicated) ===========
    float* sh1 = sg;   // 2048 floats, overlays dead partials
    if(tid < 256){
        const int i = tid;
        const ulonglong2* wu = (const ulonglong2*)d_Wm1b;
        const ulonglong2* yu = (const ulonglong2*)sy;
        u64t A[8];
        #pragma unroll
        for(int b=0;b<8;b++) A[b]=0ull;
        #pragma unroll 4
        for(int d4=0; d4<16; ++d4){
            ulonglong2 w = wu[d4*256 + i];
            #pragma unroll
            for(int b=0;b<8;b++){
                ulonglong2 yv = yu[b*16 + d4];
                ffma2(A[b], yv.x, w.x);
                ffma2(A[b], yv.y, w.y);
            }
        }
        const float bi = bm1[i];
        #pragma unroll
        for(int b=0;b<8;b++){
            float2 f = unpack2(A[b]);
            sh1[b*256 + i] = gelu_f(f.x + f.y + bi);
        }
    }
    __syncthreads();

    if(tid < 256){
        const int d = tid&63;
        const int b0 = (tid>>6)*2, b1 = b0+1;
        const ulonglong2* wu = (const ulonglong2*)d_Wm2b;
        const ulonglong2* hu = (const ulonglong2*)sh1;
        u64t A0=0ull, A1=0ull;
        #pragma unroll 8
        for(int i4=0; i4<64; ++i4){
            ulonglong2 w  = wu[i4*64 + d];
            ulonglong2 h0 = hu[b0*64 + i4];
            ulonglong2 h1v= hu[b1*64 + i4];
            ffma2(A0, h0.x, w.x);  ffma2(A0, h0.y, w.y);
            ffma2(A1, h1v.x, w.x); ffma2(A1, h1v.y, w.y);
        }
        float2 f0 = unpack2(A0), f1 = unpack2(A1);
        const float bd = bm2[d];
        out[(b0*QQ + q)*DD + d] = f0.x + f0.y + bd + sy[b0*64 + d];
        out[(b1*QQ + q)*DD + d] = f1.x + f1.y + bd + sy[b1*64 + d];
    }
}

// ---------------- launch --------------------------------------------------
extern "C" void kernel_launch(void* const* d_in, const int* in_sizes, int n_in,
                              void* d_out, int out_size){
    (void)in_sizes; (void)n_in; (void)out_size;
    const float* x     = (const float*)d_in[0];
    const float* pos   = (const float*)d_in[1];
    const float* qpos  = (const float*)d_in[2];
    const float* qmw   = (const float*)d_in[3];
    const float* qmo   = (const float*)d_in[4];
    const float* W_lin = (const float*)d_in[5];
    const float* b_lin = (const float*)d_in[6];
    const float* rffB  = (const float*)d_in[7];
    const float* W1    = (const float*)d_in[8];
    const float* b1    = (const float*)d_in[9];
    const float* W2    = (const float*)d_in[10];
    const float* filt  = (const float*)d_in[11];
    const float* bias  = (const float*)d_in[12];
    const float* Wm1   = (const float*)d_in[13];
    const float* bm1   = (const float*)d_in[14];
    const float* Wm2   = (const float*)d_in[15];
    const float* bm2   = (const float*)d_in[16];
    float* out = (float*)d_out;

    cudaFuncSetAttribute(k_fused, cudaFuncAttributeMaxDynamicSharedMemorySize, SMEM_BYTES);

    k_xl   <<<128+2+16, 256>>>(x, W_lin, b_lin, qpos, out, Wm1, Wm2, W2, filt);
    k_fused<<<QQ, NT, SMEM_BYTES>>>(pos, qpos, rffB, W1, b1, qmw, qmo,
                                    bias, bm1, bm2, out);
}